// round 2
// baseline (speedup 1.0000x reference)
#include <cuda_runtime.h>
#include <cuda_bf16.h>
#include <math.h>

// ---------------- Problem constants ----------------
#define BATCH   16384
#define NFIELD  10
#define EMB     32
#define DENSE   16
#define XDIM    336          // 10*32 + 16
#define H0      256
#define H1      128
#define H2      64

// field offsets (cumsum of FIELD_DIMS)
__constant__ int c_offsets[NFIELD] = {
    0, 1000000, 1100000, 1101008, 1102012,
    1102114, 1103114, 1103614, 1103664, 1103776
};

// ---------------- Device scratch (static, allocation-free) ----------------
__device__ float g_Xbuf[BATCH * XDIM];       // activations, row-major [B][336]
__device__ float g_fm[BATCH];                // fm_bias + first + second per sample
__device__ float g_Wt0[XDIM * H0];           // [336][256]  k-major, BN-folded
__device__ float g_Wt1[H0 * H1];             // [256][128]
__device__ float g_Wt2[H1 * H2];             // [128][64]
__device__ float g_bf0[H0];
__device__ float g_bf1[H1];
__device__ float g_bf2[H2];

// ---------------- Kernel 1: fold BN into transposed weights ----------------
__global__ void fold_kernel(const float* __restrict__ W, const float* __restrict__ b,
                            const float* __restrict__ g, const float* __restrict__ be,
                            float* __restrict__ Wt, float* __restrict__ bf,
                            int OUT, int IN)
{
    const float inv = (float)(1.0 / sqrt(1.0 + 1e-5));
    int i = blockIdx.x * blockDim.x + threadIdx.x;
    if (i < OUT * IN) {
        int k = i / OUT;
        int o = i - k * OUT;
        Wt[i] = W[o * IN + k] * (g[o] * inv);
    }
    if (i < OUT) {
        bf[i] = b[i] * (g[i] * inv) + be[i];
    }
}

// ---------------- Kernel 2: embedding gather + FM + build X ----------------
// 256 threads = 8 warps, warp per sample.
__global__ void embed_fm_kernel(const int* __restrict__ sp,
                                const float* __restrict__ dense,
                                const float* __restrict__ emb,
                                const float* __restrict__ bias,
                                const float* __restrict__ fmb)
{
    int w = threadIdx.x >> 5;
    int l = threadIdx.x & 31;
    int b = blockIdx.x * 8 + w;
    if (b >= BATCH) return;

    float s = 0.f, sq = 0.f;
#pragma unroll
    for (int f = 0; f < NFIELD; f++) {
        int row = sp[b * NFIELD + f] + c_offsets[f];
        float e = __ldg(&emb[row * EMB + l]);
        g_Xbuf[b * XDIM + f * EMB + l] = e;
        s += e;
        sq += e * e;
    }
    float part = 0.5f * (s * s - sq);
    if (l < NFIELD) {
        int row = sp[b * NFIELD + l] + c_offsets[l];
        part += __ldg(&bias[row]);
    }
#pragma unroll
    for (int d = 16; d > 0; d >>= 1)
        part += __shfl_down_sync(0xFFFFFFFFu, part, d);

    if (l < DENSE)
        g_Xbuf[b * XDIM + NFIELD * EMB + l] = dense[b * DENSE + l];
    if (l == 0)
        g_fm[b] = fmb[0] + part;
}

// ---------------- Kernel 3: fused MLP (64 samples / block) ----------------
// Shared layout (floats):
//   C1s : [256][64]  @ 0        (64 KB)
//   C2s : [128][64]  @ 16384    (32 KB)
//   Wts : [16][256]  @ 24576    (16 KB, reused smaller per layer)
//   Xs  : [16][64]   @ 28672    ( 4 KB)
//   C3s : [64][64]   @ 29696    (16 KB)
#define SMEM_FLOATS 33792
#define SMEM_BYTES  (SMEM_FLOATS * 4)

__global__ __launch_bounds__(256, 1)
void mlp_kernel(const float* __restrict__ Wo, const float* __restrict__ bo,
                float* __restrict__ out)
{
    extern __shared__ float sm[];
    float* C1s = sm;
    float* C2s = sm + 16384;
    float* Wts = sm + 24576;
    float* Xs  = sm + 28672;
    float* C3s = sm + 29696;

    const int t  = threadIdx.x;
    const int tm = t & 7;        // 0..7   (m-group)
    const int tn = t >> 3;       // 0..31  (n-group)
    const int m0 = tm * 8;
    const int blk = blockIdx.x * 64;

    // ================= Layer 0: [64x336] @ [336x256] =================
    {
        const int n0 = tn * 8;
        float acc[8][8];
#pragma unroll
        for (int i = 0; i < 8; i++)
#pragma unroll
            for (int j = 0; j < 8; j++) acc[i][j] = 0.f;

        for (int kb = 0; kb < 21; kb++) {
            // load X tile [16 k][64 m] (transposed into smem)
            {
                int m  = t >> 2;
                int k4 = (t & 3) * 4;
                float4 v = *(const float4*)&g_Xbuf[(blk + m) * XDIM + kb * 16 + k4];
                Xs[(k4 + 0) * 64 + m] = v.x;
                Xs[(k4 + 1) * 64 + m] = v.y;
                Xs[(k4 + 2) * 64 + m] = v.z;
                Xs[(k4 + 3) * 64 + m] = v.w;
            }
            // load W tile [16 k][256 n]
            {
                int r  = t >> 4;
                int c0 = (t & 15) * 16;
                const float4* src = (const float4*)&g_Wt0[(kb * 16 + r) * H0 + c0];
                float4* dst = (float4*)&Wts[r * H0 + c0];
                dst[0] = src[0]; dst[1] = src[1]; dst[2] = src[2]; dst[3] = src[3];
            }
            __syncthreads();
#pragma unroll
            for (int kk = 0; kk < 16; kk++) {
                float4 a0 = *(float4*)&Xs[kk * 64 + m0];
                float4 a1 = *(float4*)&Xs[kk * 64 + m0 + 4];
                float4 b0 = *(float4*)&Wts[kk * H0 + n0];
                float4 b1 = *(float4*)&Wts[kk * H0 + n0 + 4];
                float a[8] = {a0.x, a0.y, a0.z, a0.w, a1.x, a1.y, a1.z, a1.w};
                float bb[8] = {b0.x, b0.y, b0.z, b0.w, b1.x, b1.y, b1.z, b1.w};
#pragma unroll
                for (int i = 0; i < 8; i++)
#pragma unroll
                    for (int j = 0; j < 8; j++)
                        acc[i][j] = fmaf(a[i], bb[j], acc[i][j]);
            }
            __syncthreads();
        }
        // epilogue: bias + relu -> C1s[n][m]
        float bj[8];
#pragma unroll
        for (int j = 0; j < 8; j++) bj[j] = g_bf0[n0 + j];
#pragma unroll
        for (int j = 0; j < 8; j++)
#pragma unroll
            for (int i = 0; i < 8; i++)
                C1s[(n0 + j) * 64 + m0 + i] = fmaxf(acc[i][j] + bj[j], 0.f);
        __syncthreads();
    }

    // ================= Layer 1: [64x256] @ [256x128] =================
    {
        const int n0 = tn * 4;
        float acc[8][4];
#pragma unroll
        for (int i = 0; i < 8; i++)
#pragma unroll
            for (int j = 0; j < 4; j++) acc[i][j] = 0.f;

        for (int kb = 0; kb < 16; kb++) {
            {
                int r  = t >> 4;
                int c0 = (t & 15) * 8;
                const float4* src = (const float4*)&g_Wt1[(kb * 16 + r) * H1 + c0];
                float4* dst = (float4*)&Wts[r * H1 + c0];
                dst[0] = src[0]; dst[1] = src[1];
            }
            __syncthreads();
#pragma unroll
            for (int kk = 0; kk < 16; kk++) {
                int k = kb * 16 + kk;
                float4 a0 = *(float4*)&C1s[k * 64 + m0];
                float4 a1 = *(float4*)&C1s[k * 64 + m0 + 4];
                float4 bv = *(float4*)&Wts[kk * H1 + n0];
                float a[8] = {a0.x, a0.y, a0.z, a0.w, a1.x, a1.y, a1.z, a1.w};
                float bb[4] = {bv.x, bv.y, bv.z, bv.w};
#pragma unroll
                for (int i = 0; i < 8; i++)
#pragma unroll
                    for (int j = 0; j < 4; j++)
                        acc[i][j] = fmaf(a[i], bb[j], acc[i][j]);
            }
            __syncthreads();
        }
        float bj[4];
#pragma unroll
        for (int j = 0; j < 4; j++) bj[j] = g_bf1[n0 + j];
#pragma unroll
        for (int j = 0; j < 4; j++)
#pragma unroll
            for (int i = 0; i < 8; i++)
                C2s[(n0 + j) * 64 + m0 + i] = fmaxf(acc[i][j] + bj[j], 0.f);
        __syncthreads();
    }

    // ================= Layer 2: [64x128] @ [128x64] =================
    {
        const int n0 = tn * 2;
        float acc[8][2];
#pragma unroll
        for (int i = 0; i < 8; i++) { acc[i][0] = 0.f; acc[i][1] = 0.f; }

        for (int kb = 0; kb < 8; kb++) {
            {
                int r  = t >> 4;
                int c0 = (t & 15) * 4;
                *(float4*)&Wts[r * H2 + c0] =
                    *(const float4*)&g_Wt2[(kb * 16 + r) * H2 + c0];
            }
            __syncthreads();
#pragma unroll
            for (int kk = 0; kk < 16; kk++) {
                int k = kb * 16 + kk;
                float4 a0 = *(float4*)&C2s[k * 64 + m0];
                float4 a1 = *(float4*)&C2s[k * 64 + m0 + 4];
                float2 bv = *(float2*)&Wts[kk * H2 + n0];
                float a[8] = {a0.x, a0.y, a0.z, a0.w, a1.x, a1.y, a1.z, a1.w};
#pragma unroll
                for (int i = 0; i < 8; i++) {
                    acc[i][0] = fmaf(a[i], bv.x, acc[i][0]);
                    acc[i][1] = fmaf(a[i], bv.y, acc[i][1]);
                }
            }
            __syncthreads();
        }
        float b0f = g_bf2[n0], b1f = g_bf2[n0 + 1];
#pragma unroll
        for (int i = 0; i < 8; i++) {
            C3s[(n0 + 0) * 64 + m0 + i] = fmaxf(acc[i][0] + b0f, 0.f);
            C3s[(n0 + 1) * 64 + m0 + i] = fmaxf(acc[i][1] + b1f, 0.f);
        }
        __syncthreads();
    }

    // ================= Output: dot with Wo + fm + sigmoid =================
    if (t < 64) {
        float s = g_fm[blk + t] + bo[0];
#pragma unroll
        for (int k = 0; k < H2; k++)
            s = fmaf(C3s[k * 64 + t], __ldg(&Wo[k]), s);
        out[blk + t] = 1.f / (1.f + expf(-s));
    }
}

// ---------------- Launch ----------------
extern "C" void kernel_launch(void* const* d_in, const int* in_sizes, int n_in,
                              void* d_out, int out_size)
{
    const int*   sp    = (const int*)  d_in[0];
    const float* dense = (const float*)d_in[1];
    const float* emb   = (const float*)d_in[2];
    const float* bias  = (const float*)d_in[3];
    const float* fmb   = (const float*)d_in[4];
    const float* Wo    = (const float*)d_in[5];
    const float* bo    = (const float*)d_in[6];
    const float* W0    = (const float*)d_in[7];
    const float* b0    = (const float*)d_in[8];
    const float* g0    = (const float*)d_in[9];
    const float* be0   = (const float*)d_in[10];
    const float* W1    = (const float*)d_in[11];
    const float* b1    = (const float*)d_in[12];
    const float* g1    = (const float*)d_in[13];
    const float* be1   = (const float*)d_in[14];
    const float* W2    = (const float*)d_in[15];
    const float* b2    = (const float*)d_in[16];
    const float* g2    = (const float*)d_in[17];
    const float* be2   = (const float*)d_in[18];
    float* out = (float*)d_out;

    float *Wt0, *Wt1, *Wt2, *bf0, *bf1, *bf2;
    cudaGetSymbolAddress((void**)&Wt0, g_Wt0);
    cudaGetSymbolAddress((void**)&Wt1, g_Wt1);
    cudaGetSymbolAddress((void**)&Wt2, g_Wt2);
    cudaGetSymbolAddress((void**)&bf0, g_bf0);
    cudaGetSymbolAddress((void**)&bf1, g_bf1);
    cudaGetSymbolAddress((void**)&bf2, g_bf2);

    // fold BN into transposed weights
    fold_kernel<<<(H0 * XDIM + 255) / 256, 256>>>(W0, b0, g0, be0, Wt0, bf0, H0, XDIM);
    fold_kernel<<<(H1 * H0   + 255) / 256, 256>>>(W1, b1, g1, be1, Wt1, bf1, H1, H0);
    fold_kernel<<<(H2 * H1   + 255) / 256, 256>>>(W2, b2, g2, be2, Wt2, bf2, H2, H1);

    // embedding gather + FM
    embed_fm_kernel<<<BATCH / 8, 256>>>(sp, dense, emb, bias, fmb);

    // fused MLP
    cudaFuncSetAttribute(mlp_kernel, cudaFuncAttributeMaxDynamicSharedMemorySize, SMEM_BYTES);
    mlp_kernel<<<BATCH / 64, 256, SMEM_BYTES>>>(Wo, bo, out);
}

// round 4
// speedup vs baseline: 2.0116x; 2.0116x over previous
#include <cuda_runtime.h>
#include <cuda_bf16.h>
#include <math.h>
#include <stdint.h>

// ================= Problem constants =================
#define BATCH   16384
#define NFIELD  10
#define EMB     32
#define DENSE   16
#define K0      336         // 21 * 16
#define N0      256
#define N1      128
#define N2      64
#define MTILE   64          // samples per CTA
#define NCTA    (BATCH / MTILE)   // 256

__constant__ int c_offsets[NFIELD] = {
    0, 1000000, 1100000, 1101008, 1102012,
    1102114, 1103114, 1103614, 1103664, 1103776
};

// ================= Device scratch =================
__device__ __align__(16) __nv_bfloat16 g_Xhi[BATCH * K0];
__device__ __align__(16) __nv_bfloat16 g_Xlo[BATCH * K0];
__device__ __align__(16) __nv_bfloat16 g_W0hi[N0 * K0];
__device__ __align__(16) __nv_bfloat16 g_W0lo[N0 * K0];
__device__ __align__(16) __nv_bfloat16 g_W1hi[N1 * N0];
__device__ __align__(16) __nv_bfloat16 g_W1lo[N1 * N0];
__device__ __align__(16) __nv_bfloat16 g_W2hi[N2 * N1];
__device__ __align__(16) __nv_bfloat16 g_W2lo[N2 * N1];
__device__ float g_bf0[N0], g_bf1[N1], g_bf2[N2];
__device__ float g_fm[BATCH];

// ================= PTX helpers (sm_80-level, compute_103-safe) =================
__device__ __forceinline__ uint32_t smem_u32(const void* p) {
    uint32_t a;
    asm("{ .reg .u64 t; cvta.to.shared.u64 t, %1; cvt.u32.u64 %0, t; }" : "=r"(a) : "l"(p));
    return a;
}
__device__ __forceinline__ void cpa16(uint32_t dst, const void* src) {
    asm volatile("cp.async.cg.shared.global [%0], [%1], 16;" :: "r"(dst), "l"(src) : "memory");
}
__device__ __forceinline__ void cp_commit() {
    asm volatile("cp.async.commit_group;" ::: "memory");
}
template<int N> __device__ __forceinline__ void cp_wait() {
    asm volatile("cp.async.wait_group %0;" :: "n"(N) : "memory");
}
__device__ __forceinline__ void ldsm4(uint32_t* r, uint32_t a) {
    asm volatile("ldmatrix.sync.aligned.m8n8.x4.shared.b16 {%0,%1,%2,%3}, [%4];"
        : "=r"(r[0]), "=r"(r[1]), "=r"(r[2]), "=r"(r[3]) : "r"(a));
}
__device__ __forceinline__ void mma_bf16(float* c, const uint32_t* a, const uint32_t* b) {
    asm volatile("mma.sync.aligned.m16n8k16.row.col.f32.bf16.bf16.f32 "
        "{%0,%1,%2,%3}, {%4,%5,%6,%7}, {%8,%9}, {%0,%1,%2,%3};"
        : "+f"(c[0]), "+f"(c[1]), "+f"(c[2]), "+f"(c[3])
        : "r"(a[0]), "r"(a[1]), "r"(a[2]), "r"(a[3]), "r"(b[0]), "r"(b[1]));
}
__device__ __forceinline__ uint32_t pack_bf(float lo, float hi) {
    __nv_bfloat162 t = __floats2bfloat162_rn(lo, hi);   // .x = lo half
    return *(uint32_t*)&t;
}

// ================= Kernel 1: weight prep (fold BN, split hi/lo) =================
__global__ void prep_w(const float* __restrict__ W, const float* __restrict__ b,
                       const float* __restrict__ g, const float* __restrict__ be,
                       __nv_bfloat16* __restrict__ hi, __nv_bfloat16* __restrict__ lo,
                       float* __restrict__ bf, int OUT, int IN)
{
    const float inv = 0.9999950000374997f;   // 1/sqrt(1+1e-5)
    int i = blockIdx.x * blockDim.x + threadIdx.x;
    if (i < OUT) bf[i] = b[i] * (g[i] * inv) + be[i];
    if (i >= OUT * IN) return;
    int n = i / IN;
    float w = W[i] * (g[n] * inv);
    __nv_bfloat16 h = __float2bfloat16(w);
    hi[i] = h;
    lo[i] = __float2bfloat16(w - __bfloat162float(h));
}

// ================= Kernel 2: embedding gather + FM + X hi/lo =================
__device__ __forceinline__ void store_x(int b, int col, float v) {
    __nv_bfloat16 h = __float2bfloat16(v);
    g_Xhi[(size_t)b * K0 + col] = h;
    g_Xlo[(size_t)b * K0 + col] = __float2bfloat16(v - __bfloat162float(h));
}

__global__ void embed_fm_kernel(const int* __restrict__ sp, const float* __restrict__ dense,
                                const float* __restrict__ emb, const float* __restrict__ bias,
                                const float* __restrict__ fmb)
{
    int w = threadIdx.x >> 5, l = threadIdx.x & 31;
    int b = blockIdx.x * 8 + w;

    float s = 0.f, sq = 0.f;
#pragma unroll
    for (int f = 0; f < NFIELD; f++) {
        int row = sp[b * NFIELD + f] + c_offsets[f];
        float e = __ldg(&emb[(size_t)row * EMB + l]);
        s += e; sq += e * e;
        store_x(b, f * EMB + l, e);
    }
    if (l < DENSE) store_x(b, NFIELD * EMB + l, dense[b * DENSE + l]);

    float part = 0.5f * (s * s - sq);
    if (l < NFIELD)
        part += __ldg(&bias[sp[b * NFIELD + l] + c_offsets[l]]);
#pragma unroll
    for (int d = 16; d > 0; d >>= 1)
        part += __shfl_down_sync(0xFFFFFFFFu, part, d);
    if (l == 0) g_fm[b] = fmb[0] + part;
}

// ================= Kernel 3: HMMA fused MLP =================
// SMEM layout (bytes from dynamic base):
//  stage buffers (x2): per stage 30720 = XsHi(3072) XsLo(3072) WsHi(12288) WsLo(12288)
//  (layer1 W uses stage +0/+6144; layer2 W uses stage +0/+3072)
#define STAGE_SZ 30720
#define SX_HI 0
#define SX_LO 3072
#define SW_HI 6144
#define SW_LO 18432
#define C1_HI 61440          // [64][264 bf16] stride 528B, plane 33792
#define C1_LO 95232
#define C2_HI 129024         // [64][136 bf16] stride 272B, plane 17408
#define C2_LO 146432
#define C3F   163840         // [64][68 f32]  stride 272B
#define SMEM_DYN (163840 + 17408)

__global__ __launch_bounds__(256, 1)
void mlp_kernel(const float* __restrict__ Wo, const float* __restrict__ bo,
                float* __restrict__ out)
{
    extern __shared__ char smc[];
    const uint32_t sb = smem_u32(smc);
    const int t = threadIdx.x, w = t >> 5, lane = t & 31;
    const int cta = blockIdx.x;
    const int m0g = cta * MTILE;
    const int wm = (w >> 2) * 32;     // warp m offset (0 or 32)
    const int wn = (w & 3);           // warp n group 0..3
    const uint32_t lrow = (uint32_t)(lane & 15);
    const uint32_t lhalf = (uint32_t)(lane >> 4) * 16u;

    // ---------------- copy helpers ----------------
    auto copy0 = [&](int ks, int s) {
        uint32_t stg = sb + (uint32_t)s * STAGE_SZ;
        for (int c = t; c < 1280; c += 256) {
            uint32_t dst; const __nv_bfloat16* src;
            if (c < 256) {
                int m = c >> 2, half = (c >> 1) & 1, p = c & 1;
                dst = stg + (p ? SX_LO : SX_HI) + m * 48 + half * 16;
                src = (p ? g_Xlo : g_Xhi) + (size_t)(m0g + m) * K0 + ks * 16 + half * 8;
            } else {
                int q = c - 256; int n = q >> 2, half = (q >> 1) & 1, p = q & 1;
                dst = stg + (p ? SW_LO : SW_HI) + n * 48 + half * 16;
                src = (p ? g_W0lo : g_W0hi) + (size_t)n * K0 + ks * 16 + half * 8;
            }
            cpa16(dst, src);
        }
        cp_commit();
    };
    auto copy1 = [&](int ks, int s) {
        uint32_t stg = sb + (uint32_t)s * STAGE_SZ;
        for (int c = t; c < 512; c += 256) {
            int n = c >> 2, half = (c >> 1) & 1, p = c & 1;
            uint32_t dst = stg + p * 6144 + n * 48 + half * 16;
            const __nv_bfloat16* src = (p ? g_W1lo : g_W1hi) + (size_t)n * N0 + ks * 16 + half * 8;
            cpa16(dst, src);
        }
        cp_commit();
    };
    auto copy2 = [&](int ks, int s) {
        uint32_t stg = sb + (uint32_t)s * STAGE_SZ;
        {
            int c = t;  // exactly 256 chunks
            int n = c >> 2, half = (c >> 1) & 1, p = c & 1;
            uint32_t dst = stg + p * 3072 + n * 48 + half * 16;
            const __nv_bfloat16* src = (p ? g_W2lo : g_W2hi) + (size_t)n * N1 + ks * 16 + half * 8;
            cpa16(dst, src);
        }
        cp_commit();
    };

    // ================= Layer 0: [64x336] @ [336->256] =================
    float acc0[2][8][4];
#pragma unroll
    for (int i = 0; i < 2; i++)
#pragma unroll
        for (int j = 0; j < 8; j++)
#pragma unroll
            for (int q = 0; q < 4; q++) acc0[i][j][q] = 0.f;

    copy0(0, 0);
    for (int ks = 0; ks < 21; ks++) {
        if (ks + 1 < 21) { copy0(ks + 1, (ks + 1) & 1); cp_wait<1>(); }
        else             { cp_wait<0>(); }
        __syncthreads();
        uint32_t stg = sb + (uint32_t)(ks & 1) * STAGE_SZ;
        uint32_t aH[2][4], aL[2][4];
#pragma unroll
        for (int i = 0; i < 2; i++) {
            uint32_t rb = stg + (wm + 16 * i + lrow) * 48 + lhalf;
            ldsm4(aH[i], rb + SX_HI);
            ldsm4(aL[i], rb + SX_LO);
        }
        uint32_t bH[8][2], bL[8][2];
#pragma unroll
        for (int nb = 0; nb < 4; nb++) {
            uint32_t r[4];
            uint32_t rb = stg + (wn * 64 + 16 * nb + lrow) * 48 + lhalf;
            ldsm4(r, rb + SW_HI);
            bH[2 * nb][0] = r[0]; bH[2 * nb][1] = r[2];
            bH[2 * nb + 1][0] = r[1]; bH[2 * nb + 1][1] = r[3];
            ldsm4(r, rb + SW_LO);
            bL[2 * nb][0] = r[0]; bL[2 * nb][1] = r[2];
            bL[2 * nb + 1][0] = r[1]; bL[2 * nb + 1][1] = r[3];
        }
#pragma unroll
        for (int i = 0; i < 2; i++)
#pragma unroll
            for (int j = 0; j < 8; j++) {
                mma_bf16(acc0[i][j], aH[i], bH[j]);
                mma_bf16(acc0[i][j], aH[i], bL[j]);
                mma_bf16(acc0[i][j], aL[i], bH[j]);
            }
        __syncthreads();
    }

    // prefetch layer1 tile 0 (stage buffers free now), then epilogue 0
    copy1(0, 0);
    {
#pragma unroll
        for (int i = 0; i < 2; i++)
#pragma unroll
            for (int j = 0; j < 8; j++) {
                int col = wn * 64 + j * 8 + (lane & 3) * 2;
                int row = wm + 16 * i + (lane >> 2);
                float b0v = g_bf0[col], b1v = g_bf0[col + 1];
                float v0 = fmaxf(acc0[i][j][0] + b0v, 0.f);
                float v1 = fmaxf(acc0[i][j][1] + b1v, 0.f);
                float v2 = fmaxf(acc0[i][j][2] + b0v, 0.f);
                float v3 = fmaxf(acc0[i][j][3] + b1v, 0.f);
                __nv_bfloat16 h0 = __float2bfloat16(v0), h1 = __float2bfloat16(v1);
                __nv_bfloat16 h2 = __float2bfloat16(v2), h3 = __float2bfloat16(v3);
                *(uint32_t*)(smc + C1_HI + row * 528 + col * 2) =
                    pack_bf(__bfloat162float(h0), __bfloat162float(h1));
                *(uint32_t*)(smc + C1_LO + row * 528 + col * 2) =
                    pack_bf(v0 - __bfloat162float(h0), v1 - __bfloat162float(h1));
                *(uint32_t*)(smc + C1_HI + (row + 8) * 528 + col * 2) =
                    pack_bf(__bfloat162float(h2), __bfloat162float(h3));
                *(uint32_t*)(smc + C1_LO + (row + 8) * 528 + col * 2) =
                    pack_bf(v2 - __bfloat162float(h2), v3 - __bfloat162float(h3));
            }
    }

    // ================= Layer 1: [64x256] @ [256->128] =================
    float acc1[2][4][4];
#pragma unroll
    for (int i = 0; i < 2; i++)
#pragma unroll
        for (int j = 0; j < 4; j++)
#pragma unroll
            for (int q = 0; q < 4; q++) acc1[i][j][q] = 0.f;

    for (int ks = 0; ks < 16; ks++) {
        if (ks + 1 < 16) { copy1(ks + 1, (ks + 1) & 1); cp_wait<1>(); }
        else             { cp_wait<0>(); }
        __syncthreads();
        uint32_t stg = sb + (uint32_t)(ks & 1) * STAGE_SZ;
        uint32_t aH[2][4], aL[2][4];
#pragma unroll
        for (int i = 0; i < 2; i++) {
            uint32_t rb = sb + C1_HI + (wm + 16 * i + lrow) * 528 + ks * 32 + lhalf;
            ldsm4(aH[i], rb);
            ldsm4(aL[i], rb + (C1_LO - C1_HI));
        }
        uint32_t bH[4][2], bL[4][2];
#pragma unroll
        for (int nb = 0; nb < 2; nb++) {
            uint32_t r[4];
            uint32_t rb = stg + (wn * 32 + 16 * nb + lrow) * 48 + lhalf;
            ldsm4(r, rb);
            bH[2 * nb][0] = r[0]; bH[2 * nb][1] = r[2];
            bH[2 * nb + 1][0] = r[1]; bH[2 * nb + 1][1] = r[3];
            ldsm4(r, rb + 6144);
            bL[2 * nb][0] = r[0]; bL[2 * nb][1] = r[2];
            bL[2 * nb + 1][0] = r[1]; bL[2 * nb + 1][1] = r[3];
        }
#pragma unroll
        for (int i = 0; i < 2; i++)
#pragma unroll
            for (int j = 0; j < 4; j++) {
                mma_bf16(acc1[i][j], aH[i], bH[j]);
                mma_bf16(acc1[i][j], aH[i], bL[j]);
                mma_bf16(acc1[i][j], aL[i], bH[j]);
            }
        __syncthreads();
    }

    copy2(0, 0);
    {
#pragma unroll
        for (int i = 0; i < 2; i++)
#pragma unroll
            for (int j = 0; j < 4; j++) {
                int col = wn * 32 + j * 8 + (lane & 3) * 2;
                int row = wm + 16 * i + (lane >> 2);
                float b0v = g_bf1[col], b1v = g_bf1[col + 1];
                float v0 = fmaxf(acc1[i][j][0] + b0v, 0.f);
                float v1 = fmaxf(acc1[i][j][1] + b1v, 0.f);
                float v2 = fmaxf(acc1[i][j][2] + b0v, 0.f);
                float v3 = fmaxf(acc1[i][j][3] + b1v, 0.f);
                __nv_bfloat16 h0 = __float2bfloat16(v0), h1 = __float2bfloat16(v1);
                __nv_bfloat16 h2 = __float2bfloat16(v2), h3 = __float2bfloat16(v3);
                *(uint32_t*)(smc + C2_HI + row * 272 + col * 2) =
                    pack_bf(__bfloat162float(h0), __bfloat162float(h1));
                *(uint32_t*)(smc + C2_LO + row * 272 + col * 2) =
                    pack_bf(v0 - __bfloat162float(h0), v1 - __bfloat162float(h1));
                *(uint32_t*)(smc + C2_HI + (row + 8) * 272 + col * 2) =
                    pack_bf(__bfloat162float(h2), __bfloat162float(h3));
                *(uint32_t*)(smc + C2_LO + (row + 8) * 272 + col * 2) =
                    pack_bf(v2 - __bfloat162float(h2), v3 - __bfloat162float(h3));
            }
    }

    // ================= Layer 2: [64x128] @ [128->64] =================
    float acc2[2][2][4];
#pragma unroll
    for (int i = 0; i < 2; i++)
#pragma unroll
        for (int j = 0; j < 2; j++)
#pragma unroll
            for (int q = 0; q < 4; q++) acc2[i][j][q] = 0.f;

    for (int ks = 0; ks < 8; ks++) {
        if (ks + 1 < 8) { copy2(ks + 1, (ks + 1) & 1); cp_wait<1>(); }
        else            { cp_wait<0>(); }
        __syncthreads();
        uint32_t stg = sb + (uint32_t)(ks & 1) * STAGE_SZ;
        uint32_t aH[2][4], aL[2][4];
#pragma unroll
        for (int i = 0; i < 2; i++) {
            uint32_t rb = sb + C2_HI + (wm + 16 * i + lrow) * 272 + ks * 32 + lhalf;
            ldsm4(aH[i], rb);
            ldsm4(aL[i], rb + (C2_LO - C2_HI));
        }
        uint32_t bH[2][2], bL[2][2];
        {
            uint32_t r[4];
            uint32_t rb = stg + (wn * 16 + lrow) * 48 + lhalf;
            ldsm4(r, rb);
            bH[0][0] = r[0]; bH[0][1] = r[2]; bH[1][0] = r[1]; bH[1][1] = r[3];
            ldsm4(r, rb + 3072);
            bL[0][0] = r[0]; bL[0][1] = r[2]; bL[1][0] = r[1]; bL[1][1] = r[3];
        }
#pragma unroll
        for (int i = 0; i < 2; i++)
#pragma unroll
            for (int j = 0; j < 2; j++) {
                mma_bf16(acc2[i][j], aH[i], bH[j]);
                mma_bf16(acc2[i][j], aH[i], bL[j]);
                mma_bf16(acc2[i][j], aL[i], bH[j]);
            }
        __syncthreads();
    }

    // epilogue 2: relu -> f32 C3
    {
#pragma unroll
        for (int i = 0; i < 2; i++)
#pragma unroll
            for (int j = 0; j < 2; j++) {
                int col = wn * 16 + j * 8 + (lane & 3) * 2;
                int row = wm + 16 * i + (lane >> 2);
                float b0v = g_bf2[col], b1v = g_bf2[col + 1];
                float2 v01 = make_float2(fmaxf(acc2[i][j][0] + b0v, 0.f),
                                         fmaxf(acc2[i][j][1] + b1v, 0.f));
                float2 v23 = make_float2(fmaxf(acc2[i][j][2] + b0v, 0.f),
                                         fmaxf(acc2[i][j][3] + b1v, 0.f));
                *(float2*)(smc + C3F + row * 272 + col * 4) = v01;
                *(float2*)(smc + C3F + (row + 8) * 272 + col * 4) = v23;
            }
    }
    __syncthreads();

    // ================= Output: dot Wo + fm + sigmoid =================
    if (t < MTILE) {
        const float* c3 = (const float*)(smc + C3F) + t * 68;
        float s = g_fm[m0g + t] + bo[0];
#pragma unroll
        for (int k = 0; k < N2; k++)
            s = fmaf(c3[k], __ldg(&Wo[k]), s);
        out[m0g + t] = 1.f / (1.f + expf(-s));
    }
}

// ================= Launch =================
extern "C" void kernel_launch(void* const* d_in, const int* in_sizes, int n_in,
                              void* d_out, int out_size)
{
    const int*   sp    = (const int*)  d_in[0];
    const float* dense = (const float*)d_in[1];
    const float* emb   = (const float*)d_in[2];
    const float* bias  = (const float*)d_in[3];
    const float* fmb   = (const float*)d_in[4];
    const float* Wo    = (const float*)d_in[5];
    const float* bo    = (const float*)d_in[6];
    const float* W0    = (const float*)d_in[7];
    const float* b0    = (const float*)d_in[8];
    const float* g0    = (const float*)d_in[9];
    const float* be0   = (const float*)d_in[10];
    const float* W1    = (const float*)d_in[11];
    const float* b1    = (const float*)d_in[12];
    const float* g1    = (const float*)d_in[13];
    const float* be1   = (const float*)d_in[14];
    const float* W2    = (const float*)d_in[15];
    const float* b2    = (const float*)d_in[16];
    const float* g2    = (const float*)d_in[17];
    const float* be2   = (const float*)d_in[18];
    float* out = (float*)d_out;

    __nv_bfloat16 *w0h, *w0l, *w1h, *w1l, *w2h, *w2l;
    float *bf0, *bf1, *bf2;
    cudaGetSymbolAddress((void**)&w0h, g_W0hi);
    cudaGetSymbolAddress((void**)&w0l, g_W0lo);
    cudaGetSymbolAddress((void**)&w1h, g_W1hi);
    cudaGetSymbolAddress((void**)&w1l, g_W1lo);
    cudaGetSymbolAddress((void**)&w2h, g_W2hi);
    cudaGetSymbolAddress((void**)&w2l, g_W2lo);
    cudaGetSymbolAddress((void**)&bf0, g_bf0);
    cudaGetSymbolAddress((void**)&bf1, g_bf1);
    cudaGetSymbolAddress((void**)&bf2, g_bf2);

    prep_w<<<(N0 * K0 + 255) / 256, 256>>>(W0, b0, g0, be0, w0h, w0l, bf0, N0, K0);
    prep_w<<<(N1 * N0 + 255) / 256, 256>>>(W1, b1, g1, be1, w1h, w1l, bf1, N1, N0);
    prep_w<<<(N2 * N1 + 255) / 256, 256>>>(W2, b2, g2, be2, w2h, w2l, bf2, N2, N1);

    embed_fm_kernel<<<BATCH / 8, 256>>>(sp, dense, emb, bias, fmb);

    cudaFuncSetAttribute(mlp_kernel, cudaFuncAttributeMaxDynamicSharedMemorySize, SMEM_DYN);
    mlp_kernel<<<NCTA, 256, SMEM_DYN>>>(Wo, bo, out);
}

// round 5
// speedup vs baseline: 2.1294x; 1.0585x over previous
#include <cuda_runtime.h>
#include <cuda_bf16.h>
#include <math.h>
#include <stdint.h>

// ================= Problem constants =================
#define BATCH   16384
#define NFIELD  10
#define EMB     32
#define DENSE   16
#define K0      336         // 21 * 16
#define N0      256
#define N1      128
#define N2      64
#define MTILE   64
#define NCTA    (BATCH / MTILE)   // 256

__constant__ int c_offsets[NFIELD] = {
    0, 1000000, 1100000, 1101008, 1102012,
    1102114, 1103114, 1103614, 1103664, 1103776
};

// ================= Device scratch (weights only) =================
__device__ __align__(16) __nv_bfloat16 g_W0hi[N0 * K0];
__device__ __align__(16) __nv_bfloat16 g_W0lo[N0 * K0];
__device__ __align__(16) __nv_bfloat16 g_W1hi[N1 * N0];
__device__ __align__(16) __nv_bfloat16 g_W1lo[N1 * N0];
__device__ __align__(16) __nv_bfloat16 g_W2hi[N2 * N1];
__device__ __align__(16) __nv_bfloat16 g_W2lo[N2 * N1];
__device__ float g_bf0[N0], g_bf1[N1], g_bf2[N2];

// ================= PTX helpers =================
__device__ __forceinline__ uint32_t smem_u32(const void* p) {
    uint32_t a;
    asm("{ .reg .u64 t; cvta.to.shared.u64 t, %1; cvt.u32.u64 %0, t; }" : "=r"(a) : "l"(p));
    return a;
}
__device__ __forceinline__ void cpa16(uint32_t dst, const void* src) {
    asm volatile("cp.async.cg.shared.global [%0], [%1], 16;" :: "r"(dst), "l"(src) : "memory");
}
__device__ __forceinline__ void cp_commit() {
    asm volatile("cp.async.commit_group;" ::: "memory");
}
template<int N> __device__ __forceinline__ void cp_wait() {
    asm volatile("cp.async.wait_group %0;" :: "n"(N) : "memory");
}
__device__ __forceinline__ void ldsm4(uint32_t* r, uint32_t a) {
    asm volatile("ldmatrix.sync.aligned.m8n8.x4.shared.b16 {%0,%1,%2,%3}, [%4];"
        : "=r"(r[0]), "=r"(r[1]), "=r"(r[2]), "=r"(r[3]) : "r"(a));
}
__device__ __forceinline__ void mma_bf16(float* c, const uint32_t* a, const uint32_t* b) {
    asm volatile("mma.sync.aligned.m16n8k16.row.col.f32.bf16.bf16.f32 "
        "{%0,%1,%2,%3}, {%4,%5,%6,%7}, {%8,%9}, {%0,%1,%2,%3};"
        : "+f"(c[0]), "+f"(c[1]), "+f"(c[2]), "+f"(c[3])
        : "r"(a[0]), "r"(a[1]), "r"(a[2]), "r"(a[3]), "r"(b[0]), "r"(b[1]));
}
__device__ __forceinline__ uint32_t pack_bf(float lo, float hi) {
    __nv_bfloat162 t = __floats2bfloat162_rn(lo, hi);
    return *(uint32_t*)&t;
}

// ================= Kernel 1: all weight prep in one launch =================
#define S0SZ (N0 * K0)        // 86016
#define S1SZ (N1 * N0)        // 32768
#define S2SZ (N2 * N1)        // 8192
#define PREP_TOT (S0SZ + S1SZ + S2SZ)   // 126976 = 496 * 256

__global__ void prep_all(const float* __restrict__ W0, const float* __restrict__ b0,
                         const float* __restrict__ g0, const float* __restrict__ be0,
                         const float* __restrict__ W1, const float* __restrict__ b1,
                         const float* __restrict__ g1, const float* __restrict__ be1,
                         const float* __restrict__ W2, const float* __restrict__ b2,
                         const float* __restrict__ g2, const float* __restrict__ be2)
{
    const float inv = 0.9999950000374997f;   // 1/sqrt(1+1e-5)
    int i = blockIdx.x * blockDim.x + threadIdx.x;
    const float* W; const float* g; __nv_bfloat16 *hi, *lo; int IN, li;
    if (i < S0SZ) {
        W = W0; g = g0; hi = g_W0hi; lo = g_W0lo; IN = K0; li = i;
        if (i < N0) g_bf0[i] = b0[i] * (g0[i] * inv) + be0[i];
    } else if (i < S0SZ + S1SZ) {
        W = W1; g = g1; hi = g_W1hi; lo = g_W1lo; IN = N0; li = i - S0SZ;
        if (li < N1) g_bf1[li] = b1[li] * (g1[li] * inv) + be1[li];
    } else if (i < PREP_TOT) {
        W = W2; g = g2; hi = g_W2hi; lo = g_W2lo; IN = N1; li = i - S0SZ - S1SZ;
        if (li < N2) g_bf2[li] = b2[li] * (g2[li] * inv) + be2[li];
    } else return;
    int n = li / IN;
    float w = W[li] * (g[n] * inv);
    __nv_bfloat16 h = __float2bfloat16(w);
    hi[li] = h;
    lo[li] = __float2bfloat16(w - __bfloat162float(h));
}

// ================= Kernel 2: fused embed + FM + HMMA MLP =================
// SMEM byte map (dynamic base):
//  X_HI  @ 0       : [64][688B]  (44032)   -- alias after layer0:
//  X_LO  @ 44032   : [64][688B]  (44032)      C2_HI @0 (17408), C2_LO @17408, C3F @34816
//  WSTG  @ 88064   : 2 stages x 24576
//  C1_HI @ 137216  : [64][528B]  (33792)
//  C1_LO @ 171008  : [64][528B]  (33792)
//  FMS   @ 204800  : 64 floats
#define X_HI   0
#define X_LO   44032
#define XSTR   688
#define WSTG   88064
#define WSSZ   24576
#define C1_HI  137216
#define C1_LO  171008
#define C2_HI  0
#define C2_LO  17408
#define C3F    34816
#define FMS    204800
#define SMEM_DYN (204800 + 256)

__global__ __launch_bounds__(256, 1)
void mlp_kernel(const int* __restrict__ sp, const float* __restrict__ dense,
                const float* __restrict__ emb, const float* __restrict__ bias,
                const float* __restrict__ fmb,
                const float* __restrict__ Wo, const float* __restrict__ bo,
                float* __restrict__ out)
{
    extern __shared__ char smc[];
    const uint32_t sb = smem_u32(smc);
    const int t = threadIdx.x, w = t >> 5, lane = t & 31;
    const int m0g = blockIdx.x * MTILE;
    const int wm = (w >> 2) * 32;
    const int wn = (w & 3);
    const uint32_t lrow = (uint32_t)(lane & 15);
    const uint32_t lhalf = (uint32_t)(lane >> 4) * 16u;

    // ---------------- copy helpers (weights only) ----------------
    auto copy0 = [&](int ks, int s) {
        uint32_t stg = sb + WSTG + (uint32_t)s * WSSZ;
#pragma unroll
        for (int r = 0; r < 4; r++) {
            int c = t + r * 256;                    // 1024 chunks
            int n = c >> 2, half = (c >> 1) & 1, p = c & 1;
            uint32_t dst = stg + p * 12288 + n * 48 + half * 16;
            const __nv_bfloat16* src = (p ? g_W0lo : g_W0hi) + (size_t)n * K0 + ks * 16 + half * 8;
            cpa16(dst, src);
        }
        cp_commit();
    };
    auto copy1 = [&](int ks, int s) {
        uint32_t stg = sb + WSTG + (uint32_t)s * WSSZ;
#pragma unroll
        for (int r = 0; r < 2; r++) {
            int c = t + r * 256;                    // 512 chunks
            int n = c >> 2, half = (c >> 1) & 1, p = c & 1;
            uint32_t dst = stg + p * 6144 + n * 48 + half * 16;
            const __nv_bfloat16* src = (p ? g_W1lo : g_W1hi) + (size_t)n * N0 + ks * 16 + half * 8;
            cpa16(dst, src);
        }
        cp_commit();
    };
    auto copy2 = [&](int ks, int s) {
        uint32_t stg = sb + WSTG + (uint32_t)s * WSSZ;
        {
            int c = t;                              // 256 chunks
            int n = c >> 2, half = (c >> 1) & 1, p = c & 1;
            uint32_t dst = stg + p * 3072 + n * 48 + half * 16;
            const __nv_bfloat16* src = (p ? g_W2lo : g_W2hi) + (size_t)n * N1 + ks * 16 + half * 8;
            cpa16(dst, src);
        }
        cp_commit();
    };

    // ---------------- Prologue: kick weight stage 0, gather X, FM ----------------
    copy0(0, 0);
#pragma unroll 1
    for (int i = 0; i < 8; i++) {
        int m = w * 8 + i;
        int b = m0g + m;
        float s = 0.f, sq = 0.f;
#pragma unroll
        for (int f = 0; f < NFIELD; f++) {
            int row = sp[b * NFIELD + f] + c_offsets[f];
            float e = __ldg(&emb[(size_t)row * EMB + lane]);
            s += e; sq += e * e;
            __nv_bfloat16 h = __float2bfloat16(e);
            *(__nv_bfloat16*)(smc + X_HI + m * XSTR + (f * EMB + lane) * 2) = h;
            *(__nv_bfloat16*)(smc + X_LO + m * XSTR + (f * EMB + lane) * 2) =
                __float2bfloat16(e - __bfloat162float(h));
        }
        if (lane < DENSE) {
            float dv = dense[b * DENSE + lane];
            __nv_bfloat16 h = __float2bfloat16(dv);
            *(__nv_bfloat16*)(smc + X_HI + m * XSTR + (320 + lane) * 2) = h;
            *(__nv_bfloat16*)(smc + X_LO + m * XSTR + (320 + lane) * 2) =
                __float2bfloat16(dv - __bfloat162float(h));
        }
        float part = 0.5f * (s * s - sq);
        if (lane < NFIELD)
            part += __ldg(&bias[sp[b * NFIELD + lane] + c_offsets[lane]]);
#pragma unroll
        for (int d = 16; d > 0; d >>= 1)
            part += __shfl_down_sync(0xFFFFFFFFu, part, d);
        if (lane == 0) *(float*)(smc + FMS + m * 4) = part;
    }

    // ================= Layer 0: [64x336] -> 256 =================
    float acc0[2][8][4];
#pragma unroll
    for (int i = 0; i < 2; i++)
#pragma unroll
        for (int j = 0; j < 8; j++)
#pragma unroll
            for (int q = 0; q < 4; q++) acc0[i][j][q] = 0.f;

    for (int ks = 0; ks < 21; ks++) {
        cp_wait<0>();
        __syncthreads();
        uint32_t stg = sb + WSTG + (uint32_t)(ks & 1) * WSSZ;
        uint32_t aH[2][4], aL[2][4];
#pragma unroll
        for (int i = 0; i < 2; i++) {
            uint32_t rb = sb + X_HI + (wm + 16 * i + lrow) * XSTR + ks * 32 + lhalf;
            ldsm4(aH[i], rb);
            ldsm4(aL[i], rb + X_LO);
        }
        uint32_t bH[8][2], bL[8][2];
#pragma unroll
        for (int nb = 0; nb < 4; nb++) {
            uint32_t r[4];
            uint32_t rb = stg + (wn * 64 + 16 * nb + lrow) * 48 + lhalf;
            ldsm4(r, rb);
            bH[2 * nb][0] = r[0]; bH[2 * nb][1] = r[2];
            bH[2 * nb + 1][0] = r[1]; bH[2 * nb + 1][1] = r[3];
            ldsm4(r, rb + 12288);
            bL[2 * nb][0] = r[0]; bL[2 * nb][1] = r[2];
            bL[2 * nb + 1][0] = r[1]; bL[2 * nb + 1][1] = r[3];
        }
        if (ks + 1 < 21) copy0(ks + 1, (ks + 1) & 1);
#pragma unroll
        for (int i = 0; i < 2; i++)
#pragma unroll
            for (int j = 0; j < 8; j++) {
                mma_bf16(acc0[i][j], aH[i], bH[j]);
                mma_bf16(acc0[i][j], aH[i], bL[j]);
                mma_bf16(acc0[i][j], aL[i], bH[j]);
            }
    }
    __syncthreads();            // all stage reads done; X now dead too
    copy1(0, 0);

    // epilogue 0 -> C1 hi/lo
    {
#pragma unroll
        for (int i = 0; i < 2; i++)
#pragma unroll
            for (int j = 0; j < 8; j++) {
                int col = wn * 64 + j * 8 + (lane & 3) * 2;
                int row = wm + 16 * i + (lane >> 2);
                float b0v = g_bf0[col], b1v = g_bf0[col + 1];
                float v0 = fmaxf(acc0[i][j][0] + b0v, 0.f);
                float v1 = fmaxf(acc0[i][j][1] + b1v, 0.f);
                float v2 = fmaxf(acc0[i][j][2] + b0v, 0.f);
                float v3 = fmaxf(acc0[i][j][3] + b1v, 0.f);
                __nv_bfloat16 h0 = __float2bfloat16(v0), h1 = __float2bfloat16(v1);
                __nv_bfloat16 h2 = __float2bfloat16(v2), h3 = __float2bfloat16(v3);
                *(uint32_t*)(smc + C1_HI + row * 528 + col * 2) =
                    pack_bf(__bfloat162float(h0), __bfloat162float(h1));
                *(uint32_t*)(smc + C1_LO + row * 528 + col * 2) =
                    pack_bf(v0 - __bfloat162float(h0), v1 - __bfloat162float(h1));
                *(uint32_t*)(smc + C1_HI + (row + 8) * 528 + col * 2) =
                    pack_bf(__bfloat162float(h2), __bfloat162float(h3));
                *(uint32_t*)(smc + C1_LO + (row + 8) * 528 + col * 2) =
                    pack_bf(v2 - __bfloat162float(h2), v3 - __bfloat162float(h3));
            }
    }

    // ================= Layer 1: [64x256] -> 128 =================
    float acc1[2][4][4];
#pragma unroll
    for (int i = 0; i < 2; i++)
#pragma unroll
        for (int j = 0; j < 4; j++)
#pragma unroll
            for (int q = 0; q < 4; q++) acc1[i][j][q] = 0.f;

    for (int ks = 0; ks < 16; ks++) {
        cp_wait<0>();
        __syncthreads();
        uint32_t stg = sb + WSTG + (uint32_t)(ks & 1) * WSSZ;
        uint32_t aH[2][4], aL[2][4];
#pragma unroll
        for (int i = 0; i < 2; i++) {
            uint32_t rb = sb + C1_HI + (wm + 16 * i + lrow) * 528 + ks * 32 + lhalf;
            ldsm4(aH[i], rb);
            ldsm4(aL[i], rb + (C1_LO - C1_HI));
        }
        uint32_t bH[4][2], bL[4][2];
#pragma unroll
        for (int nb = 0; nb < 2; nb++) {
            uint32_t r[4];
            uint32_t rb = stg + (wn * 32 + 16 * nb + lrow) * 48 + lhalf;
            ldsm4(r, rb);
            bH[2 * nb][0] = r[0]; bH[2 * nb][1] = r[2];
            bH[2 * nb + 1][0] = r[1]; bH[2 * nb + 1][1] = r[3];
            ldsm4(r, rb + 6144);
            bL[2 * nb][0] = r[0]; bL[2 * nb][1] = r[2];
            bL[2 * nb + 1][0] = r[1]; bL[2 * nb + 1][1] = r[3];
        }
        if (ks + 1 < 16) copy1(ks + 1, (ks + 1) & 1);
#pragma unroll
        for (int i = 0; i < 2; i++)
#pragma unroll
            for (int j = 0; j < 4; j++) {
                mma_bf16(acc1[i][j], aH[i], bH[j]);
                mma_bf16(acc1[i][j], aH[i], bL[j]);
                mma_bf16(acc1[i][j], aL[i], bH[j]);
            }
    }
    __syncthreads();
    copy2(0, 0);

    // epilogue 1 -> C2 hi/lo (aliases dead X region)
    {
#pragma unroll
        for (int i = 0; i < 2; i++)
#pragma unroll
            for (int j = 0; j < 4; j++) {
                int col = wn * 32 + j * 8 + (lane & 3) * 2;
                int row = wm + 16 * i + (lane >> 2);
                float b0v = g_bf1[col], b1v = g_bf1[col + 1];
                float v0 = fmaxf(acc1[i][j][0] + b0v, 0.f);
                float v1 = fmaxf(acc1[i][j][1] + b1v, 0.f);
                float v2 = fmaxf(acc1[i][j][2] + b0v, 0.f);
                float v3 = fmaxf(acc1[i][j][3] + b1v, 0.f);
                __nv_bfloat16 h0 = __float2bfloat16(v0), h1 = __float2bfloat16(v1);
                __nv_bfloat16 h2 = __float2bfloat16(v2), h3 = __float2bfloat16(v3);
                *(uint32_t*)(smc + C2_HI + row * 272 + col * 2) =
                    pack_bf(__bfloat162float(h0), __bfloat162float(h1));
                *(uint32_t*)(smc + C2_LO + row * 272 + col * 2) =
                    pack_bf(v0 - __bfloat162float(h0), v1 - __bfloat162float(h1));
                *(uint32_t*)(smc + C2_HI + (row + 8) * 272 + col * 2) =
                    pack_bf(__bfloat162float(h2), __bfloat162float(h3));
                *(uint32_t*)(smc + C2_LO + (row + 8) * 272 + col * 2) =
                    pack_bf(v2 - __bfloat162float(h2), v3 - __bfloat162float(h3));
            }
    }

    // ================= Layer 2: [64x128] -> 64 =================
    float acc2[2][2][4];
#pragma unroll
    for (int i = 0; i < 2; i++)
#pragma unroll
        for (int j = 0; j < 2; j++)
#pragma unroll
            for (int q = 0; q < 4; q++) acc2[i][j][q] = 0.f;

    for (int ks = 0; ks < 8; ks++) {
        cp_wait<0>();
        __syncthreads();
        uint32_t stg = sb + WSTG + (uint32_t)(ks & 1) * WSSZ;
        uint32_t aH[2][4], aL[2][4];
#pragma unroll
        for (int i = 0; i < 2; i++) {
            uint32_t rb = sb + C2_HI + (wm + 16 * i + lrow) * 272 + ks * 32 + lhalf;
            ldsm4(aH[i], rb);
            ldsm4(aL[i], rb + (C2_LO - C2_HI));
        }
        uint32_t bH[2][2], bL[2][2];
        {
            uint32_t r[4];
            uint32_t rb = stg + (wn * 16 + lrow) * 48 + lhalf;
            ldsm4(r, rb);
            bH[0][0] = r[0]; bH[0][1] = r[2]; bH[1][0] = r[1]; bH[1][1] = r[3];
            ldsm4(r, rb + 3072);
            bL[0][0] = r[0]; bL[0][1] = r[2]; bL[1][0] = r[1]; bL[1][1] = r[3];
        }
        if (ks + 1 < 8) copy2(ks + 1, (ks + 1) & 1);
#pragma unroll
        for (int i = 0; i < 2; i++)
#pragma unroll
            for (int j = 0; j < 2; j++) {
                mma_bf16(acc2[i][j], aH[i], bH[j]);
                mma_bf16(acc2[i][j], aH[i], bL[j]);
                mma_bf16(acc2[i][j], aL[i], bH[j]);
            }
    }

    // epilogue 2 -> C3 (f32)
    {
#pragma unroll
        for (int i = 0; i < 2; i++)
#pragma unroll
            for (int j = 0; j < 2; j++) {
                int col = wn * 16 + j * 8 + (lane & 3) * 2;
                int row = wm + 16 * i + (lane >> 2);
                float b0v = g_bf2[col], b1v = g_bf2[col + 1];
                float2 v01 = make_float2(fmaxf(acc2[i][j][0] + b0v, 0.f),
                                         fmaxf(acc2[i][j][1] + b1v, 0.f));
                float2 v23 = make_float2(fmaxf(acc2[i][j][2] + b0v, 0.f),
                                         fmaxf(acc2[i][j][3] + b1v, 0.f));
                *(float2*)(smc + C3F + row * 272 + col * 4) = v01;
                *(float2*)(smc + C3F + (row + 8) * 272 + col * 4) = v23;
            }
    }
    __syncthreads();

    // ================= Output: dot Wo + fm + sigmoid =================
    if (t < MTILE) {
        const float* c3 = (const float*)(smc + C3F) + t * 68;
        float s = *(const float*)(smc + FMS + t * 4) + fmb[0] + bo[0];
#pragma unroll
        for (int k = 0; k < N2; k++)
            s = fmaf(c3[k], __ldg(&Wo[k]), s);
        out[m0g + t] = 1.f / (1.f + expf(-s));
    }
}

// ================= Launch =================
extern "C" void kernel_launch(void* const* d_in, const int* in_sizes, int n_in,
                              void* d_out, int out_size)
{
    const int*   sp    = (const int*)  d_in[0];
    const float* dense = (const float*)d_in[1];
    const float* emb   = (const float*)d_in[2];
    const float* bias  = (const float*)d_in[3];
    const float* fmb   = (const float*)d_in[4];
    const float* Wo    = (const float*)d_in[5];
    const float* bo    = (const float*)d_in[6];
    const float* W0    = (const float*)d_in[7];
    const float* b0    = (const float*)d_in[8];
    const float* g0    = (const float*)d_in[9];
    const float* be0   = (const float*)d_in[10];
    const float* W1    = (const float*)d_in[11];
    const float* b1    = (const float*)d_in[12];
    const float* g1    = (const float*)d_in[13];
    const float* be1   = (const float*)d_in[14];
    const float* W2    = (const float*)d_in[15];
    const float* b2    = (const float*)d_in[16];
    const float* g2    = (const float*)d_in[17];
    const float* be2   = (const float*)d_in[18];
    float* out = (float*)d_out;

    prep_all<<<PREP_TOT / 256, 256>>>(W0, b0, g0, be0, W1, b1, g1, be1, W2, b2, g2, be2);

    cudaFuncSetAttribute(mlp_kernel, cudaFuncAttributeMaxDynamicSharedMemorySize, SMEM_DYN);
    mlp_kernel<<<NCTA, 256, SMEM_DYN>>>(sp, dense, emb, bias, fmb, Wo, bo, out);
}

// round 6
// speedup vs baseline: 2.9621x; 1.3911x over previous
#include <cuda_runtime.h>
#include <cuda_bf16.h>
#include <math.h>
#include <stdint.h>

// ================= Problem constants =================
#define BATCH   16384
#define NFIELD  10
#define EMB     32
#define DENSE   16
#define K0      336         // 21 * 16
#define N0      256
#define N1      128
#define N2      64
#define MTILE   128
#define NCTA    (BATCH / MTILE)   // 128
#define NTHR    512

__constant__ int c_offsets[NFIELD] = {
    0, 1000000, 1100000, 1101008, 1102012,
    1102114, 1103114, 1103614, 1103664, 1103776
};

// ================= Device scratch (weights only) =================
__device__ __align__(16) __nv_bfloat16 g_W0hi[N0 * K0];
__device__ __align__(16) __nv_bfloat16 g_W0lo[N0 * K0];
__device__ __align__(16) __nv_bfloat16 g_W1hi[N1 * N0];
__device__ __align__(16) __nv_bfloat16 g_W1lo[N1 * N0];
__device__ __align__(16) __nv_bfloat16 g_W2hi[N2 * N1];
__device__ __align__(16) __nv_bfloat16 g_W2lo[N2 * N1];
__device__ float g_bf0[N0], g_bf1[N1], g_bf2[N2];

// ================= PTX helpers =================
__device__ __forceinline__ uint32_t smem_u32(const void* p) {
    uint32_t a;
    asm("{ .reg .u64 t; cvta.to.shared.u64 t, %1; cvt.u32.u64 %0, t; }" : "=r"(a) : "l"(p));
    return a;
}
__device__ __forceinline__ void cpa16(uint32_t dst, const void* src) {
    asm volatile("cp.async.cg.shared.global [%0], [%1], 16;" :: "r"(dst), "l"(src) : "memory");
}
__device__ __forceinline__ void cp_commit() {
    asm volatile("cp.async.commit_group;" ::: "memory");
}
template<int N> __device__ __forceinline__ void cp_wait() {
    asm volatile("cp.async.wait_group %0;" :: "n"(N) : "memory");
}
__device__ __forceinline__ void ldsm4(uint32_t* r, uint32_t a) {
    asm volatile("ldmatrix.sync.aligned.m8n8.x4.shared.b16 {%0,%1,%2,%3}, [%4];"
        : "=r"(r[0]), "=r"(r[1]), "=r"(r[2]), "=r"(r[3]) : "r"(a));
}
__device__ __forceinline__ void mma_bf16(float* c, const uint32_t* a, const uint32_t* b) {
    asm volatile("mma.sync.aligned.m16n8k16.row.col.f32.bf16.bf16.f32 "
        "{%0,%1,%2,%3}, {%4,%5,%6,%7}, {%8,%9}, {%0,%1,%2,%3};"
        : "+f"(c[0]), "+f"(c[1]), "+f"(c[2]), "+f"(c[3])
        : "r"(a[0]), "r"(a[1]), "r"(a[2]), "r"(a[3]), "r"(b[0]), "r"(b[1]));
}
__device__ __forceinline__ uint32_t pack_bf(float lo, float hi) {
    __nv_bfloat162 t = __floats2bfloat162_rn(lo, hi);
    return *(uint32_t*)&t;
}

// ================= Kernel 1: all weight prep in one launch =================
#define S0SZ (N0 * K0)
#define S1SZ (N1 * N0)
#define S2SZ (N2 * N1)
#define PREP_TOT (S0SZ + S1SZ + S2SZ)

__global__ void prep_all(const float* __restrict__ W0, const float* __restrict__ b0,
                         const float* __restrict__ g0, const float* __restrict__ be0,
                         const float* __restrict__ W1, const float* __restrict__ b1,
                         const float* __restrict__ g1, const float* __restrict__ be1,
                         const float* __restrict__ W2, const float* __restrict__ b2,
                         const float* __restrict__ g2, const float* __restrict__ be2)
{
    const float inv = 0.9999950000374997f;   // 1/sqrt(1+1e-5)
    int i = blockIdx.x * blockDim.x + threadIdx.x;
    const float* W; const float* g; __nv_bfloat16 *hi, *lo; int IN, li;
    if (i < S0SZ) {
        W = W0; g = g0; hi = g_W0hi; lo = g_W0lo; IN = K0; li = i;
        if (i < N0) g_bf0[i] = b0[i] * (g0[i] * inv) + be0[i];
    } else if (i < S0SZ + S1SZ) {
        W = W1; g = g1; hi = g_W1hi; lo = g_W1lo; IN = N0; li = i - S0SZ;
        if (li < N1) g_bf1[li] = b1[li] * (g1[li] * inv) + be1[li];
    } else if (i < PREP_TOT) {
        W = W2; g = g2; hi = g_W2hi; lo = g_W2lo; IN = N1; li = i - S0SZ - S1SZ;
        if (li < N2) g_bf2[li] = b2[li] * (g2[li] * inv) + be2[li];
    } else return;
    int n = li / IN;
    float w = W[li] * (g[n] * inv);
    __nv_bfloat16 h = __float2bfloat16(w);
    hi[li] = h;
    lo[li] = __float2bfloat16(w - __bfloat162float(h));
}

// ================= Kernel 2: fused embed + FM + HMMA MLP =================
// SMEM byte map:
//  X_HI  @ 0       : [128][688B] (88064)     X dead after layer0 loop:
//  X_LO  @ 88064   : [128][688B] (88064)       C1_HI @0 (67584), C1_LO @67584
//  WSTG  @ 176128  : 2 stages x 24576         C1 dead after layer1 loop:
//  FMS   @ 225280  : 128 floats                 C2_HI @0 (34816), C2_LO @34816, C3F @69632
#define X_HI   0
#define X_LO   88064
#define XSTR   688
#define WSTG   176128
#define WSSZ   24576
#define C1_HI  0
#define C1_LO  67584
#define C2_HI  0
#define C2_LO  34816
#define C3F    69632
#define FMS    225280
#define SMEM_DYN (225280 + 512)

__global__ __launch_bounds__(NTHR, 1)
void mlp_kernel(const int* __restrict__ sp, const float* __restrict__ dense,
                const float* __restrict__ emb, const float* __restrict__ bias,
                const float* __restrict__ fmb,
                const float* __restrict__ Wo, const float* __restrict__ bo,
                float* __restrict__ out)
{
    extern __shared__ char smc[];
    const uint32_t sb = smem_u32(smc);
    const int t = threadIdx.x, w = t >> 5, lane = t & 31;
    const int m0g = blockIdx.x * MTILE;
    const int wm = (w >> 2) * 32;       // 4 m-groups: 0,32,64,96
    const int wn = (w & 3);             // 4 n-groups
    const uint32_t lrow = (uint32_t)(lane & 15);
    const uint32_t lhalf = (uint32_t)(lane >> 4) * 16u;

    // ---------------- copy helpers (weights only) ----------------
    auto copy0 = [&](int ks, int s) {
        uint32_t stg = sb + WSTG + (uint32_t)s * WSSZ;
#pragma unroll
        for (int r = 0; r < 2; r++) {
            int c = t + r * NTHR;                   // 1024 chunks
            int n = c >> 2, half = (c >> 1) & 1, p = c & 1;
            uint32_t dst = stg + p * 12288 + n * 48 + half * 16;
            const __nv_bfloat16* src = (p ? g_W0lo : g_W0hi) + (size_t)n * K0 + ks * 16 + half * 8;
            cpa16(dst, src);
        }
        cp_commit();
    };
    auto copy1 = [&](int ks, int s) {
        uint32_t stg = sb + WSTG + (uint32_t)s * WSSZ;
        {
            int c = t;                              // 512 chunks
            int n = c >> 2, half = (c >> 1) & 1, p = c & 1;
            uint32_t dst = stg + p * 6144 + n * 48 + half * 16;
            const __nv_bfloat16* src = (p ? g_W1lo : g_W1hi) + (size_t)n * N0 + ks * 16 + half * 8;
            cpa16(dst, src);
        }
        cp_commit();
    };
    auto copy2 = [&](int ks, int s) {
        uint32_t stg = sb + WSTG + (uint32_t)s * WSSZ;
        if (t < 256) {                              // 256 chunks
            int c = t;
            int n = c >> 2, half = (c >> 1) & 1, p = c & 1;
            uint32_t dst = stg + p * 3072 + n * 48 + half * 16;
            const __nv_bfloat16* src = (p ? g_W2lo : g_W2hi) + (size_t)n * N1 + ks * 16 + half * 8;
            cpa16(dst, src);
        }
        cp_commit();
    };

    // ---------------- Prologue: kick weight stage 0, gather X, FM ----------------
    copy0(0, 0);
#pragma unroll 1
    for (int i = 0; i < 8; i++) {
        int m = w * 8 + i;                          // 16 warps x 8 = 128
        int b = m0g + m;
        float s = 0.f, sq = 0.f;
#pragma unroll
        for (int f = 0; f < NFIELD; f++) {
            int row = sp[b * NFIELD + f] + c_offsets[f];
            float e = __ldg(&emb[(size_t)row * EMB + lane]);
            s += e; sq += e * e;
            __nv_bfloat16 h = __float2bfloat16(e);
            *(__nv_bfloat16*)(smc + X_HI + m * XSTR + (f * EMB + lane) * 2) = h;
            *(__nv_bfloat16*)(smc + X_LO + m * XSTR + (f * EMB + lane) * 2) =
                __float2bfloat16(e - __bfloat162float(h));
        }
        if (lane < DENSE) {
            float dv = dense[b * DENSE + lane];
            __nv_bfloat16 h = __float2bfloat16(dv);
            *(__nv_bfloat16*)(smc + X_HI + m * XSTR + (320 + lane) * 2) = h;
            *(__nv_bfloat16*)(smc + X_LO + m * XSTR + (320 + lane) * 2) =
                __float2bfloat16(dv - __bfloat162float(h));
        }
        float part = 0.5f * (s * s - sq);
        if (lane < NFIELD)
            part += __ldg(&bias[sp[b * NFIELD + lane] + c_offsets[lane]]);
#pragma unroll
        for (int d = 16; d > 0; d >>= 1)
            part += __shfl_down_sync(0xFFFFFFFFu, part, d);
        if (lane == 0) *(float*)(smc + FMS + m * 4) = part;
    }

    // ================= Layer 0: [128x336] -> 256 =================
    float acc0[2][8][4];
#pragma unroll
    for (int i = 0; i < 2; i++)
#pragma unroll
        for (int j = 0; j < 8; j++)
#pragma unroll
            for (int q = 0; q < 4; q++) acc0[i][j][q] = 0.f;

    for (int ks = 0; ks < 21; ks++) {
        cp_wait<0>();
        __syncthreads();
        uint32_t stg = sb + WSTG + (uint32_t)(ks & 1) * WSSZ;
        uint32_t aH[2][4], aL[2][4];
#pragma unroll
        for (int i = 0; i < 2; i++) {
            uint32_t rb = sb + X_HI + (wm + 16 * i + lrow) * XSTR + ks * 32 + lhalf;
            ldsm4(aH[i], rb);
            ldsm4(aL[i], rb + (X_LO - X_HI));
        }
        if (ks + 1 < 21) copy0(ks + 1, (ks + 1) & 1);
#pragma unroll
        for (int nb = 0; nb < 4; nb++) {
            uint32_t rh[4], rl[4];
            uint32_t rb = stg + (wn * 64 + 16 * nb + lrow) * 48 + lhalf;
            ldsm4(rh, rb);
            ldsm4(rl, rb + 12288);
            uint32_t bH0[2] = {rh[0], rh[2]}, bH1[2] = {rh[1], rh[3]};
            uint32_t bL0[2] = {rl[0], rl[2]}, bL1[2] = {rl[1], rl[3]};
#pragma unroll
            for (int i = 0; i < 2; i++) {
                mma_bf16(acc0[i][2 * nb],     aH[i], bH0);
                mma_bf16(acc0[i][2 * nb],     aH[i], bL0);
                mma_bf16(acc0[i][2 * nb],     aL[i], bH0);
                mma_bf16(acc0[i][2 * nb + 1], aH[i], bH1);
                mma_bf16(acc0[i][2 * nb + 1], aH[i], bL1);
                mma_bf16(acc0[i][2 * nb + 1], aL[i], bH1);
            }
        }
    }
    __syncthreads();            // X + stage reads done; X region now dead
    copy1(0, 0);

    // epilogue 0 -> C1 hi/lo (aliases X)
    {
#pragma unroll
        for (int i = 0; i < 2; i++)
#pragma unroll
            for (int j = 0; j < 8; j++) {
                int col = wn * 64 + j * 8 + (lane & 3) * 2;
                int row = wm + 16 * i + (lane >> 2);
                float b0v = g_bf0[col], b1v = g_bf0[col + 1];
                float v0 = fmaxf(acc0[i][j][0] + b0v, 0.f);
                float v1 = fmaxf(acc0[i][j][1] + b1v, 0.f);
                float v2 = fmaxf(acc0[i][j][2] + b0v, 0.f);
                float v3 = fmaxf(acc0[i][j][3] + b1v, 0.f);
                __nv_bfloat16 h0 = __float2bfloat16(v0), h1 = __float2bfloat16(v1);
                __nv_bfloat16 h2 = __float2bfloat16(v2), h3 = __float2bfloat16(v3);
                *(uint32_t*)(smc + C1_HI + row * 528 + col * 2) =
                    pack_bf(__bfloat162float(h0), __bfloat162float(h1));
                *(uint32_t*)(smc + C1_LO + row * 528 + col * 2) =
                    pack_bf(v0 - __bfloat162float(h0), v1 - __bfloat162float(h1));
                *(uint32_t*)(smc + C1_HI + (row + 8) * 528 + col * 2) =
                    pack_bf(__bfloat162float(h2), __bfloat162float(h3));
                *(uint32_t*)(smc + C1_LO + (row + 8) * 528 + col * 2) =
                    pack_bf(v2 - __bfloat162float(h2), v3 - __bfloat162float(h3));
            }
    }

    // ================= Layer 1: [128x256] -> 128 =================
    float acc1[2][4][4];
#pragma unroll
    for (int i = 0; i < 2; i++)
#pragma unroll
        for (int j = 0; j < 4; j++)
#pragma unroll
            for (int q = 0; q < 4; q++) acc1[i][j][q] = 0.f;

    for (int ks = 0; ks < 16; ks++) {
        cp_wait<0>();
        __syncthreads();
        uint32_t stg = sb + WSTG + (uint32_t)(ks & 1) * WSSZ;
        uint32_t aH[2][4], aL[2][4];
#pragma unroll
        for (int i = 0; i < 2; i++) {
            uint32_t rb = sb + C1_HI + (wm + 16 * i + lrow) * 528 + ks * 32 + lhalf;
            ldsm4(aH[i], rb);
            ldsm4(aL[i], rb + (C1_LO - C1_HI));
        }
        if (ks + 1 < 16) copy1(ks + 1, (ks + 1) & 1);
#pragma unroll
        for (int nb = 0; nb < 2; nb++) {
            uint32_t rh[4], rl[4];
            uint32_t rb = stg + (wn * 32 + 16 * nb + lrow) * 48 + lhalf;
            ldsm4(rh, rb);
            ldsm4(rl, rb + 6144);
            uint32_t bH0[2] = {rh[0], rh[2]}, bH1[2] = {rh[1], rh[3]};
            uint32_t bL0[2] = {rl[0], rl[2]}, bL1[2] = {rl[1], rl[3]};
#pragma unroll
            for (int i = 0; i < 2; i++) {
                mma_bf16(acc1[i][2 * nb],     aH[i], bH0);
                mma_bf16(acc1[i][2 * nb],     aH[i], bL0);
                mma_bf16(acc1[i][2 * nb],     aL[i], bH0);
                mma_bf16(acc1[i][2 * nb + 1], aH[i], bH1);
                mma_bf16(acc1[i][2 * nb + 1], aH[i], bL1);
                mma_bf16(acc1[i][2 * nb + 1], aL[i], bH1);
            }
        }
    }
    __syncthreads();            // C1 reads done; C1 region now dead
    copy2(0, 0);

    // epilogue 1 -> C2 hi/lo (aliases C1)
    {
#pragma unroll
        for (int i = 0; i < 2; i++)
#pragma unroll
            for (int j = 0; j < 4; j++) {
                int col = wn * 32 + j * 8 + (lane & 3) * 2;
                int row = wm + 16 * i + (lane >> 2);
                float b0v = g_bf1[col], b1v = g_bf1[col + 1];
                float v0 = fmaxf(acc1[i][j][0] + b0v, 0.f);
                float v1 = fmaxf(acc1[i][j][1] + b1v, 0.f);
                float v2 = fmaxf(acc1[i][j][2] + b0v, 0.f);
                float v3 = fmaxf(acc1[i][j][3] + b1v, 0.f);
                __nv_bfloat16 h0 = __float2bfloat16(v0), h1 = __float2bfloat16(v1);
                __nv_bfloat16 h2 = __float2bfloat16(v2), h3 = __float2bfloat16(v3);
                *(uint32_t*)(smc + C2_HI + row * 272 + col * 2) =
                    pack_bf(__bfloat162float(h0), __bfloat162float(h1));
                *(uint32_t*)(smc + C2_LO + row * 272 + col * 2) =
                    pack_bf(v0 - __bfloat162float(h0), v1 - __bfloat162float(h1));
                *(uint32_t*)(smc + C2_HI + (row + 8) * 272 + col * 2) =
                    pack_bf(__bfloat162float(h2), __bfloat162float(h3));
                *(uint32_t*)(smc + C2_LO + (row + 8) * 272 + col * 2) =
                    pack_bf(v2 - __bfloat162float(h2), v3 - __bfloat162float(h3));
            }
    }

    // ================= Layer 2: [128x128] -> 64 =================
    float acc2[2][2][4];
#pragma unroll
    for (int i = 0; i < 2; i++)
#pragma unroll
        for (int j = 0; j < 2; j++)
#pragma unroll
            for (int q = 0; q < 4; q++) acc2[i][j][q] = 0.f;

    for (int ks = 0; ks < 8; ks++) {
        cp_wait<0>();
        __syncthreads();
        uint32_t stg = sb + WSTG + (uint32_t)(ks & 1) * WSSZ;
        uint32_t aH[2][4], aL[2][4];
#pragma unroll
        for (int i = 0; i < 2; i++) {
            uint32_t rb = sb + C2_HI + (wm + 16 * i + lrow) * 272 + ks * 32 + lhalf;
            ldsm4(aH[i], rb);
            ldsm4(aL[i], rb + (C2_LO - C2_HI));
        }
        if (ks + 1 < 8) copy2(ks + 1, (ks + 1) & 1);
        {
            uint32_t rh[4], rl[4];
            uint32_t rb = stg + (wn * 16 + lrow) * 48 + lhalf;
            ldsm4(rh, rb);
            ldsm4(rl, rb + 3072);
            uint32_t bH0[2] = {rh[0], rh[2]}, bH1[2] = {rh[1], rh[3]};
            uint32_t bL0[2] = {rl[0], rl[2]}, bL1[2] = {rl[1], rl[3]};
#pragma unroll
            for (int i = 0; i < 2; i++) {
                mma_bf16(acc2[i][0], aH[i], bH0);
                mma_bf16(acc2[i][0], aH[i], bL0);
                mma_bf16(acc2[i][0], aL[i], bH0);
                mma_bf16(acc2[i][1], aH[i], bH1);
                mma_bf16(acc2[i][1], aH[i], bL1);
                mma_bf16(acc2[i][1], aL[i], bH1);
            }
        }
    }

    // epilogue 2 -> C3 (f32, above C2 region)
    {
#pragma unroll
        for (int i = 0; i < 2; i++)
#pragma unroll
            for (int j = 0; j < 2; j++) {
                int col = wn * 16 + j * 8 + (lane & 3) * 2;
                int row = wm + 16 * i + (lane >> 2);
                float b0v = g_bf2[col], b1v = g_bf2[col + 1];
                float2 v01 = make_float2(fmaxf(acc2[i][j][0] + b0v, 0.f),
                                         fmaxf(acc2[i][j][1] + b1v, 0.f));
                float2 v23 = make_float2(fmaxf(acc2[i][j][2] + b0v, 0.f),
                                         fmaxf(acc2[i][j][3] + b1v, 0.f));
                *(float2*)(smc + C3F + row * 272 + col * 4) = v01;
                *(float2*)(smc + C3F + (row + 8) * 272 + col * 4) = v23;
            }
    }
    __syncthreads();

    // ================= Output: dot Wo + fm + sigmoid =================
    if (t < MTILE) {
        const float* c3 = (const float*)(smc + C3F) + t * 68;
        float s = *(const float*)(smc + FMS + t * 4) + fmb[0] + bo[0];
#pragma unroll
        for (int k = 0; k < N2; k++)
            s = fmaf(c3[k], __ldg(&Wo[k]), s);
        out[m0g + t] = 1.f / (1.f + expf(-s));
    }
}

// ================= Launch =================
extern "C" void kernel_launch(void* const* d_in, const int* in_sizes, int n_in,
                              void* d_out, int out_size)
{
    const int*   sp    = (const int*)  d_in[0];
    const float* dense = (const float*)d_in[1];
    const float* emb   = (const float*)d_in[2];
    const float* bias  = (const float*)d_in[3];
    const float* fmb   = (const float*)d_in[4];
    const float* Wo    = (const float*)d_in[5];
    const float* bo    = (const float*)d_in[6];
    const float* W0    = (const float*)d_in[7];
    const float* b0    = (const float*)d_in[8];
    const float* g0    = (const float*)d_in[9];
    const float* be0   = (const float*)d_in[10];
    const float* W1    = (const float*)d_in[11];
    const float* b1    = (const float*)d_in[12];
    const float* g1    = (const float*)d_in[13];
    const float* be1   = (const float*)d_in[14];
    const float* W2    = (const float*)d_in[15];
    const float* b2    = (const float*)d_in[16];
    const float* g2    = (const float*)d_in[17];
    const float* be2   = (const float*)d_in[18];
    float* out = (float*)d_out;

    prep_all<<<(PREP_TOT + 255) / 256, 256>>>(W0, b0, g0, be0, W1, b1, g1, be1, W2, b2, g2, be2);

    cudaFuncSetAttribute(mlp_kernel, cudaFuncAttributeMaxDynamicSharedMemorySize, SMEM_DYN);
    mlp_kernel<<<NCTA, NTHR, SMEM_DYN>>>(sp, dense, emb, bias, fmb, Wo, bo, out);
}

// round 7
// speedup vs baseline: 3.0524x; 1.0305x over previous
#include <cuda_runtime.h>
#include <cuda_bf16.h>
#include <math.h>
#include <stdint.h>

// ================= Problem constants =================
#define BATCH   16384
#define NFIELD  10
#define EMB     32
#define DENSE   16
#define K0      336         // 21 * 16
#define N0      256
#define N1      128
#define N2      64
#define MTILE   128
#define NCTA    (BATCH / MTILE)   // 128
#define NTHR    512

__constant__ int c_offsets[NFIELD] = {
    0, 1000000, 1100000, 1101008, 1102012,
    1102114, 1103114, 1103614, 1103664, 1103776
};

// ================= Device scratch (weights only) =================
__device__ __align__(16) __nv_bfloat16 g_W0hi[N0 * K0];
__device__ __align__(16) __nv_bfloat16 g_W0lo[N0 * K0];
__device__ __align__(16) __nv_bfloat16 g_W1hi[N1 * N0];
__device__ __align__(16) __nv_bfloat16 g_W1lo[N1 * N0];
__device__ __align__(16) __nv_bfloat16 g_W2hi[N2 * N1];
__device__ __align__(16) __nv_bfloat16 g_W2lo[N2 * N1];
__device__ float g_bf0[N0], g_bf1[N1], g_bf2[N2];

// ================= PTX helpers =================
__device__ __forceinline__ uint32_t smem_u32(const void* p) {
    uint32_t a;
    asm("{ .reg .u64 t; cvta.to.shared.u64 t, %1; cvt.u32.u64 %0, t; }" : "=r"(a) : "l"(p));
    return a;
}
__device__ __forceinline__ void cpa16(uint32_t dst, const void* src) {
    asm volatile("cp.async.cg.shared.global [%0], [%1], 16;" :: "r"(dst), "l"(src) : "memory");
}
__device__ __forceinline__ void cp_commit() {
    asm volatile("cp.async.commit_group;" ::: "memory");
}
template<int N> __device__ __forceinline__ void cp_wait() {
    asm volatile("cp.async.wait_group %0;" :: "n"(N) : "memory");
}
__device__ __forceinline__ void ldsm4(uint32_t* r, uint32_t a) {
    asm volatile("ldmatrix.sync.aligned.m8n8.x4.shared.b16 {%0,%1,%2,%3}, [%4];"
        : "=r"(r[0]), "=r"(r[1]), "=r"(r[2]), "=r"(r[3]) : "r"(a));
}
__device__ __forceinline__ void mma_bf16(float* c, const uint32_t* a, const uint32_t* b) {
    asm volatile("mma.sync.aligned.m16n8k16.row.col.f32.bf16.bf16.f32 "
        "{%0,%1,%2,%3}, {%4,%5,%6,%7}, {%8,%9}, {%0,%1,%2,%3};"
        : "+f"(c[0]), "+f"(c[1]), "+f"(c[2]), "+f"(c[3])
        : "r"(a[0]), "r"(a[1]), "r"(a[2]), "r"(a[3]), "r"(b[0]), "r"(b[1]));
}
__device__ __forceinline__ uint32_t pack_bf(float lo, float hi) {
    __nv_bfloat162 t = __floats2bfloat162_rn(lo, hi);
    return *(uint32_t*)&t;
}

// ================= Kernel 1: all weight prep in one launch =================
#define S0SZ (N0 * K0)
#define S1SZ (N1 * N0)
#define S2SZ (N2 * N1)
#define PREP_TOT (S0SZ + S1SZ + S2SZ)

__global__ void prep_all(const float* __restrict__ W0, const float* __restrict__ b0,
                         const float* __restrict__ g0, const float* __restrict__ be0,
                         const float* __restrict__ W1, const float* __restrict__ b1,
                         const float* __restrict__ g1, const float* __restrict__ be1,
                         const float* __restrict__ W2, const float* __restrict__ b2,
                         const float* __restrict__ g2, const float* __restrict__ be2)
{
    const float inv = 0.9999950000374997f;   // 1/sqrt(1+1e-5)
    int i = blockIdx.x * blockDim.x + threadIdx.x;
    const float* W; const float* g; __nv_bfloat16 *hi, *lo; int IN, li;
    if (i < S0SZ) {
        W = W0; g = g0; hi = g_W0hi; lo = g_W0lo; IN = K0; li = i;
        if (i < N0) g_bf0[i] = b0[i] * (g0[i] * inv) + be0[i];
    } else if (i < S0SZ + S1SZ) {
        W = W1; g = g1; hi = g_W1hi; lo = g_W1lo; IN = N0; li = i - S0SZ;
        if (li < N1) g_bf1[li] = b1[li] * (g1[li] * inv) + be1[li];
    } else if (i < PREP_TOT) {
        W = W2; g = g2; hi = g_W2hi; lo = g_W2lo; IN = N1; li = i - S0SZ - S1SZ;
        if (li < N2) g_bf2[li] = b2[li] * (g2[li] * inv) + be2[li];
    } else return;
    int n = li / IN;
    float w = W[li] * (g[n] * inv);
    __nv_bfloat16 h = __float2bfloat16(w);
    hi[li] = h;
    lo[li] = __float2bfloat16(w - __bfloat162float(h));
}

// ================= Kernel 2: fused embed + FM + HMMA MLP =================
#define X_HI   0
#define X_LO   88064
#define XSTR   688
#define WSTG   176128
#define WSSZ   24576
#define C1_HI  0
#define C1_LO  67584
#define C2_HI  0
#define C2_LO  34816
#define C3F    69632
#define FMS    225280
#define SMEM_DYN (225280 + 512)

__global__ __launch_bounds__(NTHR, 1)
void mlp_kernel(const int* __restrict__ sp, const float* __restrict__ dense,
                const float* __restrict__ emb, const float* __restrict__ bias,
                const float* __restrict__ fmb,
                const float* __restrict__ Wo, const float* __restrict__ bo,
                float* __restrict__ out)
{
    extern __shared__ char smc[];
    const uint32_t sb = smem_u32(smc);
    const int t = threadIdx.x, w = t >> 5, lane = t & 31;
    const int m0g = blockIdx.x * MTILE;
    const int wm = (w >> 2) * 32;
    const int wn = (w & 3);
    const uint32_t lrow = (uint32_t)(lane & 15);
    const uint32_t lhalf = (uint32_t)(lane >> 4) * 16u;

    // ---------------- copy helpers ----------------
    auto copy0 = [&](int ks, int s) {
        uint32_t stg = sb + WSTG + (uint32_t)s * WSSZ;
#pragma unroll
        for (int r = 0; r < 2; r++) {
            int c = t + r * NTHR;
            int n = c >> 2, half = (c >> 1) & 1, p = c & 1;
            uint32_t dst = stg + p * 12288 + n * 48 + half * 16;
            const __nv_bfloat16* src = (p ? g_W0lo : g_W0hi) + (size_t)n * K0 + ks * 16 + half * 8;
            cpa16(dst, src);
        }
        cp_commit();
    };
    auto copy1 = [&](int ks, int s) {
        uint32_t stg = sb + WSTG + (uint32_t)s * WSSZ;
        {
            int c = t;
            int n = c >> 2, half = (c >> 1) & 1, p = c & 1;
            uint32_t dst = stg + p * 6144 + n * 48 + half * 16;
            const __nv_bfloat16* src = (p ? g_W1lo : g_W1hi) + (size_t)n * N0 + ks * 16 + half * 8;
            cpa16(dst, src);
        }
        cp_commit();
    };
    auto copy2 = [&](int ks, int s) {
        uint32_t stg = sb + WSTG + (uint32_t)s * WSSZ;
        if (t < 256) {
            int c = t;
            int n = c >> 2, half = (c >> 1) & 1, p = c & 1;
            uint32_t dst = stg + p * 3072 + n * 48 + half * 16;
            const __nv_bfloat16* src = (p ? g_W2lo : g_W2hi) + (size_t)n * N1 + ks * 16 + half * 8;
            cpa16(dst, src);
        }
        cp_commit();
    };

    // ---------------- Prologue: kick weight stage 0, gather X, FM ----------------
    copy0(0, 0);
#pragma unroll 1
    for (int i = 0; i < 8; i++) {
        int m = w * 8 + i;
        int b = m0g + m;
        float s = 0.f, sq = 0.f;
#pragma unroll
        for (int f = 0; f < NFIELD; f++) {
            int row = sp[b * NFIELD + f] + c_offsets[f];
            float e = __ldg(&emb[(size_t)row * EMB + lane]);
            s += e; sq += e * e;
            __nv_bfloat16 h = __float2bfloat16(e);
            *(__nv_bfloat16*)(smc + X_HI + m * XSTR + (f * EMB + lane) * 2) = h;
            *(__nv_bfloat16*)(smc + X_LO + m * XSTR + (f * EMB + lane) * 2) =
                __float2bfloat16(e - __bfloat162float(h));
        }
        if (lane < DENSE) {
            float dv = dense[b * DENSE + lane];
            __nv_bfloat16 h = __float2bfloat16(dv);
            *(__nv_bfloat16*)(smc + X_HI + m * XSTR + (320 + lane) * 2) = h;
            *(__nv_bfloat16*)(smc + X_LO + m * XSTR + (320 + lane) * 2) =
                __float2bfloat16(dv - __bfloat162float(h));
        }
        float part = 0.5f * (s * s - sq);
        if (lane < NFIELD)
            part += __ldg(&bias[sp[b * NFIELD + lane] + c_offsets[lane]]);
#pragma unroll
        for (int d = 16; d > 0; d >>= 1)
            part += __shfl_down_sync(0xFFFFFFFFu, part, d);
        if (lane == 0) *(float*)(smc + FMS + m * 4) = part;
    }

    // ================= Layer 0: [128x336] -> 256 =================
    float acc0[2][8][4];
#pragma unroll
    for (int i = 0; i < 2; i++)
#pragma unroll
        for (int j = 0; j < 8; j++)
#pragma unroll
            for (int q = 0; q < 4; q++) acc0[i][j][q] = 0.f;

    for (int ks = 0; ks < 21; ks++) {
        cp_wait<0>();
        __syncthreads();
        uint32_t stg = sb + WSTG + (uint32_t)(ks & 1) * WSSZ;
        uint32_t aH[2][4], aL[2][4];
#pragma unroll
        for (int i = 0; i < 2; i++) {
            uint32_t rb = sb + X_HI + (wm + 16 * i + lrow) * XSTR + ks * 32 + lhalf;
            ldsm4(aH[i], rb);
            ldsm4(aL[i], rb + (X_LO - X_HI));
        }
        if (ks + 1 < 21) copy0(ks + 1, (ks + 1) & 1);
#pragma unroll
        for (int nb = 0; nb < 4; nb++) {
            uint32_t rh[4], rl[4];
            uint32_t rb = stg + (wn * 64 + 16 * nb + lrow) * 48 + lhalf;
            ldsm4(rh, rb);
            ldsm4(rl, rb + 12288);
            uint32_t bH0[2] = {rh[0], rh[2]}, bH1[2] = {rh[1], rh[3]};
            uint32_t bL0[2] = {rl[0], rl[2]}, bL1[2] = {rl[1], rl[3]};
            // term-major: acc reuse distance = 4 MMAs (was 1)
            mma_bf16(acc0[0][2 * nb],     aH[0], bH0);
            mma_bf16(acc0[0][2 * nb + 1], aH[0], bH1);
            mma_bf16(acc0[1][2 * nb],     aH[1], bH0);
            mma_bf16(acc0[1][2 * nb + 1], aH[1], bH1);
            mma_bf16(acc0[0][2 * nb],     aH[0], bL0);
            mma_bf16(acc0[0][2 * nb + 1], aH[0], bL1);
            mma_bf16(acc0[1][2 * nb],     aH[1], bL0);
            mma_bf16(acc0[1][2 * nb + 1], aH[1], bL1);
            mma_bf16(acc0[0][2 * nb],     aL[0], bH0);
            mma_bf16(acc0[0][2 * nb + 1], aL[0], bH1);
            mma_bf16(acc0[1][2 * nb],     aL[1], bH0);
            mma_bf16(acc0[1][2 * nb + 1], aL[1], bH1);
        }
    }
    __syncthreads();
    copy1(0, 0);

    // epilogue 0 -> C1 hi/lo (aliases X)
    {
#pragma unroll
        for (int i = 0; i < 2; i++)
#pragma unroll
            for (int j = 0; j < 8; j++) {
                int col = wn * 64 + j * 8 + (lane & 3) * 2;
                int row = wm + 16 * i + (lane >> 2);
                float b0v = g_bf0[col], b1v = g_bf0[col + 1];
                float v0 = fmaxf(acc0[i][j][0] + b0v, 0.f);
                float v1 = fmaxf(acc0[i][j][1] + b1v, 0.f);
                float v2 = fmaxf(acc0[i][j][2] + b0v, 0.f);
                float v3 = fmaxf(acc0[i][j][3] + b1v, 0.f);
                __nv_bfloat16 h0 = __float2bfloat16(v0), h1 = __float2bfloat16(v1);
                __nv_bfloat16 h2 = __float2bfloat16(v2), h3 = __float2bfloat16(v3);
                *(uint32_t*)(smc + C1_HI + row * 528 + col * 2) =
                    pack_bf(__bfloat162float(h0), __bfloat162float(h1));
                *(uint32_t*)(smc + C1_LO + row * 528 + col * 2) =
                    pack_bf(v0 - __bfloat162float(h0), v1 - __bfloat162float(h1));
                *(uint32_t*)(smc + C1_HI + (row + 8) * 528 + col * 2) =
                    pack_bf(__bfloat162float(h2), __bfloat162float(h3));
                *(uint32_t*)(smc + C1_LO + (row + 8) * 528 + col * 2) =
                    pack_bf(v2 - __bfloat162float(h2), v3 - __bfloat162float(h3));
            }
    }

    // ================= Layer 1: [128x256] -> 128 =================
    float acc1[2][4][4];
#pragma unroll
    for (int i = 0; i < 2; i++)
#pragma unroll
        for (int j = 0; j < 4; j++)
#pragma unroll
            for (int q = 0; q < 4; q++) acc1[i][j][q] = 0.f;

    for (int ks = 0; ks < 16; ks++) {
        cp_wait<0>();
        __syncthreads();
        uint32_t stg = sb + WSTG + (uint32_t)(ks & 1) * WSSZ;
        uint32_t aH[2][4], aL[2][4];
#pragma unroll
        for (int i = 0; i < 2; i++) {
            uint32_t rb = sb + C1_HI + (wm + 16 * i + lrow) * 528 + ks * 32 + lhalf;
            ldsm4(aH[i], rb);
            ldsm4(aL[i], rb + (C1_LO - C1_HI));
        }
        if (ks + 1 < 16) copy1(ks + 1, (ks + 1) & 1);
#pragma unroll
        for (int nb = 0; nb < 2; nb++) {
            uint32_t rh[4], rl[4];
            uint32_t rb = stg + (wn * 32 + 16 * nb + lrow) * 48 + lhalf;
            ldsm4(rh, rb);
            ldsm4(rl, rb + 6144);
            uint32_t bH0[2] = {rh[0], rh[2]}, bH1[2] = {rh[1], rh[3]};
            uint32_t bL0[2] = {rl[0], rl[2]}, bL1[2] = {rl[1], rl[3]};
            mma_bf16(acc1[0][2 * nb],     aH[0], bH0);
            mma_bf16(acc1[0][2 * nb + 1], aH[0], bH1);
            mma_bf16(acc1[1][2 * nb],     aH[1], bH0);
            mma_bf16(acc1[1][2 * nb + 1], aH[1], bH1);
            mma_bf16(acc1[0][2 * nb],     aH[0], bL0);
            mma_bf16(acc1[0][2 * nb + 1], aH[0], bL1);
            mma_bf16(acc1[1][2 * nb],     aH[1], bL0);
            mma_bf16(acc1[1][2 * nb + 1], aH[1], bL1);
            mma_bf16(acc1[0][2 * nb],     aL[0], bH0);
            mma_bf16(acc1[0][2 * nb + 1], aL[0], bH1);
            mma_bf16(acc1[1][2 * nb],     aL[1], bH0);
            mma_bf16(acc1[1][2 * nb + 1], aL[1], bH1);
        }
    }
    __syncthreads();
    copy2(0, 0);

    // epilogue 1 -> C2 hi/lo (aliases C1)
    {
#pragma unroll
        for (int i = 0; i < 2; i++)
#pragma unroll
            for (int j = 0; j < 4; j++) {
                int col = wn * 32 + j * 8 + (lane & 3) * 2;
                int row = wm + 16 * i + (lane >> 2);
                float b0v = g_bf1[col], b1v = g_bf1[col + 1];
                float v0 = fmaxf(acc1[i][j][0] + b0v, 0.f);
                float v1 = fmaxf(acc1[i][j][1] + b1v, 0.f);
                float v2 = fmaxf(acc1[i][j][2] + b0v, 0.f);
                float v3 = fmaxf(acc1[i][j][3] + b1v, 0.f);
                __nv_bfloat16 h0 = __float2bfloat16(v0), h1 = __float2bfloat16(v1);
                __nv_bfloat16 h2 = __float2bfloat16(v2), h3 = __float2bfloat16(v3);
                *(uint32_t*)(smc + C2_HI + row * 272 + col * 2) =
                    pack_bf(__bfloat162float(h0), __bfloat162float(h1));
                *(uint32_t*)(smc + C2_LO + row * 272 + col * 2) =
                    pack_bf(v0 - __bfloat162float(h0), v1 - __bfloat162float(h1));
                *(uint32_t*)(smc + C2_HI + (row + 8) * 272 + col * 2) =
                    pack_bf(__bfloat162float(h2), __bfloat162float(h3));
                *(uint32_t*)(smc + C2_LO + (row + 8) * 272 + col * 2) =
                    pack_bf(v2 - __bfloat162float(h2), v3 - __bfloat162float(h3));
            }
    }

    // ================= Layer 2: [128x128] -> 64 =================
    float acc2[2][2][4];
#pragma unroll
    for (int i = 0; i < 2; i++)
#pragma unroll
        for (int j = 0; j < 2; j++)
#pragma unroll
            for (int q = 0; q < 4; q++) acc2[i][j][q] = 0.f;

    for (int ks = 0; ks < 8; ks++) {
        cp_wait<0>();
        __syncthreads();
        uint32_t stg = sb + WSTG + (uint32_t)(ks & 1) * WSSZ;
        uint32_t aH[2][4], aL[2][4];
#pragma unroll
        for (int i = 0; i < 2; i++) {
            uint32_t rb = sb + C2_HI + (wm + 16 * i + lrow) * 272 + ks * 32 + lhalf;
            ldsm4(aH[i], rb);
            ldsm4(aL[i], rb + (C2_LO - C2_HI));
        }
        if (ks + 1 < 8) copy2(ks + 1, (ks + 1) & 1);
        {
            uint32_t rh[4], rl[4];
            uint32_t rb = stg + (wn * 16 + lrow) * 48 + lhalf;
            ldsm4(rh, rb);
            ldsm4(rl, rb + 3072);
            uint32_t bH0[2] = {rh[0], rh[2]}, bH1[2] = {rh[1], rh[3]};
            uint32_t bL0[2] = {rl[0], rl[2]}, bL1[2] = {rl[1], rl[3]};
            mma_bf16(acc2[0][0], aH[0], bH0);
            mma_bf16(acc2[0][1], aH[0], bH1);
            mma_bf16(acc2[1][0], aH[1], bH0);
            mma_bf16(acc2[1][1], aH[1], bH1);
            mma_bf16(acc2[0][0], aH[0], bL0);
            mma_bf16(acc2[0][1], aH[0], bL1);
            mma_bf16(acc2[1][0], aH[1], bL0);
            mma_bf16(acc2[1][1], aH[1], bL1);
            mma_bf16(acc2[0][0], aL[0], bH0);
            mma_bf16(acc2[0][1], aL[0], bH1);
            mma_bf16(acc2[1][0], aL[1], bH0);
            mma_bf16(acc2[1][1], aL[1], bH1);
        }
    }

    // epilogue 2 -> C3 (f32)
    {
#pragma unroll
        for (int i = 0; i < 2; i++)
#pragma unroll
            for (int j = 0; j < 2; j++) {
                int col = wn * 16 + j * 8 + (lane & 3) * 2;
                int row = wm + 16 * i + (lane >> 2);
                float b0v = g_bf2[col], b1v = g_bf2[col + 1];
                float2 v01 = make_float2(fmaxf(acc2[i][j][0] + b0v, 0.f),
                                         fmaxf(acc2[i][j][1] + b1v, 0.f));
                float2 v23 = make_float2(fmaxf(acc2[i][j][2] + b0v, 0.f),
                                         fmaxf(acc2[i][j][3] + b1v, 0.f));
                *(float2*)(smc + C3F + row * 272 + col * 4) = v01;
                *(float2*)(smc + C3F + (row + 8) * 272 + col * 4) = v23;
            }
    }
    __syncthreads();

    // ================= Output: dot Wo + fm + sigmoid =================
    if (t < MTILE) {
        const float* c3 = (const float*)(smc + C3F) + t * 68;
        float s = *(const float*)(smc + FMS + t * 4) + fmb[0] + bo[0];
#pragma unroll
        for (int k = 0; k < N2; k++)
            s = fmaf(c3[k], __ldg(&Wo[k]), s);
        out[m0g + t] = 1.f / (1.f + expf(-s));
    }
}

// ================= Launch =================
extern "C" void kernel_launch(void* const* d_in, const int* in_sizes, int n_in,
                              void* d_out, int out_size)
{
    const int*   sp    = (const int*)  d_in[0];
    const float* dense = (const float*)d_in[1];
    const float* emb   = (const float*)d_in[2];
    const float* bias  = (const float*)d_in[3];
    const float* fmb   = (const float*)d_in[4];
    const float* Wo    = (const float*)d_in[5];
    const float* bo    = (const float*)d_in[6];
    const float* W0    = (const float*)d_in[7];
    const float* b0    = (const float*)d_in[8];
    const float* g0    = (const float*)d_in[9];
    const float* be0   = (const float*)d_in[10];
    const float* W1    = (const float*)d_in[11];
    const float* b1    = (const float*)d_in[12];
    const float* g1    = (const float*)d_in[13];
    const float* be1   = (const float*)d_in[14];
    const float* W2    = (const float*)d_in[15];
    const float* b2    = (const float*)d_in[16];
    const float* g2    = (const float*)d_in[17];
    const float* be2   = (const float*)d_in[18];
    float* out = (float*)d_out;

    prep_all<<<(PREP_TOT + 255) / 256, 256>>>(W0, b0, g0, be0, W1, b1, g1, be1, W2, b2, g2, be2);

    cudaFuncSetAttribute(mlp_kernel, cudaFuncAttributeMaxDynamicSharedMemorySize, SMEM_DYN);
    mlp_kernel<<<NCTA, NTHR, SMEM_DYN>>>(sp, dense, emb, bias, fmb, Wo, bo, out);
}

// round 8
// speedup vs baseline: 3.2747x; 1.0728x over previous
#include <cuda_runtime.h>
#include <cuda_bf16.h>
#include <math.h>
#include <stdint.h>

// ================= Problem constants =================
#define BATCH   16384
#define NFIELD  10
#define EMB     32
#define DENSE   16
#define K0      336         // 21 * 16
#define N0      256
#define N1      128
#define N2      64
#define MTILE   128
#define NCTA    (BATCH / MTILE)   // 128
#define NTHR    512
#define GK_L1   21
#define GK_L2   37
#define GK_END  45

__constant__ int c_offsets[NFIELD] = {
    0, 1000000, 1100000, 1101008, 1102012,
    1102114, 1103114, 1103614, 1103664, 1103776
};

// ================= Device scratch (weights only) =================
__device__ __align__(16) __nv_bfloat16 g_W0hi[N0 * K0];
__device__ __align__(16) __nv_bfloat16 g_W0lo[N0 * K0];
__device__ __align__(16) __nv_bfloat16 g_W1hi[N1 * N0];
__device__ __align__(16) __nv_bfloat16 g_W1lo[N1 * N0];
__device__ __align__(16) __nv_bfloat16 g_W2hi[N2 * N1];
__device__ __align__(16) __nv_bfloat16 g_W2lo[N2 * N1];
__device__ float g_bf0[N0], g_bf1[N1], g_bf2[N2];

// ================= PTX helpers =================
__device__ __forceinline__ uint32_t smem_u32(const void* p) {
    uint32_t a;
    asm("{ .reg .u64 t; cvta.to.shared.u64 t, %1; cvt.u32.u64 %0, t; }" : "=r"(a) : "l"(p));
    return a;
}
__device__ __forceinline__ void cpa16(uint32_t dst, const void* src) {
    asm volatile("cp.async.cg.shared.global [%0], [%1], 16;" :: "r"(dst), "l"(src) : "memory");
}
__device__ __forceinline__ void ldsm4(uint32_t* r, uint32_t a) {
    asm volatile("ldmatrix.sync.aligned.m8n8.x4.shared.b16 {%0,%1,%2,%3}, [%4];"
        : "=r"(r[0]), "=r"(r[1]), "=r"(r[2]), "=r"(r[3]) : "r"(a));
}
__device__ __forceinline__ void mma_bf16(float* c, const uint32_t* a, const uint32_t* b) {
    asm volatile("mma.sync.aligned.m16n8k16.row.col.f32.bf16.bf16.f32 "
        "{%0,%1,%2,%3}, {%4,%5,%6,%7}, {%8,%9}, {%0,%1,%2,%3};"
        : "+f"(c[0]), "+f"(c[1]), "+f"(c[2]), "+f"(c[3])
        : "r"(a[0]), "r"(a[1]), "r"(a[2]), "r"(a[3]), "r"(b[0]), "r"(b[1]));
}
__device__ __forceinline__ uint32_t pack_bf(float lo, float hi) {
    __nv_bfloat162 t = __floats2bfloat162_rn(lo, hi);
    return *(uint32_t*)&t;
}

#define MBAR_INIT(a, c) \
    asm volatile("mbarrier.init.shared.b64 [%0], %1;" :: "r"(a), "r"((uint32_t)(c)) : "memory")
__device__ __forceinline__ void mbar_arrive(uint32_t a) {
    asm volatile("{ .reg .b64 _t; mbarrier.arrive.shared.b64 _t, [%0]; }" :: "r"(a) : "memory");
}
__device__ __forceinline__ void cpa_mbar_arrive(uint32_t a) {
    asm volatile("cp.async.mbarrier.arrive.noinc.shared.b64 [%0];" :: "r"(a) : "memory");
}
#define MBAR_WAIT(mbar, par) do { \
    uint32_t _m = (uint32_t)(mbar); uint32_t _p = (uint32_t)(par); uint32_t _d; \
    asm volatile("{\n\t.reg .pred p;\n\t" \
        "mbarrier.try_wait.parity.acquire.cta.shared::cta.b64 p, [%1], %2;\n\t" \
        "selp.b32 %0, 1, 0, p;\n\t}" : "=r"(_d) : "r"(_m), "r"(_p) : "memory"); \
    if (!_d) { \
        asm volatile("{\n\t.reg .pred P1;\n\t" \
            "WL_%=:\n\t" \
            "mbarrier.try_wait.parity.acquire.cta.shared::cta.b64 P1, [%0], %1, 0x989680;\n\t" \
            "@P1 bra.uni WD_%=;\n\t" \
            "bra.uni WL_%=;\n\t" \
            "WD_%=:\n\t}" :: "r"(_m), "r"(_p) : "memory"); \
    } \
} while (0)

// ================= Kernel 1: all weight prep in one launch =================
#define S0SZ (N0 * K0)
#define S1SZ (N1 * N0)
#define S2SZ (N2 * N1)
#define PREP_TOT (S0SZ + S1SZ + S2SZ)

__global__ void prep_all(const float* __restrict__ W0, const float* __restrict__ b0,
                         const float* __restrict__ g0, const float* __restrict__ be0,
                         const float* __restrict__ W1, const float* __restrict__ b1,
                         const float* __restrict__ g1, const float* __restrict__ be1,
                         const float* __restrict__ W2, const float* __restrict__ b2,
                         const float* __restrict__ g2, const float* __restrict__ be2)
{
    const float inv = 0.9999950000374997f;   // 1/sqrt(1+1e-5)
    int i = blockIdx.x * blockDim.x + threadIdx.x;
    const float* W; const float* g; __nv_bfloat16 *hi, *lo; int IN, li;
    if (i < S0SZ) {
        W = W0; g = g0; hi = g_W0hi; lo = g_W0lo; IN = K0; li = i;
        if (i < N0) g_bf0[i] = b0[i] * (g0[i] * inv) + be0[i];
    } else if (i < S0SZ + S1SZ) {
        W = W1; g = g1; hi = g_W1hi; lo = g_W1lo; IN = N0; li = i - S0SZ;
        if (li < N1) g_bf1[li] = b1[li] * (g1[li] * inv) + be1[li];
    } else if (i < PREP_TOT) {
        W = W2; g = g2; hi = g_W2hi; lo = g_W2lo; IN = N1; li = i - S0SZ - S1SZ;
        if (li < N2) g_bf2[li] = b2[li] * (g2[li] * inv) + be2[li];
    } else return;
    int n = li / IN;
    float w = W[li] * (g[n] * inv);
    __nv_bfloat16 h = __float2bfloat16(w);
    hi[li] = h;
    lo[li] = __float2bfloat16(w - __bfloat162float(h));
}

// ================= Kernel 2: fused embed + FM + HMMA MLP =================
#define X_HI   0
#define X_LO   88064
#define XSTR   688
#define WSTG   176128
#define WSSZ   24576
#define C1_HI  0
#define C1_LO  67584
#define C2_HI  0
#define C2_LO  34816
#define C3F    69632
#define FMS    225280
#define BARS   (FMS + 256)        // full0,full1,empty0,empty1 (8B each)
#define SMEM_DYN (225280 + 512)

__global__ __launch_bounds__(NTHR, 1)
void mlp_kernel(const int* __restrict__ sp, const float* __restrict__ dense,
                const float* __restrict__ emb, const float* __restrict__ bias,
                const float* __restrict__ fmb,
                const float* __restrict__ Wo, const float* __restrict__ bo,
                float* __restrict__ out)
{
    extern __shared__ char smc[];
    const uint32_t sb = smem_u32(smc);
    const int t = threadIdx.x, w = t >> 5, lane = t & 31;
    const int m0g = blockIdx.x * MTILE;
    const int wm = (w >> 2) * 32;
    const int wn = (w & 3);
    const uint32_t lrow = (uint32_t)(lane & 15);
    const uint32_t lhalf = (uint32_t)(lane >> 4) * 16u;
    const uint32_t fullb = sb + BARS;
    const uint32_t emptyb = sb + BARS + 16;

    // produce stage gkp into ring (all threads participate)
    auto produce = [&](int gkp) {
        int slot = gkp & 1;
        uint32_t stg = sb + WSTG + (uint32_t)slot * WSSZ;
        if (gkp >= 2) MBAR_WAIT(emptyb + slot * 8, ((gkp - 2) >> 1) & 1);
        if (gkp < GK_L1) {
            int ks = gkp;
#pragma unroll
            for (int r = 0; r < 2; r++) {
                int c = t + r * NTHR;
                int n = c >> 2, half = (c >> 1) & 1, p = c & 1;
                cpa16(stg + p * 12288 + n * 48 + half * 16,
                      (p ? g_W0lo : g_W0hi) + (size_t)n * K0 + ks * 16 + half * 8);
            }
        } else if (gkp < GK_L2) {
            int ks = gkp - GK_L1;
            int n = t >> 2, half = (t >> 1) & 1, p = t & 1;
            cpa16(stg + p * 6144 + n * 48 + half * 16,
                  (p ? g_W1lo : g_W1hi) + (size_t)n * N0 + ks * 16 + half * 8);
        } else {
            int ks = gkp - GK_L2;
            if (t < 256) {
                int n = t >> 2, half = (t >> 1) & 1, p = t & 1;
                cpa16(stg + p * 3072 + n * 48 + half * 16,
                      (p ? g_W2lo : g_W2hi) + (size_t)n * N1 + ks * 16 + half * 8);
            }
        }
        cpa_mbar_arrive(fullb + slot * 8);
    };

    // ---------------- Init barriers, kick stages 0/1, gather X, FM ----------------
    if (t == 0) {
        MBAR_INIT(fullb, NTHR); MBAR_INIT(fullb + 8, NTHR);
        MBAR_INIT(emptyb, 16);  MBAR_INIT(emptyb + 8, 16);
    }
    __syncthreads();
    produce(0);
    produce(1);

#pragma unroll 1
    for (int i = 0; i < 8; i++) {
        int m = w * 8 + i;
        int b = m0g + m;
        float s = 0.f, sq = 0.f;
#pragma unroll
        for (int f = 0; f < NFIELD; f++) {
            int row = sp[b * NFIELD + f] + c_offsets[f];
            float e = __ldg(&emb[(size_t)row * EMB + lane]);
            s += e; sq += e * e;
            __nv_bfloat16 h = __float2bfloat16(e);
            *(__nv_bfloat16*)(smc + X_HI + m * XSTR + (f * EMB + lane) * 2) = h;
            *(__nv_bfloat16*)(smc + X_LO + m * XSTR + (f * EMB + lane) * 2) =
                __float2bfloat16(e - __bfloat162float(h));
        }
        if (lane < DENSE) {
            float dv = dense[b * DENSE + lane];
            __nv_bfloat16 h = __float2bfloat16(dv);
            *(__nv_bfloat16*)(smc + X_HI + m * XSTR + (320 + lane) * 2) = h;
            *(__nv_bfloat16*)(smc + X_LO + m * XSTR + (320 + lane) * 2) =
                __float2bfloat16(dv - __bfloat162float(h));
        }
        float part = 0.5f * (s * s - sq);
        if (lane < NFIELD)
            part += __ldg(&bias[sp[b * NFIELD + lane] + c_offsets[lane]]);
#pragma unroll
        for (int d = 16; d > 0; d >>= 1)
            part += __shfl_down_sync(0xFFFFFFFFu, part, d);
        if (lane == 0) *(float*)(smc + FMS + m * 4) = part;
    }
    __syncthreads();   // X visible to all consumer warps

    // ================= Layer 0: [128x336] -> 256 =================
    float acc0[2][8][4];
#pragma unroll
    for (int i = 0; i < 2; i++)
#pragma unroll
        for (int j = 0; j < 8; j++)
#pragma unroll
            for (int q = 0; q < 4; q++) acc0[i][j][q] = 0.f;

    for (int ks = 0; ks < 21; ks++) {
        const int gks = ks, slot = gks & 1, par = (gks >> 1) & 1;
        uint32_t aH[2][4], aL[2][4];
#pragma unroll
        for (int i = 0; i < 2; i++) {
            uint32_t rb = sb + X_HI + (wm + 16 * i + lrow) * XSTR + ks * 32 + lhalf;
            ldsm4(aH[i], rb);
            ldsm4(aL[i], rb + (X_LO - X_HI));
        }
        MBAR_WAIT(fullb + slot * 8, par);
        uint32_t stg = sb + WSTG + (uint32_t)slot * WSSZ;
#pragma unroll
        for (int nb = 0; nb < 4; nb++) {
            uint32_t rh[4], rl[4];
            uint32_t rb = stg + (wn * 64 + 16 * nb + lrow) * 48 + lhalf;
            ldsm4(rh, rb);
            ldsm4(rl, rb + 12288);
            uint32_t bH0[2] = {rh[0], rh[2]}, bH1[2] = {rh[1], rh[3]};
            uint32_t bL0[2] = {rl[0], rl[2]}, bL1[2] = {rl[1], rl[3]};
            mma_bf16(acc0[0][2 * nb],     aH[0], bH0);
            mma_bf16(acc0[0][2 * nb + 1], aH[0], bH1);
            mma_bf16(acc0[1][2 * nb],     aH[1], bH0);
            mma_bf16(acc0[1][2 * nb + 1], aH[1], bH1);
            mma_bf16(acc0[0][2 * nb],     aH[0], bL0);
            mma_bf16(acc0[0][2 * nb + 1], aH[0], bL1);
            mma_bf16(acc0[1][2 * nb],     aH[1], bL0);
            mma_bf16(acc0[1][2 * nb + 1], aH[1], bL1);
            mma_bf16(acc0[0][2 * nb],     aL[0], bH0);
            mma_bf16(acc0[0][2 * nb + 1], aL[0], bH1);
            mma_bf16(acc0[1][2 * nb],     aL[1], bH0);
            mma_bf16(acc0[1][2 * nb + 1], aL[1], bH1);
        }
        if (lane == 0) mbar_arrive(emptyb + slot * 8);
        produce(gks + 2);
    }
    __syncthreads();    // all warps done reading X; X region now dead

    // epilogue 0 -> C1 hi/lo (aliases X)
    {
#pragma unroll
        for (int i = 0; i < 2; i++)
#pragma unroll
            for (int j = 0; j < 8; j++) {
                int col = wn * 64 + j * 8 + (lane & 3) * 2;
                int row = wm + 16 * i + (lane >> 2);
                float b0v = g_bf0[col], b1v = g_bf0[col + 1];
                float v0 = fmaxf(acc0[i][j][0] + b0v, 0.f);
                float v1 = fmaxf(acc0[i][j][1] + b1v, 0.f);
                float v2 = fmaxf(acc0[i][j][2] + b0v, 0.f);
                float v3 = fmaxf(acc0[i][j][3] + b1v, 0.f);
                __nv_bfloat16 h0 = __float2bfloat16(v0), h1 = __float2bfloat16(v1);
                __nv_bfloat16 h2 = __float2bfloat16(v2), h3 = __float2bfloat16(v3);
                *(uint32_t*)(smc + C1_HI + row * 528 + col * 2) =
                    pack_bf(__bfloat162float(h0), __bfloat162float(h1));
                *(uint32_t*)(smc + C1_LO + row * 528 + col * 2) =
                    pack_bf(v0 - __bfloat162float(h0), v1 - __bfloat162float(h1));
                *(uint32_t*)(smc + C1_HI + (row + 8) * 528 + col * 2) =
                    pack_bf(__bfloat162float(h2), __bfloat162float(h3));
                *(uint32_t*)(smc + C1_LO + (row + 8) * 528 + col * 2) =
                    pack_bf(v2 - __bfloat162float(h2), v3 - __bfloat162float(h3));
            }
    }
    __syncthreads();    // C1 visible

    // ================= Layer 1: [128x256] -> 128 =================
    float acc1[2][4][4];
#pragma unroll
    for (int i = 0; i < 2; i++)
#pragma unroll
        for (int j = 0; j < 4; j++)
#pragma unroll
            for (int q = 0; q < 4; q++) acc1[i][j][q] = 0.f;

    for (int ks = 0; ks < 16; ks++) {
        const int gks = GK_L1 + ks, slot = gks & 1, par = (gks >> 1) & 1;
        uint32_t aH[2][4], aL[2][4];
#pragma unroll
        for (int i = 0; i < 2; i++) {
            uint32_t rb = sb + C1_HI + (wm + 16 * i + lrow) * 528 + ks * 32 + lhalf;
            ldsm4(aH[i], rb);
            ldsm4(aL[i], rb + (C1_LO - C1_HI));
        }
        MBAR_WAIT(fullb + slot * 8, par);
        uint32_t stg = sb + WSTG + (uint32_t)slot * WSSZ;
#pragma unroll
        for (int nb = 0; nb < 2; nb++) {
            uint32_t rh[4], rl[4];
            uint32_t rb = stg + (wn * 32 + 16 * nb + lrow) * 48 + lhalf;
            ldsm4(rh, rb);
            ldsm4(rl, rb + 6144);
            uint32_t bH0[2] = {rh[0], rh[2]}, bH1[2] = {rh[1], rh[3]};
            uint32_t bL0[2] = {rl[0], rl[2]}, bL1[2] = {rl[1], rl[3]};
            mma_bf16(acc1[0][2 * nb],     aH[0], bH0);
            mma_bf16(acc1[0][2 * nb + 1], aH[0], bH1);
            mma_bf16(acc1[1][2 * nb],     aH[1], bH0);
            mma_bf16(acc1[1][2 * nb + 1], aH[1], bH1);
            mma_bf16(acc1[0][2 * nb],     aH[0], bL0);
            mma_bf16(acc1[0][2 * nb + 1], aH[0], bL1);
            mma_bf16(acc1[1][2 * nb],     aH[1], bL0);
            mma_bf16(acc1[1][2 * nb + 1], aH[1], bL1);
            mma_bf16(acc1[0][2 * nb],     aL[0], bH0);
            mma_bf16(acc1[0][2 * nb + 1], aL[0], bH1);
            mma_bf16(acc1[1][2 * nb],     aL[1], bH0);
            mma_bf16(acc1[1][2 * nb + 1], aL[1], bH1);
        }
        if (lane == 0) mbar_arrive(emptyb + slot * 8);
        produce(gks + 2);
    }
    __syncthreads();    // all warps done reading C1; C1 region now dead

    // epilogue 1 -> C2 hi/lo (aliases C1)
    {
#pragma unroll
        for (int i = 0; i < 2; i++)
#pragma unroll
            for (int j = 0; j < 4; j++) {
                int col = wn * 32 + j * 8 + (lane & 3) * 2;
                int row = wm + 16 * i + (lane >> 2);
                float b0v = g_bf1[col], b1v = g_bf1[col + 1];
                float v0 = fmaxf(acc1[i][j][0] + b0v, 0.f);
                float v1 = fmaxf(acc1[i][j][1] + b1v, 0.f);
                float v2 = fmaxf(acc1[i][j][2] + b0v, 0.f);
                float v3 = fmaxf(acc1[i][j][3] + b1v, 0.f);
                __nv_bfloat16 h0 = __float2bfloat16(v0), h1 = __float2bfloat16(v1);
                __nv_bfloat16 h2 = __float2bfloat16(v2), h3 = __float2bfloat16(v3);
                *(uint32_t*)(smc + C2_HI + row * 272 + col * 2) =
                    pack_bf(__bfloat162float(h0), __bfloat162float(h1));
                *(uint32_t*)(smc + C2_LO + row * 272 + col * 2) =
                    pack_bf(v0 - __bfloat162float(h0), v1 - __bfloat162float(h1));
                *(uint32_t*)(smc + C2_HI + (row + 8) * 272 + col * 2) =
                    pack_bf(__bfloat162float(h2), __bfloat162float(h3));
                *(uint32_t*)(smc + C2_LO + (row + 8) * 272 + col * 2) =
                    pack_bf(v2 - __bfloat162float(h2), v3 - __bfloat162float(h3));
            }
    }
    __syncthreads();    // C2 visible

    // ================= Layer 2: [128x128] -> 64 =================
    float acc2[2][2][4];
#pragma unroll
    for (int i = 0; i < 2; i++)
#pragma unroll
        for (int j = 0; j < 2; j++)
#pragma unroll
            for (int q = 0; q < 4; q++) acc2[i][j][q] = 0.f;

    for (int ks = 0; ks < 8; ks++) {
        const int gks = GK_L2 + ks, slot = gks & 1, par = (gks >> 1) & 1;
        uint32_t aH[2][4], aL[2][4];
#pragma unroll
        for (int i = 0; i < 2; i++) {
            uint32_t rb = sb + C2_HI + (wm + 16 * i + lrow) * 272 + ks * 32 + lhalf;
            ldsm4(aH[i], rb);
            ldsm4(aL[i], rb + (C2_LO - C2_HI));
        }
        MBAR_WAIT(fullb + slot * 8, par);
        uint32_t stg = sb + WSTG + (uint32_t)slot * WSSZ;
        {
            uint32_t rh[4], rl[4];
            uint32_t rb = stg + (wn * 16 + lrow) * 48 + lhalf;
            ldsm4(rh, rb);
            ldsm4(rl, rb + 3072);
            uint32_t bH0[2] = {rh[0], rh[2]}, bH1[2] = {rh[1], rh[3]};
            uint32_t bL0[2] = {rl[0], rl[2]}, bL1[2] = {rl[1], rl[3]};
            mma_bf16(acc2[0][0], aH[0], bH0);
            mma_bf16(acc2[0][1], aH[0], bH1);
            mma_bf16(acc2[1][0], aH[1], bH0);
            mma_bf16(acc2[1][1], aH[1], bH1);
            mma_bf16(acc2[0][0], aH[0], bL0);
            mma_bf16(acc2[0][1], aH[0], bL1);
            mma_bf16(acc2[1][0], aH[1], bL0);
            mma_bf16(acc2[1][1], aH[1], bL1);
            mma_bf16(acc2[0][0], aL[0], bH0);
            mma_bf16(acc2[0][1], aL[0], bH1);
            mma_bf16(acc2[1][0], aL[1], bH0);
            mma_bf16(acc2[1][1], aL[1], bH1);
        }
        if (lane == 0) mbar_arrive(emptyb + slot * 8);
        if (gks + 2 < GK_END) produce(gks + 2);
    }

    // epilogue 2 -> C3 (f32)
    {
#pragma unroll
        for (int i = 0; i < 2; i++)
#pragma unroll
            for (int j = 0; j < 2; j++) {
                int col = wn * 16 + j * 8 + (lane & 3) * 2;
                int row = wm + 16 * i + (lane >> 2);
                float b0v = g_bf2[col], b1v = g_bf2[col + 1];
                float2 v01 = make_float2(fmaxf(acc2[i][j][0] + b0v, 0.f),
                                         fmaxf(acc2[i][j][1] + b1v, 0.f));
                float2 v23 = make_float2(fmaxf(acc2[i][j][2] + b0v, 0.f),
                                         fmaxf(acc2[i][j][3] + b1v, 0.f));
                *(float2*)(smc + C3F + row * 272 + col * 4) = v01;
                *(float2*)(smc + C3F + (row + 8) * 272 + col * 4) = v23;
            }
    }
    __syncthreads();

    // ================= Output: dot Wo + fm + sigmoid =================
    if (t < MTILE) {
        const float* c3 = (const float*)(smc + C3F) + t * 68;
        float s = *(const float*)(smc + FMS + t * 4) + fmb[0] + bo[0];
#pragma unroll
        for (int k = 0; k < N2; k++)
            s = fmaf(c3[k], __ldg(&Wo[k]), s);
        out[m0g + t] = 1.f / (1.f + expf(-s));
    }
}

// ================= Launch =================
extern "C" void kernel_launch(void* const* d_in, const int* in_sizes, int n_in,
                              void* d_out, int out_size)
{
    const int*   sp    = (const int*)  d_in[0];
    const float* dense = (const float*)d_in[1];
    const float* emb   = (const float*)d_in[2];
    const float* bias  = (const float*)d_in[3];
    const float* fmb   = (const float*)d_in[4];
    const float* Wo    = (const float*)d_in[5];
    const float* bo    = (const float*)d_in[6];
    const float* W0    = (const float*)d_in[7];
    const float* b0    = (const float*)d_in[8];
    const float* g0    = (const float*)d_in[9];
    const float* be0   = (const float*)d_in[10];
    const float* W1    = (const float*)d_in[11];
    const float* b1    = (const float*)d_in[12];
    const float* g1    = (const float*)d_in[13];
    const float* be1   = (const float*)d_in[14];
    const float* W2    = (const float*)d_in[15];
    const float* b2    = (const float*)d_in[16];
    const float* g2    = (const float*)d_in[17];
    const float* be2   = (const float*)d_in[18];
    float* out = (float*)d_out;

    prep_all<<<(PREP_TOT + 255) / 256, 256>>>(W0, b0, g0, be0, W1, b1, g1, be1, W2, b2, g2, be2);

    cudaFuncSetAttribute(mlp_kernel, cudaFuncAttributeMaxDynamicSharedMemorySize, SMEM_DYN);
    mlp_kernel<<<NCTA, NTHR, SMEM_DYN>>>(sp, dense, emb, bias, fmb, Wo, bo, out);
}

// round 9
// speedup vs baseline: 3.6821x; 1.1244x over previous
#include <cuda_runtime.h>
#include <cuda_bf16.h>
#include <math.h>
#include <stdint.h>

// ================= Problem constants =================
#define BATCH   16384
#define NFIELD  10
#define EMB     32
#define DENSE   16
#define K0      336         // 21 * 16
#define N0      256
#define N1      128
#define N2      64
#define MTILE   128
#define NCTA    (BATCH / MTILE)   // 128
#define NTHR    512
#define GK_L1   21
#define GK_L2   37
#define GK_END  45

__constant__ int c_offsets[NFIELD] = {
    0, 1000000, 1100000, 1101008, 1102012,
    1102114, 1103114, 1103614, 1103664, 1103776
};

// ================= Device scratch: weight stage images =================
// Each k-step stage is an exact byte image of the smem stage buffer:
//   layer0: [hi 12288][lo 12288] = 24576 B  (n*48 + (kk/8)*16 + (kk%8)*2)
//   layer1: [hi  6144][lo  6144] = 12288 B
//   layer2: [hi  3072][lo  3072] =  6144 B
__device__ __align__(128) char g_S0[21 * 24576];
__device__ __align__(128) char g_S1[16 * 12288];
__device__ __align__(128) char g_S2[8 * 6144];
__device__ float g_bf0[N0], g_bf1[N1], g_bf2[N2];

// ================= PTX helpers =================
__device__ __forceinline__ uint32_t smem_u32(const void* p) {
    uint32_t a;
    asm("{ .reg .u64 t; cvta.to.shared.u64 t, %1; cvt.u32.u64 %0, t; }" : "=r"(a) : "l"(p));
    return a;
}
__device__ __forceinline__ void ldsm4(uint32_t* r, uint32_t a) {
    asm volatile("ldmatrix.sync.aligned.m8n8.x4.shared.b16 {%0,%1,%2,%3}, [%4];"
        : "=r"(r[0]), "=r"(r[1]), "=r"(r[2]), "=r"(r[3]) : "r"(a));
}
__device__ __forceinline__ void mma_bf16(float* c, const uint32_t* a, const uint32_t* b) {
    asm volatile("mma.sync.aligned.m16n8k16.row.col.f32.bf16.bf16.f32 "
        "{%0,%1,%2,%3}, {%4,%5,%6,%7}, {%8,%9}, {%0,%1,%2,%3};"
        : "+f"(c[0]), "+f"(c[1]), "+f"(c[2]), "+f"(c[3])
        : "r"(a[0]), "r"(a[1]), "r"(a[2]), "r"(a[3]), "r"(b[0]), "r"(b[1]));
}
__device__ __forceinline__ uint32_t pack_bf(float lo, float hi) {
    __nv_bfloat162 t = __floats2bfloat162_rn(lo, hi);
    return *(uint32_t*)&t;
}

#define MBAR_INIT(a, c) \
    asm volatile("mbarrier.init.shared.b64 [%0], %1;" :: "r"(a), "r"((uint32_t)(c)) : "memory")
__device__ __forceinline__ void mbar_arrive(uint32_t a) {
    asm volatile("{ .reg .b64 _t; mbarrier.arrive.shared.b64 _t, [%0]; }" :: "r"(a) : "memory");
}
__device__ __forceinline__ void mbar_expect_tx(uint32_t a, uint32_t bytes) {
    asm volatile("mbarrier.arrive.expect_tx.shared.b64 _, [%0], %1;"
        :: "r"(a), "r"(bytes) : "memory");
}
__device__ __forceinline__ void bulk_g2s(uint32_t dst, const void* src, uint32_t bytes,
                                         uint32_t mbar) {
    asm volatile("cp.async.bulk.shared::cluster.global.mbarrier::complete_tx::bytes "
        "[%0], [%1], %2, [%3];"
        :: "r"(dst), "l"(src), "r"(bytes), "r"(mbar) : "memory");
}
#define FENCE_PROXY_ASYNC() asm volatile("fence.proxy.async.shared::cta;" ::: "memory")
#define MBAR_WAIT(mbar, par) do { \
    uint32_t _m = (uint32_t)(mbar); uint32_t _p = (uint32_t)(par); uint32_t _d; \
    asm volatile("{\n\t.reg .pred p;\n\t" \
        "mbarrier.try_wait.parity.acquire.cta.shared::cta.b64 p, [%1], %2;\n\t" \
        "selp.b32 %0, 1, 0, p;\n\t}" : "=r"(_d) : "r"(_m), "r"(_p) : "memory"); \
    if (!_d) { \
        asm volatile("{\n\t.reg .pred P1;\n\t" \
            "WL_%=:\n\t" \
            "mbarrier.try_wait.parity.acquire.cta.shared::cta.b64 P1, [%0], %1, 0x989680;\n\t" \
            "@P1 bra.uni WD_%=;\n\t" \
            "bra.uni WL_%=;\n\t" \
            "WD_%=:\n\t}" :: "r"(_m), "r"(_p) : "memory"); \
    } \
} while (0)

// ================= Kernel 1: weight prep -> staged blobs =================
#define S0SZ (N0 * K0)
#define S1SZ (N1 * N0)
#define S2SZ (N2 * N1)
#define PREP_TOT (S0SZ + S1SZ + S2SZ)

__global__ void prep_all(const float* __restrict__ W0, const float* __restrict__ b0,
                         const float* __restrict__ g0, const float* __restrict__ be0,
                         const float* __restrict__ W1, const float* __restrict__ b1,
                         const float* __restrict__ g1, const float* __restrict__ be1,
                         const float* __restrict__ W2, const float* __restrict__ b2,
                         const float* __restrict__ g2, const float* __restrict__ be2)
{
    const float inv = 0.9999950000374997f;   // 1/sqrt(1+1e-5)
    int i = blockIdx.x * blockDim.x + threadIdx.x;
    if (i >= PREP_TOT) return;
    char* base; uint32_t stagesz, losz; const float *W, *g; int n, k;
    if (i < S0SZ) {
        n = i / K0; k = i - n * K0;
        W = W0; g = g0; base = g_S0; stagesz = 24576; losz = 12288;
        if (i < N0) g_bf0[i] = b0[i] * (g0[i] * inv) + be0[i];
    } else if (i < S0SZ + S1SZ) {
        int li = i - S0SZ; n = li >> 8; k = li & 255;
        W = W1; g = g1; base = g_S1; stagesz = 12288; losz = 6144;
        if (li < N1) g_bf1[li] = b1[li] * (g1[li] * inv) + be1[li];
    } else {
        int li = i - S0SZ - S1SZ; n = li >> 7; k = li & 127;
        W = W2; g = g2; base = g_S2; stagesz = 6144; losz = 3072;
        if (li < N2) g_bf2[li] = b2[li] * (g2[li] * inv) + be2[li];
    }
    float w = W[(i < S0SZ) ? i : ((i < S0SZ + S1SZ) ? (i - S0SZ) : (i - S0SZ - S1SZ))]
              * (g[n] * inv);
    __nv_bfloat16 h = __float2bfloat16(w);
    __nv_bfloat16 l = __float2bfloat16(w - __bfloat162float(h));
    int ks = k >> 4, kk = k & 15;
    uint32_t off = (uint32_t)ks * stagesz + (uint32_t)n * 48u
                 + (uint32_t)((kk >> 3) << 4) + (uint32_t)((kk & 7) << 1);
    *(__nv_bfloat16*)(base + off) = h;
    *(__nv_bfloat16*)(base + off + losz) = l;
}

// ================= Kernel 2: fused embed + FM + HMMA MLP =================
#define X_HI   0
#define X_LO   88064
#define XSTR   688
#define WSTG   176128
#define WSSZ   24576
#define C1_HI  0
#define C1_LO  67584
#define C2_HI  0
#define C2_LO  34816
#define C3F    69632
#define FMS    225280
#define BARS   (FMS + 256)        // full0,full1,empty0,empty1 (8B each)
#define SMEM_DYN (225280 + 512)

__global__ __launch_bounds__(NTHR, 1)
void mlp_kernel(const int* __restrict__ sp, const float* __restrict__ dense,
                const float* __restrict__ emb, const float* __restrict__ bias,
                const float* __restrict__ fmb,
                const float* __restrict__ Wo, const float* __restrict__ bo,
                float* __restrict__ out)
{
    extern __shared__ char smc[];
    const uint32_t sb = smem_u32(smc);
    const int t = threadIdx.x, w = t >> 5, lane = t & 31;
    const int m0g = blockIdx.x * MTILE;
    const int wm = (w >> 2) * 32;
    const int wn = (w & 3);
    const uint32_t lrow = (uint32_t)(lane & 15);
    const uint32_t lhalf = (uint32_t)(lane >> 4) * 16u;
    const uint32_t fullb = sb + BARS;
    const uint32_t emptyb = sb + BARS + 16;

    // single-thread producer: one bulk copy per stage
    auto produce = [&](int gkp) {
        if (t != 0) return;
        int slot = gkp & 1;
        uint32_t stg = sb + WSTG + (uint32_t)slot * WSSZ;
        if (gkp >= 2) MBAR_WAIT(emptyb + slot * 8, ((gkp - 2) >> 1) & 1);
        const char* src; uint32_t bytes;
        if (gkp < GK_L1)      { src = g_S0 + (size_t)gkp * 24576;            bytes = 24576; }
        else if (gkp < GK_L2) { src = g_S1 + (size_t)(gkp - GK_L1) * 12288;  bytes = 12288; }
        else                  { src = g_S2 + (size_t)(gkp - GK_L2) * 6144;   bytes = 6144; }
        mbar_expect_tx(fullb + slot * 8, bytes);
        bulk_g2s(stg, src, bytes, fullb + slot * 8);
    };

    // ---------------- Init barriers, kick stages 0/1, gather X, FM ----------------
    if (t == 0) {
        MBAR_INIT(fullb, 1);    MBAR_INIT(fullb + 8, 1);
        MBAR_INIT(emptyb, 16);  MBAR_INIT(emptyb + 8, 16);
        FENCE_PROXY_ASYNC();
    }
    __syncthreads();
    produce(0);
    produce(1);

#pragma unroll 1
    for (int i = 0; i < 8; i++) {
        int m = w * 8 + i;
        int b = m0g + m;
        float s = 0.f, sq = 0.f;
#pragma unroll
        for (int f = 0; f < NFIELD; f++) {
            int row = sp[b * NFIELD + f] + c_offsets[f];
            float e = __ldg(&emb[(size_t)row * EMB + lane]);
            s += e; sq += e * e;
            __nv_bfloat16 h = __float2bfloat16(e);
            *(__nv_bfloat16*)(smc + X_HI + m * XSTR + (f * EMB + lane) * 2) = h;
            *(__nv_bfloat16*)(smc + X_LO + m * XSTR + (f * EMB + lane) * 2) =
                __float2bfloat16(e - __bfloat162float(h));
        }
        if (lane < DENSE) {
            float dv = dense[b * DENSE + lane];
            __nv_bfloat16 h = __float2bfloat16(dv);
            *(__nv_bfloat16*)(smc + X_HI + m * XSTR + (320 + lane) * 2) = h;
            *(__nv_bfloat16*)(smc + X_LO + m * XSTR + (320 + lane) * 2) =
                __float2bfloat16(dv - __bfloat162float(h));
        }
        float part = 0.5f * (s * s - sq);
        if (lane < NFIELD)
            part += __ldg(&bias[sp[b * NFIELD + lane] + c_offsets[lane]]);
#pragma unroll
        for (int d = 16; d > 0; d >>= 1)
            part += __shfl_down_sync(0xFFFFFFFFu, part, d);
        if (lane == 0) *(float*)(smc + FMS + m * 4) = part;
    }
    __syncthreads();   // X visible to all consumer warps

    // ================= Layer 0: [128x336] -> 256 =================
    float acc0[2][8][4];
#pragma unroll
    for (int i = 0; i < 2; i++)
#pragma unroll
        for (int j = 0; j < 8; j++)
#pragma unroll
            for (int q = 0; q < 4; q++) acc0[i][j][q] = 0.f;

    for (int ks = 0; ks < 21; ks++) {
        const int gks = ks, slot = gks & 1, par = (gks >> 1) & 1;
        uint32_t aH[2][4], aL[2][4];
#pragma unroll
        for (int i = 0; i < 2; i++) {
            uint32_t rb = sb + X_HI + (wm + 16 * i + lrow) * XSTR + ks * 32 + lhalf;
            ldsm4(aH[i], rb);
            ldsm4(aL[i], rb + (X_LO - X_HI));
        }
        MBAR_WAIT(fullb + slot * 8, par);
        uint32_t stg = sb + WSTG + (uint32_t)slot * WSSZ;
        uint32_t bH[8][2], bL[8][2];
#pragma unroll
        for (int nb = 0; nb < 4; nb++) {
            uint32_t rh[4], rl[4];
            uint32_t rb = stg + (wn * 64 + 16 * nb + lrow) * 48 + lhalf;
            ldsm4(rh, rb);
            ldsm4(rl, rb + 12288);
            bH[2 * nb][0] = rh[0]; bH[2 * nb][1] = rh[2];
            bH[2 * nb + 1][0] = rh[1]; bH[2 * nb + 1][1] = rh[3];
            bL[2 * nb][0] = rl[0]; bL[2 * nb][1] = rl[2];
            bL[2 * nb + 1][0] = rl[1]; bL[2 * nb + 1][1] = rl[3];
        }
        if (lane == 0) mbar_arrive(emptyb + slot * 8);
#pragma unroll
        for (int j = 0; j < 8; j++) {
            mma_bf16(acc0[0][j], aH[0], bH[j]);
            mma_bf16(acc0[1][j], aH[1], bH[j]);
        }
#pragma unroll
        for (int j = 0; j < 8; j++) {
            mma_bf16(acc0[0][j], aH[0], bL[j]);
            mma_bf16(acc0[1][j], aH[1], bL[j]);
        }
#pragma unroll
        for (int j = 0; j < 8; j++) {
            mma_bf16(acc0[0][j], aL[0], bH[j]);
            mma_bf16(acc0[1][j], aL[1], bH[j]);
        }
        produce(gks + 2);
    }
    __syncthreads();    // all warps done reading X; X region now dead

    // epilogue 0 -> C1 hi/lo (aliases X)
    {
#pragma unroll
        for (int i = 0; i < 2; i++)
#pragma unroll
            for (int j = 0; j < 8; j++) {
                int col = wn * 64 + j * 8 + (lane & 3) * 2;
                int row = wm + 16 * i + (lane >> 2);
                float b0v = g_bf0[col], b1v = g_bf0[col + 1];
                float v0 = fmaxf(acc0[i][j][0] + b0v, 0.f);
                float v1 = fmaxf(acc0[i][j][1] + b1v, 0.f);
                float v2 = fmaxf(acc0[i][j][2] + b0v, 0.f);
                float v3 = fmaxf(acc0[i][j][3] + b1v, 0.f);
                __nv_bfloat16 h0 = __float2bfloat16(v0), h1 = __float2bfloat16(v1);
                __nv_bfloat16 h2 = __float2bfloat16(v2), h3 = __float2bfloat16(v3);
                *(uint32_t*)(smc + C1_HI + row * 528 + col * 2) =
                    pack_bf(__bfloat162float(h0), __bfloat162float(h1));
                *(uint32_t*)(smc + C1_LO + row * 528 + col * 2) =
                    pack_bf(v0 - __bfloat162float(h0), v1 - __bfloat162float(h1));
                *(uint32_t*)(smc + C1_HI + (row + 8) * 528 + col * 2) =
                    pack_bf(__bfloat162float(h2), __bfloat162float(h3));
                *(uint32_t*)(smc + C1_LO + (row + 8) * 528 + col * 2) =
                    pack_bf(v2 - __bfloat162float(h2), v3 - __bfloat162float(h3));
            }
    }
    __syncthreads();    // C1 visible

    // ================= Layer 1: [128x256] -> 128 =================
    float acc1[2][4][4];
#pragma unroll
    for (int i = 0; i < 2; i++)
#pragma unroll
        for (int j = 0; j < 4; j++)
#pragma unroll
            for (int q = 0; q < 4; q++) acc1[i][j][q] = 0.f;

    for (int ks = 0; ks < 16; ks++) {
        const int gks = GK_L1 + ks, slot = gks & 1, par = (gks >> 1) & 1;
        uint32_t aH[2][4], aL[2][4];
#pragma unroll
        for (int i = 0; i < 2; i++) {
            uint32_t rb = sb + C1_HI + (wm + 16 * i + lrow) * 528 + ks * 32 + lhalf;
            ldsm4(aH[i], rb);
            ldsm4(aL[i], rb + (C1_LO - C1_HI));
        }
        MBAR_WAIT(fullb + slot * 8, par);
        uint32_t stg = sb + WSTG + (uint32_t)slot * WSSZ;
        uint32_t bH[4][2], bL[4][2];
#pragma unroll
        for (int nb = 0; nb < 2; nb++) {
            uint32_t rh[4], rl[4];
            uint32_t rb = stg + (wn * 32 + 16 * nb + lrow) * 48 + lhalf;
            ldsm4(rh, rb);
            ldsm4(rl, rb + 6144);
            bH[2 * nb][0] = rh[0]; bH[2 * nb][1] = rh[2];
            bH[2 * nb + 1][0] = rh[1]; bH[2 * nb + 1][1] = rh[3];
            bL[2 * nb][0] = rl[0]; bL[2 * nb][1] = rl[2];
            bL[2 * nb + 1][0] = rl[1]; bL[2 * nb + 1][1] = rl[3];
        }
        if (lane == 0) mbar_arrive(emptyb + slot * 8);
#pragma unroll
        for (int j = 0; j < 4; j++) {
            mma_bf16(acc1[0][j], aH[0], bH[j]);
            mma_bf16(acc1[1][j], aH[1], bH[j]);
        }
#pragma unroll
        for (int j = 0; j < 4; j++) {
            mma_bf16(acc1[0][j], aH[0], bL[j]);
            mma_bf16(acc1[1][j], aH[1], bL[j]);
        }
#pragma unroll
        for (int j = 0; j < 4; j++) {
            mma_bf16(acc1[0][j], aL[0], bH[j]);
            mma_bf16(acc1[1][j], aL[1], bH[j]);
        }
        produce(gks + 2);
    }
    __syncthreads();    // C1 reads done; C1 region now dead

    // epilogue 1 -> C2 hi/lo (aliases C1)
    {
#pragma unroll
        for (int i = 0; i < 2; i++)
#pragma unroll
            for (int j = 0; j < 4; j++) {
                int col = wn * 32 + j * 8 + (lane & 3) * 2;
                int row = wm + 16 * i + (lane >> 2);
                float b0v = g_bf1[col], b1v = g_bf1[col + 1];
                float v0 = fmaxf(acc1[i][j][0] + b0v, 0.f);
                float v1 = fmaxf(acc1[i][j][1] + b1v, 0.f);
                float v2 = fmaxf(acc1[i][j][2] + b0v, 0.f);
                float v3 = fmaxf(acc1[i][j][3] + b1v, 0.f);
                __nv_bfloat16 h0 = __float2bfloat16(v0), h1 = __float2bfloat16(v1);
                __nv_bfloat16 h2 = __float2bfloat16(v2), h3 = __float2bfloat16(v3);
                *(uint32_t*)(smc + C2_HI + row * 272 + col * 2) =
                    pack_bf(__bfloat162float(h0), __bfloat162float(h1));
                *(uint32_t*)(smc + C2_LO + row * 272 + col * 2) =
                    pack_bf(v0 - __bfloat162float(h0), v1 - __bfloat162float(h1));
                *(uint32_t*)(smc + C2_HI + (row + 8) * 272 + col * 2) =
                    pack_bf(__bfloat162float(h2), __bfloat162float(h3));
                *(uint32_t*)(smc + C2_LO + (row + 8) * 272 + col * 2) =
                    pack_bf(v2 - __bfloat162float(h2), v3 - __bfloat162float(h3));
            }
    }
    __syncthreads();    // C2 visible

    // ================= Layer 2: [128x128] -> 64 =================
    float acc2[2][2][4];
#pragma unroll
    for (int i = 0; i < 2; i++)
#pragma unroll
        for (int j = 0; j < 2; j++)
#pragma unroll
            for (int q = 0; q < 4; q++) acc2[i][j][q] = 0.f;

    for (int ks = 0; ks < 8; ks++) {
        const int gks = GK_L2 + ks, slot = gks & 1, par = (gks >> 1) & 1;
        uint32_t aH[2][4], aL[2][4];
#pragma unroll
        for (int i = 0; i < 2; i++) {
            uint32_t rb = sb + C2_HI + (wm + 16 * i + lrow) * 272 + ks * 32 + lhalf;
            ldsm4(aH[i], rb);
            ldsm4(aL[i], rb + (C2_LO - C2_HI));
        }
        MBAR_WAIT(fullb + slot * 8, par);
        uint32_t stg = sb + WSTG + (uint32_t)slot * WSSZ;
        uint32_t bH[2][2], bL[2][2];
        {
            uint32_t rh[4], rl[4];
            uint32_t rb = stg + (wn * 16 + lrow) * 48 + lhalf;
            ldsm4(rh, rb);
            ldsm4(rl, rb + 3072);
            bH[0][0] = rh[0]; bH[0][1] = rh[2]; bH[1][0] = rh[1]; bH[1][1] = rh[3];
            bL[0][0] = rl[0]; bL[0][1] = rl[2]; bL[1][0] = rl[1]; bL[1][1] = rl[3];
        }
        if (lane == 0) mbar_arrive(emptyb + slot * 8);
#pragma unroll
        for (int j = 0; j < 2; j++) {
            mma_bf16(acc2[0][j], aH[0], bH[j]);
            mma_bf16(acc2[1][j], aH[1], bH[j]);
        }
#pragma unroll
        for (int j = 0; j < 2; j++) {
            mma_bf16(acc2[0][j], aH[0], bL[j]);
            mma_bf16(acc2[1][j], aH[1], bL[j]);
        }
#pragma unroll
        for (int j = 0; j < 2; j++) {
            mma_bf16(acc2[0][j], aL[0], bH[j]);
            mma_bf16(acc2[1][j], aL[1], bH[j]);
        }
        if (gks + 2 < GK_END) produce(gks + 2);
    }

    // epilogue 2 -> C3 (f32)
    {
#pragma unroll
        for (int i = 0; i < 2; i++)
#pragma unroll
            for (int j = 0; j < 2; j++) {
                int col = wn * 16 + j * 8 + (lane & 3) * 2;
                int row = wm + 16 * i + (lane >> 2);
                float b0v = g_bf2[col], b1v = g_bf2[col + 1];
                float2 v01 = make_float2(fmaxf(acc2[i][j][0] + b0v, 0.f),
                                         fmaxf(acc2[i][j][1] + b1v, 0.f));
                float2 v23 = make_float2(fmaxf(acc2[i][j][2] + b0v, 0.f),
                                         fmaxf(acc2[i][j][3] + b1v, 0.f));
                *(float2*)(smc + C3F + row * 272 + col * 4) = v01;
                *(float2*)(smc + C3F + (row + 8) * 272 + col * 4) = v23;
            }
    }
    __syncthreads();

    // ================= Output: dot Wo + fm + sigmoid =================
    if (t < MTILE) {
        const float* c3 = (const float*)(smc + C3F) + t * 68;
        float s = *(const float*)(smc + FMS + t * 4) + fmb[0] + bo[0];
#pragma unroll
        for (int k = 0; k < N2; k++)
            s = fmaf(c3[k], __ldg(&Wo[k]), s);
        out[m0g + t] = 1.f / (1.f + expf(-s));
    }
}

// ================= Launch =================
extern "C" void kernel_launch(void* const* d_in, const int* in_sizes, int n_in,
                              void* d_out, int out_size)
{
    const int*   sp    = (const int*)  d_in[0];
    const float* dense = (const float*)d_in[1];
    const float* emb   = (const float*)d_in[2];
    const float* bias  = (const float*)d_in[3];
    const float* fmb   = (const float*)d_in[4];
    const float* Wo    = (const float*)d_in[5];
    const float* bo    = (const float*)d_in[6];
    const float* W0    = (const float*)d_in[7];
    const float* b0    = (const float*)d_in[8];
    const float* g0    = (const float*)d_in[9];
    const float* be0   = (const float*)d_in[10];
    const float* W1    = (const float*)d_in[11];
    const float* b1    = (const float*)d_in[12];
    const float* g1    = (const float*)d_in[13];
    const float* be1   = (const float*)d_in[14];
    const float* W2    = (const float*)d_in[15];
    const float* b2    = (const float*)d_in[16];
    const float* g2    = (const float*)d_in[17];
    const float* be2   = (const float*)d_in[18];
    float* out = (float*)d_out;

    prep_all<<<(PREP_TOT + 255) / 256, 256>>>(W0, b0, g0, be0, W1, b1, g1, be1, W2, b2, g2, be2);

    cudaFuncSetAttribute(mlp_kernel, cudaFuncAttributeMaxDynamicSharedMemorySize, SMEM_DYN);
    mlp_kernel<<<NCTA, NTHR, SMEM_DYN>>>(sp, dense, emb, bias, fmb, Wo, bo, out);
}

// round 10
// speedup vs baseline: 3.8201x; 1.0375x over previous
#include <cuda_runtime.h>
#include <cuda_bf16.h>
#include <math.h>
#include <stdint.h>

// ================= Problem constants =================
#define BATCH   16384
#define NFIELD  10
#define EMB     32
#define DENSE   16
#define K0      336         // 21 * 16
#define N0      256
#define N1      128
#define N2      64
#define MTILE   128
#define NCTA    (BATCH / MTILE)   // 128
#define NTHR    512
#define GK_L1   21
#define GK_L2   37
#define GK_END  45

__constant__ int c_offsets[NFIELD] = {
    0, 1000000, 1100000, 1101008, 1102012,
    1102114, 1103114, 1103614, 1103664, 1103776
};

// ================= Device scratch: weight stage images =================
__device__ __align__(128) char g_S0[21 * 24576];
__device__ __align__(128) char g_S1[16 * 12288];
__device__ __align__(128) char g_S2[8 * 6144];
__device__ float g_bf0[N0], g_bf1[N1], g_bf2[N2];

// ================= PTX helpers =================
__device__ __forceinline__ uint32_t smem_u32(const void* p) {
    uint32_t a;
    asm("{ .reg .u64 t; cvta.to.shared.u64 t, %1; cvt.u32.u64 %0, t; }" : "=r"(a) : "l"(p));
    return a;
}
__device__ __forceinline__ void ldsm4(uint32_t* r, uint32_t a) {
    asm volatile("ldmatrix.sync.aligned.m8n8.x4.shared.b16 {%0,%1,%2,%3}, [%4];"
        : "=r"(r[0]), "=r"(r[1]), "=r"(r[2]), "=r"(r[3]) : "r"(a));
}
__device__ __forceinline__ void mma_bf16(float* c, const uint32_t* a, const uint32_t* b) {
    asm volatile("mma.sync.aligned.m16n8k16.row.col.f32.bf16.bf16.f32 "
        "{%0,%1,%2,%3}, {%4,%5,%6,%7}, {%8,%9}, {%0,%1,%2,%3};"
        : "+f"(c[0]), "+f"(c[1]), "+f"(c[2]), "+f"(c[3])
        : "r"(a[0]), "r"(a[1]), "r"(a[2]), "r"(a[3]), "r"(b[0]), "r"(b[1]));
}
__device__ __forceinline__ uint32_t pack_bf(float lo, float hi) {
    __nv_bfloat162 t = __floats2bfloat162_rn(lo, hi);
    return *(uint32_t*)&t;
}

#define MBAR_INIT(a, c) \
    asm volatile("mbarrier.init.shared.b64 [%0], %1;" :: "r"(a), "r"((uint32_t)(c)) : "memory")
__device__ __forceinline__ void mbar_arrive(uint32_t a) {
    asm volatile("{ .reg .b64 _t; mbarrier.arrive.shared.b64 _t, [%0]; }" :: "r"(a) : "memory");
}
__device__ __forceinline__ void mbar_expect_tx(uint32_t a, uint32_t bytes) {
    asm volatile("mbarrier.arrive.expect_tx.shared.b64 _, [%0], %1;"
        :: "r"(a), "r"(bytes) : "memory");
}
__device__ __forceinline__ void bulk_g2s(uint32_t dst, const void* src, uint32_t bytes,
                                         uint32_t mbar) {
    asm volatile("cp.async.bulk.shared::cluster.global.mbarrier::complete_tx::bytes "
        "[%0], [%1], %2, [%3];"
        :: "r"(dst), "l"(src), "r"(bytes), "r"(mbar) : "memory");
}
#define FENCE_PROXY_ASYNC() asm volatile("fence.proxy.async.shared::cta;" ::: "memory")
#define MBAR_WAIT(mbar, par) do { \
    uint32_t _m = (uint32_t)(mbar); uint32_t _p = (uint32_t)(par); uint32_t _d; \
    asm volatile("{\n\t.reg .pred p;\n\t" \
        "mbarrier.try_wait.parity.acquire.cta.shared::cta.b64 p, [%1], %2;\n\t" \
        "selp.b32 %0, 1, 0, p;\n\t}" : "=r"(_d) : "r"(_m), "r"(_p) : "memory"); \
    if (!_d) { \
        asm volatile("{\n\t.reg .pred P1;\n\t" \
            "WL_%=:\n\t" \
            "mbarrier.try_wait.parity.acquire.cta.shared::cta.b64 P1, [%0], %1, 0x989680;\n\t" \
            "@P1 bra.uni WD_%=;\n\t" \
            "bra.uni WL_%=;\n\t" \
            "WD_%=:\n\t}" :: "r"(_m), "r"(_p) : "memory"); \
    } \
} while (0)

// ================= Kernel 1: weight prep -> staged blobs =================
#define S0SZ (N0 * K0)
#define S1SZ (N1 * N0)
#define S2SZ (N2 * N1)
#define PREP_TOT (S0SZ + S1SZ + S2SZ)

__global__ void prep_all(const float* __restrict__ W0, const float* __restrict__ b0,
                         const float* __restrict__ g0, const float* __restrict__ be0,
                         const float* __restrict__ W1, const float* __restrict__ b1,
                         const float* __restrict__ g1, const float* __restrict__ be1,
                         const float* __restrict__ W2, const float* __restrict__ b2,
                         const float* __restrict__ g2, const float* __restrict__ be2)
{
    const float inv = 0.9999950000374997f;   // 1/sqrt(1+1e-5)
    int i = blockIdx.x * blockDim.x + threadIdx.x;
    if (i >= PREP_TOT) return;
    char* base; uint32_t stagesz, losz; const float *W, *g; int n, k;
    if (i < S0SZ) {
        n = i / K0; k = i - n * K0;
        W = W0; g = g0; base = g_S0; stagesz = 24576; losz = 12288;
        if (i < N0) g_bf0[i] = b0[i] * (g0[i] * inv) + be0[i];
    } else if (i < S0SZ + S1SZ) {
        int li = i - S0SZ; n = li >> 8; k = li & 255;
        W = W1; g = g1; base = g_S1; stagesz = 12288; losz = 6144;
        if (li < N1) g_bf1[li] = b1[li] * (g1[li] * inv) + be1[li];
    } else {
        int li = i - S0SZ - S1SZ; n = li >> 7; k = li & 127;
        W = W2; g = g2; base = g_S2; stagesz = 6144; losz = 3072;
        if (li < N2) g_bf2[li] = b2[li] * (g2[li] * inv) + be2[li];
    }
    float w = W[(i < S0SZ) ? i : ((i < S0SZ + S1SZ) ? (i - S0SZ) : (i - S0SZ - S1SZ))]
              * (g[n] * inv);
    __nv_bfloat16 h = __float2bfloat16(w);
    __nv_bfloat16 l = __float2bfloat16(w - __bfloat162float(h));
    int ks = k >> 4, kk = k & 15;
    uint32_t off = (uint32_t)ks * stagesz + (uint32_t)n * 48u
                 + (uint32_t)((kk >> 3) << 4) + (uint32_t)((kk & 7) << 1);
    *(__nv_bfloat16*)(base + off) = h;
    *(__nv_bfloat16*)(base + off + losz) = l;
}

// ================= Kernel 2: fused embed + FM + HMMA MLP =================
#define X_HI   0
#define X_LO   88064
#define XSTR   688
#define WSTG   176128
#define WSSZ   24576
#define C1_HI  0
#define C1_LO  67584
#define C2_HI  0
#define C2_LO  34816
#define C3F    69632
#define FMS    225280
#define BARS   (FMS + 256)
#define SMEM_DYN (225280 + 512)

__global__ __launch_bounds__(NTHR, 1)
void mlp_kernel(const int* __restrict__ sp, const float* __restrict__ dense,
                const float* __restrict__ emb, const float* __restrict__ bias,
                const float* __restrict__ fmb,
                const float* __restrict__ Wo, const float* __restrict__ bo,
                float* __restrict__ out)
{
    extern __shared__ char smc[];
    const uint32_t sb = smem_u32(smc);
    const int t = threadIdx.x, w = t >> 5, lane = t & 31;
    const int m0g = blockIdx.x * MTILE;
    const int wm = (w >> 2) * 32;
    const int wn = (w & 3);
    const uint32_t lrow = (uint32_t)(lane & 15);
    const uint32_t lhalf = (uint32_t)(lane >> 4) * 16u;
    const uint32_t fullb = sb + BARS;
    const uint32_t emptyb = sb + BARS + 16;

    auto produce = [&](int gkp) {
        if (t != 0) return;
        int slot = gkp & 1;
        uint32_t stg = sb + WSTG + (uint32_t)slot * WSSZ;
        if (gkp >= 2) MBAR_WAIT(emptyb + slot * 8, ((gkp - 2) >> 1) & 1);
        const char* src; uint32_t bytes;
        if (gkp < GK_L1)      { src = g_S0 + (size_t)gkp * 24576;            bytes = 24576; }
        else if (gkp < GK_L2) { src = g_S1 + (size_t)(gkp - GK_L1) * 12288;  bytes = 12288; }
        else                  { src = g_S2 + (size_t)(gkp - GK_L2) * 6144;   bytes = 6144; }
        mbar_expect_tx(fullb + slot * 8, bytes);
        bulk_g2s(stg, src, bytes, fullb + slot * 8);
    };

    // ---------------- Init barriers, kick stages 0/1, gather X, FM ----------------
    if (t == 0) {
        MBAR_INIT(fullb, 1);    MBAR_INIT(fullb + 8, 1);
        MBAR_INIT(emptyb, 16);  MBAR_INIT(emptyb + 8, 16);
        FENCE_PROXY_ASYNC();
    }
    __syncthreads();
    produce(0);
    produce(1);

    // fully unrolled gather: all 80 LDGs per warp in flight
#pragma unroll
    for (int i = 0; i < 8; i++) {
        int m = w * 8 + i;
        int b = m0g + m;
        float e[NFIELD];
#pragma unroll
        for (int f = 0; f < NFIELD; f++) {
            int row = sp[b * NFIELD + f] + c_offsets[f];
            e[f] = __ldg(&emb[(size_t)row * EMB + lane]);
        }
        float s = 0.f, sq = 0.f;
#pragma unroll
        for (int f = 0; f < NFIELD; f++) {
            s += e[f]; sq += e[f] * e[f];
            __nv_bfloat16 h = __float2bfloat16(e[f]);
            *(__nv_bfloat16*)(smc + X_HI + m * XSTR + (f * EMB + lane) * 2) = h;
            *(__nv_bfloat16*)(smc + X_LO + m * XSTR + (f * EMB + lane) * 2) =
                __float2bfloat16(e[f] - __bfloat162float(h));
        }
        if (lane < DENSE) {
            float dv = dense[b * DENSE + lane];
            __nv_bfloat16 h = __float2bfloat16(dv);
            *(__nv_bfloat16*)(smc + X_HI + m * XSTR + (320 + lane) * 2) = h;
            *(__nv_bfloat16*)(smc + X_LO + m * XSTR + (320 + lane) * 2) =
                __float2bfloat16(dv - __bfloat162float(h));
        }
        float part = 0.5f * (s * s - sq);
        if (lane < NFIELD)
            part += __ldg(&bias[sp[b * NFIELD + lane] + c_offsets[lane]]);
#pragma unroll
        for (int d = 16; d > 0; d >>= 1)
            part += __shfl_down_sync(0xFFFFFFFFu, part, d);
        if (lane == 0) *(float*)(smc + FMS + m * 4) = part;
    }
    __syncthreads();   // X visible

    // ================= Layer 0: [128x336] -> 256 =================
    float acc0[2][8][4];
#pragma unroll
    for (int i = 0; i < 2; i++)
#pragma unroll
        for (int j = 0; j < 8; j++)
#pragma unroll
            for (int q = 0; q < 4; q++) acc0[i][j][q] = 0.f;

    uint32_t aH[2][4], aL[2][4];
#pragma unroll
    for (int i = 0; i < 2; i++) {
        uint32_t rb = sb + X_HI + (wm + 16 * i + lrow) * XSTR + lhalf;
        ldsm4(aH[i], rb);
        ldsm4(aL[i], rb + (X_LO - X_HI));
    }

    for (int ks = 0; ks < 21; ks++) {
        const int gks = ks, slot = gks & 1, par = (gks >> 1) & 1;
        MBAR_WAIT(fullb + slot * 8, par);
        uint32_t stg = sb + WSTG + (uint32_t)slot * WSSZ;
        uint32_t bH[8][2], bL[8][2];
#pragma unroll
        for (int nb = 0; nb < 4; nb++) {
            uint32_t rh[4], rl[4];
            uint32_t rb = stg + (wn * 64 + 16 * nb + lrow) * 48 + lhalf;
            ldsm4(rh, rb);
            ldsm4(rl, rb + 12288);
            bH[2 * nb][0] = rh[0]; bH[2 * nb][1] = rh[2];
            bH[2 * nb + 1][0] = rh[1]; bH[2 * nb + 1][1] = rh[3];
            bL[2 * nb][0] = rl[0]; bL[2 * nb][1] = rl[2];
            bL[2 * nb + 1][0] = rl[1]; bL[2 * nb + 1][1] = rl[3];
        }
        if (lane == 0) mbar_arrive(emptyb + slot * 8);
        // group HH (aH)
#pragma unroll
        for (int j = 0; j < 8; j++) {
            mma_bf16(acc0[0][j], aH[0], bH[j]);
            mma_bf16(acc0[1][j], aH[1], bH[j]);
        }
        // group HL (aH) — aH dead after this
#pragma unroll
        for (int j = 0; j < 8; j++) {
            mma_bf16(acc0[0][j], aH[0], bL[j]);
            mma_bf16(acc0[1][j], aH[1], bL[j]);
        }
        if (ks + 1 < 21) {      // prefetch next aH into freed regs
#pragma unroll
            for (int i = 0; i < 2; i++)
                ldsm4(aH[i], sb + X_HI + (wm + 16 * i + lrow) * XSTR + (ks + 1) * 32 + lhalf);
        }
        // group LH (aL) — aL dead after this
#pragma unroll
        for (int j = 0; j < 8; j++) {
            mma_bf16(acc0[0][j], aL[0], bH[j]);
            mma_bf16(acc0[1][j], aL[1], bH[j]);
        }
        if (ks + 1 < 21) {      // prefetch next aL
#pragma unroll
            for (int i = 0; i < 2; i++)
                ldsm4(aL[i], sb + X_LO + (wm + 16 * i + lrow) * XSTR + (ks + 1) * 32 + lhalf);
        }
        produce(gks + 2);
    }
    __syncthreads();    // X reads done; X region dead

    // epilogue 0 -> C1 hi/lo (aliases X)
    {
#pragma unroll
        for (int i = 0; i < 2; i++)
#pragma unroll
            for (int j = 0; j < 8; j++) {
                int col = wn * 64 + j * 8 + (lane & 3) * 2;
                int row = wm + 16 * i + (lane >> 2);
                float b0v = g_bf0[col], b1v = g_bf0[col + 1];
                float v0 = fmaxf(acc0[i][j][0] + b0v, 0.f);
                float v1 = fmaxf(acc0[i][j][1] + b1v, 0.f);
                float v2 = fmaxf(acc0[i][j][2] + b0v, 0.f);
                float v3 = fmaxf(acc0[i][j][3] + b1v, 0.f);
                __nv_bfloat16 h0 = __float2bfloat16(v0), h1 = __float2bfloat16(v1);
                __nv_bfloat16 h2 = __float2bfloat16(v2), h3 = __float2bfloat16(v3);
                *(uint32_t*)(smc + C1_HI + row * 528 + col * 2) =
                    pack_bf(__bfloat162float(h0), __bfloat162float(h1));
                *(uint32_t*)(smc + C1_LO + row * 528 + col * 2) =
                    pack_bf(v0 - __bfloat162float(h0), v1 - __bfloat162float(h1));
                *(uint32_t*)(smc + C1_HI + (row + 8) * 528 + col * 2) =
                    pack_bf(__bfloat162float(h2), __bfloat162float(h3));
                *(uint32_t*)(smc + C1_LO + (row + 8) * 528 + col * 2) =
                    pack_bf(v2 - __bfloat162float(h2), v3 - __bfloat162float(h3));
            }
    }
    __syncthreads();    // C1 visible

    // ================= Layer 1: [128x256] -> 128 =================
    float acc1[2][4][4];
#pragma unroll
    for (int i = 0; i < 2; i++)
#pragma unroll
        for (int j = 0; j < 4; j++)
#pragma unroll
            for (int q = 0; q < 4; q++) acc1[i][j][q] = 0.f;

#pragma unroll
    for (int i = 0; i < 2; i++) {
        uint32_t rb = sb + C1_HI + (wm + 16 * i + lrow) * 528 + lhalf;
        ldsm4(aH[i], rb);
        ldsm4(aL[i], rb + (C1_LO - C1_HI));
    }

    for (int ks = 0; ks < 16; ks++) {
        const int gks = GK_L1 + ks, slot = gks & 1, par = (gks >> 1) & 1;
        MBAR_WAIT(fullb + slot * 8, par);
        uint32_t stg = sb + WSTG + (uint32_t)slot * WSSZ;
        uint32_t bH[4][2], bL[4][2];
#pragma unroll
        for (int nb = 0; nb < 2; nb++) {
            uint32_t rh[4], rl[4];
            uint32_t rb = stg + (wn * 32 + 16 * nb + lrow) * 48 + lhalf;
            ldsm4(rh, rb);
            ldsm4(rl, rb + 6144);
            bH[2 * nb][0] = rh[0]; bH[2 * nb][1] = rh[2];
            bH[2 * nb + 1][0] = rh[1]; bH[2 * nb + 1][1] = rh[3];
            bL[2 * nb][0] = rl[0]; bL[2 * nb][1] = rl[2];
            bL[2 * nb + 1][0] = rl[1]; bL[2 * nb + 1][1] = rl[3];
        }
        if (lane == 0) mbar_arrive(emptyb + slot * 8);
#pragma unroll
        for (int j = 0; j < 4; j++) {
            mma_bf16(acc1[0][j], aH[0], bH[j]);
            mma_bf16(acc1[1][j], aH[1], bH[j]);
        }
#pragma unroll
        for (int j = 0; j < 4; j++) {
            mma_bf16(acc1[0][j], aH[0], bL[j]);
            mma_bf16(acc1[1][j], aH[1], bL[j]);
        }
        if (ks + 1 < 16) {
#pragma unroll
            for (int i = 0; i < 2; i++)
                ldsm4(aH[i], sb + C1_HI + (wm + 16 * i + lrow) * 528 + (ks + 1) * 32 + lhalf);
        }
#pragma unroll
        for (int j = 0; j < 4; j++) {
            mma_bf16(acc1[0][j], aL[0], bH[j]);
            mma_bf16(acc1[1][j], aL[1], bH[j]);
        }
        if (ks + 1 < 16) {
#pragma unroll
            for (int i = 0; i < 2; i++)
                ldsm4(aL[i], sb + C1_LO + (wm + 16 * i + lrow) * 528 + (ks + 1) * 32 + lhalf);
        }
        produce(gks + 2);
    }
    __syncthreads();    // C1 reads done; C1 region dead

    // epilogue 1 -> C2 hi/lo (aliases C1)
    {
#pragma unroll
        for (int i = 0; i < 2; i++)
#pragma unroll
            for (int j = 0; j < 4; j++) {
                int col = wn * 32 + j * 8 + (lane & 3) * 2;
                int row = wm + 16 * i + (lane >> 2);
                float b0v = g_bf1[col], b1v = g_bf1[col + 1];
                float v0 = fmaxf(acc1[i][j][0] + b0v, 0.f);
                float v1 = fmaxf(acc1[i][j][1] + b1v, 0.f);
                float v2 = fmaxf(acc1[i][j][2] + b0v, 0.f);
                float v3 = fmaxf(acc1[i][j][3] + b1v, 0.f);
                __nv_bfloat16 h0 = __float2bfloat16(v0), h1 = __float2bfloat16(v1);
                __nv_bfloat16 h2 = __float2bfloat16(v2), h3 = __float2bfloat16(v3);
                *(uint32_t*)(smc + C2_HI + row * 272 + col * 2) =
                    pack_bf(__bfloat162float(h0), __bfloat162float(h1));
                *(uint32_t*)(smc + C2_LO + row * 272 + col * 2) =
                    pack_bf(v0 - __bfloat162float(h0), v1 - __bfloat162float(h1));
                *(uint32_t*)(smc + C2_HI + (row + 8) * 272 + col * 2) =
                    pack_bf(__bfloat162float(h2), __bfloat162float(h3));
                *(uint32_t*)(smc + C2_LO + (row + 8) * 272 + col * 2) =
                    pack_bf(v2 - __bfloat162float(h2), v3 - __bfloat162float(h3));
            }
    }
    __syncthreads();    // C2 visible

    // ================= Layer 2: [128x128] -> 64 =================
    float acc2[2][2][4];
#pragma unroll
    for (int i = 0; i < 2; i++)
#pragma unroll
        for (int j = 0; j < 2; j++)
#pragma unroll
            for (int q = 0; q < 4; q++) acc2[i][j][q] = 0.f;

#pragma unroll
    for (int i = 0; i < 2; i++) {
        uint32_t rb = sb + C2_HI + (wm + 16 * i + lrow) * 272 + lhalf;
        ldsm4(aH[i], rb);
        ldsm4(aL[i], rb + (C2_LO - C2_HI));
    }

    for (int ks = 0; ks < 8; ks++) {
        const int gks = GK_L2 + ks, slot = gks & 1, par = (gks >> 1) & 1;
        MBAR_WAIT(fullb + slot * 8, par);
        uint32_t stg = sb + WSTG + (uint32_t)slot * WSSZ;
        uint32_t bH[2][2], bL[2][2];
        {
            uint32_t rh[4], rl[4];
            uint32_t rb = stg + (wn * 16 + lrow) * 48 + lhalf;
            ldsm4(rh, rb);
            ldsm4(rl, rb + 3072);
            bH[0][0] = rh[0]; bH[0][1] = rh[2]; bH[1][0] = rh[1]; bH[1][1] = rh[3];
            bL[0][0] = rl[0]; bL[0][1] = rl[2]; bL[1][0] = rl[1]; bL[1][1] = rl[3];
        }
        if (lane == 0) mbar_arrive(emptyb + slot * 8);
#pragma unroll
        for (int j = 0; j < 2; j++) {
            mma_bf16(acc2[0][j], aH[0], bH[j]);
            mma_bf16(acc2[1][j], aH[1], bH[j]);
        }
#pragma unroll
        for (int j = 0; j < 2; j++) {
            mma_bf16(acc2[0][j], aH[0], bL[j]);
            mma_bf16(acc2[1][j], aH[1], bL[j]);
        }
        if (ks + 1 < 8) {
#pragma unroll
            for (int i = 0; i < 2; i++)
                ldsm4(aH[i], sb + C2_HI + (wm + 16 * i + lrow) * 272 + (ks + 1) * 32 + lhalf);
        }
#pragma unroll
        for (int j = 0; j < 2; j++) {
            mma_bf16(acc2[0][j], aL[0], bH[j]);
            mma_bf16(acc2[1][j], aL[1], bH[j]);
        }
        if (ks + 1 < 8) {
#pragma unroll
            for (int i = 0; i < 2; i++)
                ldsm4(aL[i], sb + C2_LO + (wm + 16 * i + lrow) * 272 + (ks + 1) * 32 + lhalf);
        }
        if (gks + 2 < GK_END) produce(gks + 2);
    }

    // epilogue 2 -> C3 (f32)
    {
#pragma unroll
        for (int i = 0; i < 2; i++)
#pragma unroll
            for (int j = 0; j < 2; j++) {
                int col = wn * 16 + j * 8 + (lane & 3) * 2;
                int row = wm + 16 * i + (lane >> 2);
                float b0v = g_bf2[col], b1v = g_bf2[col + 1];
                float2 v01 = make_float2(fmaxf(acc2[i][j][0] + b0v, 0.f),
                                         fmaxf(acc2[i][j][1] + b1v, 0.f));
                float2 v23 = make_float2(fmaxf(acc2[i][j][2] + b0v, 0.f),
                                         fmaxf(acc2[i][j][3] + b1v, 0.f));
                *(float2*)(smc + C3F + row * 272 + col * 4) = v01;
                *(float2*)(smc + C3F + (row + 8) * 272 + col * 4) = v23;
            }
    }
    __syncthreads();

    // ================= Output: dot Wo + fm + sigmoid =================
    if (t < MTILE) {
        const float* c3 = (const float*)(smc + C3F) + t * 68;
        float s = *(const float*)(smc + FMS + t * 4) + fmb[0] + bo[0];
#pragma unroll
        for (int k = 0; k < N2; k++)
            s = fmaf(c3[k], __ldg(&Wo[k]), s);
        out[m0g + t] = 1.f / (1.f + __expf(-s));
    }
}

// ================= Launch =================
extern "C" void kernel_launch(void* const* d_in, const int* in_sizes, int n_in,
                              void* d_out, int out_size)
{
    const int*   sp    = (const int*)  d_in[0];
    const float* dense = (const float*)d_in[1];
    const float* emb   = (const float*)d_in[2];
    const float* bias  = (const float*)d_in[3];
    const float* fmb   = (const float*)d_in[4];
    const float* Wo    = (const float*)d_in[5];
    const float* bo    = (const float*)d_in[6];
    const float* W0    = (const float*)d_in[7];
    const float* b0    = (const float*)d_in[8];
    const float* g0    = (const float*)d_in[9];
    const float* be0   = (const float*)d_in[10];
    const float* W1    = (const float*)d_in[11];
    const float* b1    = (const float*)d_in[12];
    const float* g1    = (const float*)d_in[13];
    const float* be1   = (const float*)d_in[14];
    const float* W2    = (const float*)d_in[15];
    const float* b2    = (const float*)d_in[16];
    const float* g2    = (const float*)d_in[17];
    const float* be2   = (const float*)d_in[18];
    float* out = (float*)d_out;

    prep_all<<<(PREP_TOT + 255) / 256, 256>>>(W0, b0, g0, be0, W1, b1, g1, be1, W2, b2, g2, be2);

    cudaFuncSetAttribute(mlp_kernel, cudaFuncAttributeMaxDynamicSharedMemorySize, SMEM_DYN);
    mlp_kernel<<<NCTA, NTHR, SMEM_DYN>>>(sp, dense, emb, bias, fmb, Wo, bo, out);
}

// round 11
// speedup vs baseline: 4.6056x; 1.2056x over previous
#include <cuda_runtime.h>
#include <cuda_fp16.h>
#include <math.h>
#include <stdint.h>

// ================= Problem constants =================
#define BATCH   16384
#define NFIELD  10
#define EMB     32
#define DENSE   16
#define K0      336         // 21 * 16
#define N0      256
#define N1      128
#define N2      64
#define MTILE   128
#define NCTA    (BATCH / MTILE)   // 128
#define NTHR    512
#define GK_L1   21
#define GK_L2   37
#define GK_END  45

__constant__ int c_offsets[NFIELD] = {
    0, 1000000, 1100000, 1101008, 1102012,
    1102114, 1103114, 1103614, 1103664, 1103776
};

// ================= Device scratch: weight stage images (fp16, hi only) =====
//   layer0 stage: 256 rows x 48B = 12288 B   (n*48 + (kk/8)*16 + (kk%8)*2)
//   layer1 stage: 128 rows x 48B =  6144 B
//   layer2 stage:  64 rows x 48B =  3072 B
__device__ __align__(128) char g_S0[21 * 12288];
__device__ __align__(128) char g_S1[16 * 6144];
__device__ __align__(128) char g_S2[8 * 3072];
__device__ float g_bf0[N0], g_bf1[N1], g_bf2[N2];

// ================= PTX helpers =================
__device__ __forceinline__ uint32_t smem_u32(const void* p) {
    uint32_t a;
    asm("{ .reg .u64 t; cvta.to.shared.u64 t, %1; cvt.u32.u64 %0, t; }" : "=r"(a) : "l"(p));
    return a;
}
__device__ __forceinline__ void ldsm4(uint32_t* r, uint32_t a) {
    asm volatile("ldmatrix.sync.aligned.m8n8.x4.shared.b16 {%0,%1,%2,%3}, [%4];"
        : "=r"(r[0]), "=r"(r[1]), "=r"(r[2]), "=r"(r[3]) : "r"(a));
}
__device__ __forceinline__ void mma_f16(float* c, const uint32_t* a, const uint32_t* b) {
    asm volatile("mma.sync.aligned.m16n8k16.row.col.f32.f16.f16.f32 "
        "{%0,%1,%2,%3}, {%4,%5,%6,%7}, {%8,%9}, {%0,%1,%2,%3};"
        : "+f"(c[0]), "+f"(c[1]), "+f"(c[2]), "+f"(c[3])
        : "r"(a[0]), "r"(a[1]), "r"(a[2]), "r"(a[3]), "r"(b[0]), "r"(b[1]));
}
__device__ __forceinline__ uint32_t pack_h2(__half a, __half b) {
    __half2 t = __halves2half2(a, b);
    return *(uint32_t*)&t;
}

#define MBAR_INIT(a, c) \
    asm volatile("mbarrier.init.shared.b64 [%0], %1;" :: "r"(a), "r"((uint32_t)(c)) : "memory")
__device__ __forceinline__ void mbar_arrive(uint32_t a) {
    asm volatile("{ .reg .b64 _t; mbarrier.arrive.shared.b64 _t, [%0]; }" :: "r"(a) : "memory");
}
__device__ __forceinline__ void mbar_expect_tx(uint32_t a, uint32_t bytes) {
    asm volatile("mbarrier.arrive.expect_tx.shared.b64 _, [%0], %1;"
        :: "r"(a), "r"(bytes) : "memory");
}
__device__ __forceinline__ void bulk_g2s(uint32_t dst, const void* src, uint32_t bytes,
                                         uint32_t mbar) {
    asm volatile("cp.async.bulk.shared::cluster.global.mbarrier::complete_tx::bytes "
        "[%0], [%1], %2, [%3];"
        :: "r"(dst), "l"(src), "r"(bytes), "r"(mbar) : "memory");
}
#define FENCE_PROXY_ASYNC() asm volatile("fence.proxy.async.shared::cta;" ::: "memory")
#define MBAR_WAIT(mbar, par) do { \
    uint32_t _m = (uint32_t)(mbar); uint32_t _p = (uint32_t)(par); uint32_t _d; \
    asm volatile("{\n\t.reg .pred p;\n\t" \
        "mbarrier.try_wait.parity.acquire.cta.shared::cta.b64 p, [%1], %2;\n\t" \
        "selp.b32 %0, 1, 0, p;\n\t}" : "=r"(_d) : "r"(_m), "r"(_p) : "memory"); \
    if (!_d) { \
        asm volatile("{\n\t.reg .pred P1;\n\t" \
            "WL_%=:\n\t" \
            "mbarrier.try_wait.parity.acquire.cta.shared::cta.b64 P1, [%0], %1, 0x989680;\n\t" \
            "@P1 bra.uni WD_%=;\n\t" \
            "bra.uni WL_%=;\n\t" \
            "WD_%=:\n\t}" :: "r"(_m), "r"(_p) : "memory"); \
    } \
} while (0)

// ================= Kernel 1: weight prep -> fp16 staged blobs =================
#define S0SZ (N0 * K0)
#define S1SZ (N1 * N0)
#define S2SZ (N2 * N1)
#define PREP_TOT (S0SZ + S1SZ + S2SZ)

__global__ void prep_all(const float* __restrict__ W0, const float* __restrict__ b0,
                         const float* __restrict__ g0, const float* __restrict__ be0,
                         const float* __restrict__ W1, const float* __restrict__ b1,
                         const float* __restrict__ g1, const float* __restrict__ be1,
                         const float* __restrict__ W2, const float* __restrict__ b2,
                         const float* __restrict__ g2, const float* __restrict__ be2)
{
    const float inv = 0.9999950000374997f;   // 1/sqrt(1+1e-5)
    int i = blockIdx.x * blockDim.x + threadIdx.x;
    if (i >= PREP_TOT) return;
    char* base; uint32_t stagesz; const float *W, *g; int n, k, li;
    if (i < S0SZ) {
        li = i; n = li / K0; k = li - n * K0;
        W = W0; g = g0; base = g_S0; stagesz = 12288;
        if (li < N0) g_bf0[li] = b0[li] * (g0[li] * inv) + be0[li];
    } else if (i < S0SZ + S1SZ) {
        li = i - S0SZ; n = li >> 8; k = li & 255;
        W = W1; g = g1; base = g_S1; stagesz = 6144;
        if (li < N1) g_bf1[li] = b1[li] * (g1[li] * inv) + be1[li];
    } else {
        li = i - S0SZ - S1SZ; n = li >> 7; k = li & 127;
        W = W2; g = g2; base = g_S2; stagesz = 3072;
        if (li < N2) g_bf2[li] = b2[li] * (g2[li] * inv) + be2[li];
    }
    float w = W[li] * (g[n] * inv);
    int ks = k >> 4, kk = k & 15;
    uint32_t off = (uint32_t)ks * stagesz + (uint32_t)n * 48u
                 + (uint32_t)((kk >> 3) << 4) + (uint32_t)((kk & 7) << 1);
    *(__half*)(base + off) = __float2half_rn(w);
}

// ================= Kernel 2: fused embed + FM + HMMA MLP (fp16) =============
#define X_HI   0
#define X_LO   88064
#define XSTR   688
#define WSTG   176128
#define WSSZ   12288
#define C1_HI  0
#define C1_LO  67584
#define C2_HI  0
#define C2_LO  34816
#define C3F    69632
#define FMS    200704
#define BARS   (FMS + 256)
#define SMEM_DYN (200704 + 512)

__global__ __launch_bounds__(NTHR, 1)
void mlp_kernel(const int* __restrict__ sp, const float* __restrict__ dense,
                const float* __restrict__ emb, const float* __restrict__ bias,
                const float* __restrict__ fmb,
                const float* __restrict__ Wo, const float* __restrict__ bo,
                float* __restrict__ out)
{
    extern __shared__ char smc[];
    const uint32_t sb = smem_u32(smc);
    const int t = threadIdx.x, w = t >> 5, lane = t & 31;
    const int m0g = blockIdx.x * MTILE;
    const int wm = (w >> 2) * 32;
    const int wn = (w & 3);
    const uint32_t lrow = (uint32_t)(lane & 15);
    const uint32_t lhalf = (uint32_t)(lane >> 4) * 16u;
    const uint32_t fullb = sb + BARS;
    const uint32_t emptyb = sb + BARS + 16;

    auto produce = [&](int gkp) {
        if (t != 0) return;
        int slot = gkp & 1;
        uint32_t stg = sb + WSTG + (uint32_t)slot * WSSZ;
        if (gkp >= 2) MBAR_WAIT(emptyb + slot * 8, ((gkp - 2) >> 1) & 1);
        const char* src; uint32_t bytes;
        if (gkp < GK_L1)      { src = g_S0 + (size_t)gkp * 12288;            bytes = 12288; }
        else if (gkp < GK_L2) { src = g_S1 + (size_t)(gkp - GK_L1) * 6144;   bytes = 6144; }
        else                  { src = g_S2 + (size_t)(gkp - GK_L2) * 3072;   bytes = 3072; }
        mbar_expect_tx(fullb + slot * 8, bytes);
        bulk_g2s(stg, src, bytes, fullb + slot * 8);
    };

    // ---------------- Init barriers, kick stages 0/1, gather X, FM ----------------
    if (t == 0) {
        MBAR_INIT(fullb, 1);    MBAR_INIT(fullb + 8, 1);
        MBAR_INIT(emptyb, 16);  MBAR_INIT(emptyb + 8, 16);
        FENCE_PROXY_ASYNC();
    }
    __syncthreads();
    produce(0);
    produce(1);

    // fully unrolled gather: all 80 LDGs per warp in flight
#pragma unroll
    for (int i = 0; i < 8; i++) {
        int m = w * 8 + i;
        int b = m0g + m;
        float e[NFIELD];
#pragma unroll
        for (int f = 0; f < NFIELD; f++) {
            int row = sp[b * NFIELD + f] + c_offsets[f];
            e[f] = __ldg(&emb[(size_t)row * EMB + lane]);
        }
        float s = 0.f, sq = 0.f;
#pragma unroll
        for (int f = 0; f < NFIELD; f++) {
            s += e[f]; sq += e[f] * e[f];
            __half h = __float2half_rn(e[f]);
            *(__half*)(smc + X_HI + m * XSTR + (f * EMB + lane) * 2) = h;
            *(__half*)(smc + X_LO + m * XSTR + (f * EMB + lane) * 2) =
                __float2half_rn(e[f] - __half2float(h));
        }
        if (lane < DENSE) {
            float dv = dense[b * DENSE + lane];
            __half h = __float2half_rn(dv);
            *(__half*)(smc + X_HI + m * XSTR + (320 + lane) * 2) = h;
            *(__half*)(smc + X_LO + m * XSTR + (320 + lane) * 2) =
                __float2half_rn(dv - __half2float(h));
        }
        float part = 0.5f * (s * s - sq);
        if (lane < NFIELD)
            part += __ldg(&bias[sp[b * NFIELD + lane] + c_offsets[lane]]);
#pragma unroll
        for (int d = 16; d > 0; d >>= 1)
            part += __shfl_down_sync(0xFFFFFFFFu, part, d);
        if (lane == 0) *(float*)(smc + FMS + m * 4) = part;
    }
    __syncthreads();   // X visible

    // ================= Layer 0: [128x336] -> 256 =================
    float acc0[2][8][4];
#pragma unroll
    for (int i = 0; i < 2; i++)
#pragma unroll
        for (int j = 0; j < 8; j++)
#pragma unroll
            for (int q = 0; q < 4; q++) acc0[i][j][q] = 0.f;

    uint32_t aH[2][4], aL[2][4];
#pragma unroll
    for (int i = 0; i < 2; i++) {
        uint32_t rb = sb + X_HI + (wm + 16 * i + lrow) * XSTR + lhalf;
        ldsm4(aH[i], rb);
        ldsm4(aL[i], rb + (X_LO - X_HI));
    }

    for (int ks = 0; ks < 21; ks++) {
        const int gks = ks, slot = gks & 1, par = (gks >> 1) & 1;
        MBAR_WAIT(fullb + slot * 8, par);
        uint32_t stg = sb + WSTG + (uint32_t)slot * WSSZ;
        uint32_t bH[8][2];
#pragma unroll
        for (int nb = 0; nb < 4; nb++) {
            uint32_t rh[4];
            ldsm4(rh, stg + (wn * 64 + 16 * nb + lrow) * 48 + lhalf);
            bH[2 * nb][0] = rh[0]; bH[2 * nb][1] = rh[2];
            bH[2 * nb + 1][0] = rh[1]; bH[2 * nb + 1][1] = rh[3];
        }
        if (lane == 0) mbar_arrive(emptyb + slot * 8);
        // group HH
#pragma unroll
        for (int j = 0; j < 8; j++) {
            mma_f16(acc0[0][j], aH[0], bH[j]);
            mma_f16(acc0[1][j], aH[1], bH[j]);
        }
        if (ks + 1 < 21) {      // prefetch next aH into freed regs
#pragma unroll
            for (int i = 0; i < 2; i++)
                ldsm4(aH[i], sb + X_HI + (wm + 16 * i + lrow) * XSTR + (ks + 1) * 32 + lhalf);
        }
        // group LH
#pragma unroll
        for (int j = 0; j < 8; j++) {
            mma_f16(acc0[0][j], aL[0], bH[j]);
            mma_f16(acc0[1][j], aL[1], bH[j]);
        }
        if (ks + 1 < 21) {      // prefetch next aL
#pragma unroll
            for (int i = 0; i < 2; i++)
                ldsm4(aL[i], sb + X_LO + (wm + 16 * i + lrow) * XSTR + (ks + 1) * 32 + lhalf);
        }
        produce(gks + 2);
    }
    __syncthreads();    // X reads done; X region dead

    // epilogue 0 -> C1 hi/lo (aliases X)
    {
#pragma unroll
        for (int i = 0; i < 2; i++)
#pragma unroll
            for (int j = 0; j < 8; j++) {
                int col = wn * 64 + j * 8 + (lane & 3) * 2;
                int row = wm + 16 * i + (lane >> 2);
                float b0v = g_bf0[col], b1v = g_bf0[col + 1];
                float v0 = fmaxf(acc0[i][j][0] + b0v, 0.f);
                float v1 = fmaxf(acc0[i][j][1] + b1v, 0.f);
                float v2 = fmaxf(acc0[i][j][2] + b0v, 0.f);
                float v3 = fmaxf(acc0[i][j][3] + b1v, 0.f);
                __half h0 = __float2half_rn(v0), h1 = __float2half_rn(v1);
                __half h2 = __float2half_rn(v2), h3 = __float2half_rn(v3);
                *(uint32_t*)(smc + C1_HI + row * 528 + col * 2) = pack_h2(h0, h1);
                *(uint32_t*)(smc + C1_LO + row * 528 + col * 2) =
                    pack_h2(__float2half_rn(v0 - __half2float(h0)),
                            __float2half_rn(v1 - __half2float(h1)));
                *(uint32_t*)(smc + C1_HI + (row + 8) * 528 + col * 2) = pack_h2(h2, h3);
                *(uint32_t*)(smc + C1_LO + (row + 8) * 528 + col * 2) =
                    pack_h2(__float2half_rn(v2 - __half2float(h2)),
                            __float2half_rn(v3 - __half2float(h3)));
            }
    }
    __syncthreads();    // C1 visible

    // ================= Layer 1: [128x256] -> 128 =================
    float acc1[2][4][4];
#pragma unroll
    for (int i = 0; i < 2; i++)
#pragma unroll
        for (int j = 0; j < 4; j++)
#pragma unroll
            for (int q = 0; q < 4; q++) acc1[i][j][q] = 0.f;

#pragma unroll
    for (int i = 0; i < 2; i++) {
        uint32_t rb = sb + C1_HI + (wm + 16 * i + lrow) * 528 + lhalf;
        ldsm4(aH[i], rb);
        ldsm4(aL[i], rb + (C1_LO - C1_HI));
    }

    for (int ks = 0; ks < 16; ks++) {
        const int gks = GK_L1 + ks, slot = gks & 1, par = (gks >> 1) & 1;
        MBAR_WAIT(fullb + slot * 8, par);
        uint32_t stg = sb + WSTG + (uint32_t)slot * WSSZ;
        uint32_t bH[4][2];
#pragma unroll
        for (int nb = 0; nb < 2; nb++) {
            uint32_t rh[4];
            ldsm4(rh, stg + (wn * 32 + 16 * nb + lrow) * 48 + lhalf);
            bH[2 * nb][0] = rh[0]; bH[2 * nb][1] = rh[2];
            bH[2 * nb + 1][0] = rh[1]; bH[2 * nb + 1][1] = rh[3];
        }
        if (lane == 0) mbar_arrive(emptyb + slot * 8);
#pragma unroll
        for (int j = 0; j < 4; j++) {
            mma_f16(acc1[0][j], aH[0], bH[j]);
            mma_f16(acc1[1][j], aH[1], bH[j]);
        }
        if (ks + 1 < 16) {
#pragma unroll
            for (int i = 0; i < 2; i++)
                ldsm4(aH[i], sb + C1_HI + (wm + 16 * i + lrow) * 528 + (ks + 1) * 32 + lhalf);
        }
#pragma unroll
        for (int j = 0; j < 4; j++) {
            mma_f16(acc1[0][j], aL[0], bH[j]);
            mma_f16(acc1[1][j], aL[1], bH[j]);
        }
        if (ks + 1 < 16) {
#pragma unroll
            for (int i = 0; i < 2; i++)
                ldsm4(aL[i], sb + C1_LO + (wm + 16 * i + lrow) * 528 + (ks + 1) * 32 + lhalf);
        }
        produce(gks + 2);
    }
    __syncthreads();    // C1 reads done; region dead

    // epilogue 1 -> C2 hi/lo (aliases C1)
    {
#pragma unroll
        for (int i = 0; i < 2; i++)
#pragma unroll
            for (int j = 0; j < 4; j++) {
                int col = wn * 32 + j * 8 + (lane & 3) * 2;
                int row = wm + 16 * i + (lane >> 2);
                float b0v = g_bf1[col], b1v = g_bf1[col + 1];
                float v0 = fmaxf(acc1[i][j][0] + b0v, 0.f);
                float v1 = fmaxf(acc1[i][j][1] + b1v, 0.f);
                float v2 = fmaxf(acc1[i][j][2] + b0v, 0.f);
                float v3 = fmaxf(acc1[i][j][3] + b1v, 0.f);
                __half h0 = __float2half_rn(v0), h1 = __float2half_rn(v1);
                __half h2 = __float2half_rn(v2), h3 = __float2half_rn(v3);
                *(uint32_t*)(smc + C2_HI + row * 272 + col * 2) = pack_h2(h0, h1);
                *(uint32_t*)(smc + C2_LO + row * 272 + col * 2) =
                    pack_h2(__float2half_rn(v0 - __half2float(h0)),
                            __float2half_rn(v1 - __half2float(h1)));
                *(uint32_t*)(smc + C2_HI + (row + 8) * 272 + col * 2) = pack_h2(h2, h3);
                *(uint32_t*)(smc + C2_LO + (row + 8) * 272 + col * 2) =
                    pack_h2(__float2half_rn(v2 - __half2float(h2)),
                            __float2half_rn(v3 - __half2float(h3)));
            }
    }
    __syncthreads();    // C2 visible

    // ================= Layer 2: [128x128] -> 64 =================
    float acc2[2][2][4];
#pragma unroll
    for (int i = 0; i < 2; i++)
#pragma unroll
        for (int j = 0; j < 2; j++)
#pragma unroll
            for (int q = 0; q < 4; q++) acc2[i][j][q] = 0.f;

#pragma unroll
    for (int i = 0; i < 2; i++) {
        uint32_t rb = sb + C2_HI + (wm + 16 * i + lrow) * 272 + lhalf;
        ldsm4(aH[i], rb);
        ldsm4(aL[i], rb + (C2_LO - C2_HI));
    }

    for (int ks = 0; ks < 8; ks++) {
        const int gks = GK_L2 + ks, slot = gks & 1, par = (gks >> 1) & 1;
        MBAR_WAIT(fullb + slot * 8, par);
        uint32_t stg = sb + WSTG + (uint32_t)slot * WSSZ;
        uint32_t bH[2][2];
        {
            uint32_t rh[4];
            ldsm4(rh, stg + (wn * 16 + lrow) * 48 + lhalf);
            bH[0][0] = rh[0]; bH[0][1] = rh[2]; bH[1][0] = rh[1]; bH[1][1] = rh[3];
        }
        if (lane == 0) mbar_arrive(emptyb + slot * 8);
#pragma unroll
        for (int j = 0; j < 2; j++) {
            mma_f16(acc2[0][j], aH[0], bH[j]);
            mma_f16(acc2[1][j], aH[1], bH[j]);
        }
        if (ks + 1 < 8) {
#pragma unroll
            for (int i = 0; i < 2; i++)
                ldsm4(aH[i], sb + C2_HI + (wm + 16 * i + lrow) * 272 + (ks + 1) * 32 + lhalf);
        }
#pragma unroll
        for (int j = 0; j < 2; j++) {
            mma_f16(acc2[0][j], aL[0], bH[j]);
            mma_f16(acc2[1][j], aL[1], bH[j]);
        }
        if (ks + 1 < 8) {
#pragma unroll
            for (int i = 0; i < 2; i++)
                ldsm4(aL[i], sb + C2_LO + (wm + 16 * i + lrow) * 272 + (ks + 1) * 32 + lhalf);
        }
        if (gks + 2 < GK_END) produce(gks + 2);
    }

    // epilogue 2 -> C3 (f32)
    {
#pragma unroll
        for (int i = 0; i < 2; i++)
#pragma unroll
            for (int j = 0; j < 2; j++) {
                int col = wn * 16 + j * 8 + (lane & 3) * 2;
                int row = wm + 16 * i + (lane >> 2);
                float b0v = g_bf2[col], b1v = g_bf2[col + 1];
                float2 v01 = make_float2(fmaxf(acc2[i][j][0] + b0v, 0.f),
                                         fmaxf(acc2[i][j][1] + b1v, 0.f));
                float2 v23 = make_float2(fmaxf(acc2[i][j][2] + b0v, 0.f),
                                         fmaxf(acc2[i][j][3] + b1v, 0.f));
                *(float2*)(smc + C3F + row * 272 + col * 4) = v01;
                *(float2*)(smc + C3F + (row + 8) * 272 + col * 4) = v23;
            }
    }
    __syncthreads();

    // ================= Output: dot Wo + fm + sigmoid =================
    if (t < MTILE) {
        const float* c3 = (const float*)(smc + C3F) + t * 68;
        float s = *(const float*)(smc + FMS + t * 4) + fmb[0] + bo[0];
#pragma unroll
        for (int k = 0; k < N2; k++)
            s = fmaf(c3[k], __ldg(&Wo[k]), s);
        out[m0g + t] = 1.f / (1.f + __expf(-s));
    }
}

// ================= Launch =================
extern "C" void kernel_launch(void* const* d_in, const int* in_sizes, int n_in,
                              void* d_out, int out_size)
{
    const int*   sp    = (const int*)  d_in[0];
    const float* dense = (const float*)d_in[1];
    const float* emb   = (const float*)d_in[2];
    const float* bias  = (const float*)d_in[3];
    const float* fmb   = (const float*)d_in[4];
    const float* Wo    = (const float*)d_in[5];
    const float* bo    = (const float*)d_in[6];
    const float* W0    = (const float*)d_in[7];
    const float* b0    = (const float*)d_in[8];
    const float* g0    = (const float*)d_in[9];
    const float* be0   = (const float*)d_in[10];
    const float* W1    = (const float*)d_in[11];
    const float* b1    = (const float*)d_in[12];
    const float* g1    = (const float*)d_in[13];
    const float* be1   = (const float*)d_in[14];
    const float* W2    = (const float*)d_in[15];
    const float* b2    = (const float*)d_in[16];
    const float* g2    = (const float*)d_in[17];
    const float* be2   = (const float*)d_in[18];
    float* out = (float*)d_out;

    prep_all<<<(PREP_TOT + 255) / 256, 256>>>(W0, b0, g0, be0, W1, b1, g1, be1, W2, b2, g2, be2);

    cudaFuncSetAttribute(mlp_kernel, cudaFuncAttributeMaxDynamicSharedMemorySize, SMEM_DYN);
    mlp_kernel<<<NCTA, NTHR, SMEM_DYN>>>(sp, dense, emb, bias, fmb, Wo, bo, out);
}

// round 12
// speedup vs baseline: 6.2689x; 1.3611x over previous
#include <cuda_runtime.h>
#include <cuda_fp16.h>
#include <math.h>
#include <stdint.h>

// ================= Problem constants =================
#define BATCH   16384
#define NFIELD  10
#define EMB     32
#define DENSE   16
#define K0      336         // 21 * 16
#define N0      256
#define N1      128
#define N2      64
#define MTILE   128
#define NCTA    (BATCH / MTILE)   // 128
#define NTHR    512
#define GK_L1   21
#define GK_L2   37
#define GK_END  45

__constant__ int c_offsets[NFIELD] = {
    0, 1000000, 1100000, 1101008, 1102012,
    1102114, 1103114, 1103614, 1103664, 1103776
};

// ================= Device scratch: weight stage images (fp16) =====
__device__ __align__(128) char g_S0[21 * 12288];
__device__ __align__(128) char g_S1[16 * 6144];
__device__ __align__(128) char g_S2[8 * 3072];
__device__ float g_bf0[N0], g_bf1[N1], g_bf2[N2];

// ================= PTX helpers =================
__device__ __forceinline__ uint32_t smem_u32(const void* p) {
    uint32_t a;
    asm("{ .reg .u64 t; cvta.to.shared.u64 t, %1; cvt.u32.u64 %0, t; }" : "=r"(a) : "l"(p));
    return a;
}
__device__ __forceinline__ void ldsm4(uint32_t* r, uint32_t a) {
    asm volatile("ldmatrix.sync.aligned.m8n8.x4.shared.b16 {%0,%1,%2,%3}, [%4];"
        : "=r"(r[0]), "=r"(r[1]), "=r"(r[2]), "=r"(r[3]) : "r"(a));
}
__device__ __forceinline__ void mma_f16(float* c, const uint32_t* a, const uint32_t* b) {
    asm volatile("mma.sync.aligned.m16n8k16.row.col.f32.f16.f16.f32 "
        "{%0,%1,%2,%3}, {%4,%5,%6,%7}, {%8,%9}, {%0,%1,%2,%3};"
        : "+f"(c[0]), "+f"(c[1]), "+f"(c[2]), "+f"(c[3])
        : "r"(a[0]), "r"(a[1]), "r"(a[2]), "r"(a[3]), "r"(b[0]), "r"(b[1]));
}
__device__ __forceinline__ uint32_t pack_h2(__half a, __half b) {
    __half2 t = __halves2half2(a, b);
    return *(uint32_t*)&t;
}

#define MBAR_INIT(a, c) \
    asm volatile("mbarrier.init.shared.b64 [%0], %1;" :: "r"(a), "r"((uint32_t)(c)) : "memory")
__device__ __forceinline__ void mbar_arrive(uint32_t a) {
    asm volatile("{ .reg .b64 _t; mbarrier.arrive.shared.b64 _t, [%0]; }" :: "r"(a) : "memory");
}
__device__ __forceinline__ void mbar_expect_tx(uint32_t a, uint32_t bytes) {
    asm volatile("mbarrier.arrive.expect_tx.shared.b64 _, [%0], %1;"
        :: "r"(a), "r"(bytes) : "memory");
}
__device__ __forceinline__ void bulk_g2s(uint32_t dst, const void* src, uint32_t bytes,
                                         uint32_t mbar) {
    asm volatile("cp.async.bulk.shared::cluster.global.mbarrier::complete_tx::bytes "
        "[%0], [%1], %2, [%3];"
        :: "r"(dst), "l"(src), "r"(bytes), "r"(mbar) : "memory");
}
#define FENCE_PROXY_ASYNC() asm volatile("fence.proxy.async.shared::cta;" ::: "memory")
#define MBAR_WAIT(mbar, par) do { \
    uint32_t _m = (uint32_t)(mbar); uint32_t _p = (uint32_t)(par); uint32_t _d; \
    asm volatile("{\n\t.reg .pred p;\n\t" \
        "mbarrier.try_wait.parity.acquire.cta.shared::cta.b64 p, [%1], %2;\n\t" \
        "selp.b32 %0, 1, 0, p;\n\t}" : "=r"(_d) : "r"(_m), "r"(_p) : "memory"); \
    if (!_d) { \
        asm volatile("{\n\t.reg .pred P1;\n\t" \
            "WL_%=:\n\t" \
            "mbarrier.try_wait.parity.acquire.cta.shared::cta.b64 P1, [%0], %1, 0x989680;\n\t" \
            "@P1 bra.uni WD_%=;\n\t" \
            "bra.uni WL_%=;\n\t" \
            "WD_%=:\n\t}" :: "r"(_m), "r"(_p) : "memory"); \
    } \
} while (0)

// ================= Kernel 1: weight prep -> fp16 staged blobs =================
#define S0SZ (N0 * K0)
#define S1SZ (N1 * N0)
#define S2SZ (N2 * N1)
#define PREP_TOT (S0SZ + S1SZ + S2SZ)

__global__ void prep_all(const float* __restrict__ W0, const float* __restrict__ b0,
                         const float* __restrict__ g0, const float* __restrict__ be0,
                         const float* __restrict__ W1, const float* __restrict__ b1,
                         const float* __restrict__ g1, const float* __restrict__ be1,
                         const float* __restrict__ W2, const float* __restrict__ b2,
                         const float* __restrict__ g2, const float* __restrict__ be2)
{
    const float inv = 0.9999950000374997f;   // 1/sqrt(1+1e-5)
    int i = blockIdx.x * blockDim.x + threadIdx.x;
    if (i >= PREP_TOT) return;
    char* base; uint32_t stagesz; const float *W, *g; int n, k, li;
    if (i < S0SZ) {
        li = i; n = li / K0; k = li - n * K0;
        W = W0; g = g0; base = g_S0; stagesz = 12288;
        if (li < N0) g_bf0[li] = b0[li] * (g0[li] * inv) + be0[li];
    } else if (i < S0SZ + S1SZ) {
        li = i - S0SZ; n = li >> 8; k = li & 255;
        W = W1; g = g1; base = g_S1; stagesz = 6144;
        if (li < N1) g_bf1[li] = b1[li] * (g1[li] * inv) + be1[li];
    } else {
        li = i - S0SZ - S1SZ; n = li >> 7; k = li & 127;
        W = W2; g = g2; base = g_S2; stagesz = 3072;
        if (li < N2) g_bf2[li] = b2[li] * (g2[li] * inv) + be2[li];
    }
    float w = W[li] * (g[n] * inv);
    int ks = k >> 4, kk = k & 15;
    uint32_t off = (uint32_t)ks * stagesz + (uint32_t)n * 48u
                 + (uint32_t)((kk >> 3) << 4) + (uint32_t)((kk & 7) << 1);
    *(__half*)(base + off) = __float2half_rn(w);
}

// ================= Kernel 2: fused embed + FM + HMMA MLP (fp16 x fp16) =====
// SMEM map:
//   X    @ 0      : [128][688B] = 88064        (dead after layer0:
//   WSTG @ 88064  : 2 x 12288  = 24576          C1 @0: 67584;
//   FMS  @ 112640 : 512                         then C2 @0: 34816, C3F @34816: 34816)
//   BARS @ 113152
#define X_OFF  0
#define XSTR   688
#define WSTG   88064
#define WSSZ   12288
#define C1_OFF 0
#define C2_OFF 0
#define C3F    34816
#define FMS    112640
#define BARS   (FMS + 512)
#define SMEM_DYN (FMS + 512 + 64)

__global__ __launch_bounds__(NTHR, 1)
void mlp_kernel(const int* __restrict__ sp, const float* __restrict__ dense,
                const float* __restrict__ emb, const float* __restrict__ bias,
                const float* __restrict__ fmb,
                const float* __restrict__ Wo, const float* __restrict__ bo,
                float* __restrict__ out)
{
    extern __shared__ char smc[];
    const uint32_t sb = smem_u32(smc);
    const int t = threadIdx.x, w = t >> 5, lane = t & 31;
    const int m0g = blockIdx.x * MTILE;
    const int wm = (w >> 2) * 32;
    const int wn = (w & 3);
    const uint32_t lrow = (uint32_t)(lane & 15);
    const uint32_t lhalf = (uint32_t)(lane >> 4) * 16u;
    const uint32_t fullb = sb + BARS;
    const uint32_t emptyb = sb + BARS + 16;

    auto produce = [&](int gkp) {
        if (t != 0) return;
        int slot = gkp & 1;
        uint32_t stg = sb + WSTG + (uint32_t)slot * WSSZ;
        if (gkp >= 2) MBAR_WAIT(emptyb + slot * 8, ((gkp - 2) >> 1) & 1);
        const char* src; uint32_t bytes;
        if (gkp < GK_L1)      { src = g_S0 + (size_t)gkp * 12288;            bytes = 12288; }
        else if (gkp < GK_L2) { src = g_S1 + (size_t)(gkp - GK_L1) * 6144;   bytes = 6144; }
        else                  { src = g_S2 + (size_t)(gkp - GK_L2) * 3072;   bytes = 3072; }
        mbar_expect_tx(fullb + slot * 8, bytes);
        bulk_g2s(stg, src, bytes, fullb + slot * 8);
    };

    // ---------------- Init barriers, kick stages 0/1, gather X, FM ----------------
    if (t == 0) {
        MBAR_INIT(fullb, 1);    MBAR_INIT(fullb + 8, 1);
        MBAR_INIT(emptyb, 16);  MBAR_INIT(emptyb + 8, 16);
        FENCE_PROXY_ASYNC();
    }
    __syncthreads();
    produce(0);
    produce(1);

    // fully unrolled gather: all 80 LDGs per warp in flight
#pragma unroll
    for (int i = 0; i < 8; i++) {
        int m = w * 8 + i;
        int b = m0g + m;
        float e[NFIELD];
#pragma unroll
        for (int f = 0; f < NFIELD; f++) {
            int row = sp[b * NFIELD + f] + c_offsets[f];
            e[f] = __ldg(&emb[(size_t)row * EMB + lane]);
        }
        float s = 0.f, sq = 0.f;
#pragma unroll
        for (int f = 0; f < NFIELD; f++) {
            s += e[f]; sq += e[f] * e[f];
            *(__half*)(smc + X_OFF + m * XSTR + (f * EMB + lane) * 2) = __float2half_rn(e[f]);
        }
        if (lane < DENSE)
            *(__half*)(smc + X_OFF + m * XSTR + (320 + lane) * 2) =
                __float2half_rn(dense[b * DENSE + lane]);
        float part = 0.5f * (s * s - sq);
        if (lane < NFIELD)
            part += __ldg(&bias[sp[b * NFIELD + lane] + c_offsets[lane]]);
#pragma unroll
        for (int d = 16; d > 0; d >>= 1)
            part += __shfl_down_sync(0xFFFFFFFFu, part, d);
        if (lane == 0) *(float*)(smc + FMS + m * 4) = part;
    }
    __syncthreads();   // X visible

    // ================= Layer 0: [128x336] -> 256 =================
    float acc0[2][8][4];
#pragma unroll
    for (int i = 0; i < 2; i++)
#pragma unroll
        for (int j = 0; j < 8; j++)
#pragma unroll
            for (int q = 0; q < 4; q++) acc0[i][j][q] = 0.f;

    uint32_t aH[2][4];
#pragma unroll
    for (int i = 0; i < 2; i++)
        ldsm4(aH[i], sb + X_OFF + (wm + 16 * i + lrow) * XSTR + lhalf);

    for (int ks = 0; ks < 21; ks++) {
        const int gks = ks, slot = gks & 1, par = (gks >> 1) & 1;
        MBAR_WAIT(fullb + slot * 8, par);
        uint32_t stg = sb + WSTG + (uint32_t)slot * WSSZ;
        uint32_t bH[8][2];
#pragma unroll
        for (int nb = 0; nb < 4; nb++) {
            uint32_t rh[4];
            ldsm4(rh, stg + (wn * 64 + 16 * nb + lrow) * 48 + lhalf);
            bH[2 * nb][0] = rh[0]; bH[2 * nb][1] = rh[2];
            bH[2 * nb + 1][0] = rh[1]; bH[2 * nb + 1][1] = rh[3];
        }
        if (lane == 0) mbar_arrive(emptyb + slot * 8);
        // first half of MMAs with current aH, then prefetch, then rest
#pragma unroll
        for (int j = 0; j < 8; j++)
            mma_f16(acc0[0][j], aH[0], bH[j]);
        uint32_t aN[2][4];
        if (ks + 1 < 21) {
#pragma unroll
            for (int i = 0; i < 2; i++)
                ldsm4(aN[i], sb + X_OFF + (wm + 16 * i + lrow) * XSTR + (ks + 1) * 32 + lhalf);
        }
#pragma unroll
        for (int j = 0; j < 8; j++)
            mma_f16(acc0[1][j], aH[1], bH[j]);
        if (ks + 1 < 21) {
#pragma unroll
            for (int i = 0; i < 2; i++)
#pragma unroll
                for (int q = 0; q < 4; q++) aH[i][q] = aN[i][q];
        }
        produce(gks + 2);
    }
    __syncthreads();    // X reads done; X region dead

    // epilogue 0 -> C1 (aliases X)
    {
#pragma unroll
        for (int i = 0; i < 2; i++)
#pragma unroll
            for (int j = 0; j < 8; j++) {
                int col = wn * 64 + j * 8 + (lane & 3) * 2;
                int row = wm + 16 * i + (lane >> 2);
                float b0v = g_bf0[col], b1v = g_bf0[col + 1];
                *(uint32_t*)(smc + C1_OFF + row * 528 + col * 2) =
                    pack_h2(__float2half_rn(fmaxf(acc0[i][j][0] + b0v, 0.f)),
                            __float2half_rn(fmaxf(acc0[i][j][1] + b1v, 0.f)));
                *(uint32_t*)(smc + C1_OFF + (row + 8) * 528 + col * 2) =
                    pack_h2(__float2half_rn(fmaxf(acc0[i][j][2] + b0v, 0.f)),
                            __float2half_rn(fmaxf(acc0[i][j][3] + b1v, 0.f)));
            }
    }
    __syncthreads();    // C1 visible

    // ================= Layer 1: [128x256] -> 128 =================
    float acc1[2][4][4];
#pragma unroll
    for (int i = 0; i < 2; i++)
#pragma unroll
        for (int j = 0; j < 4; j++)
#pragma unroll
            for (int q = 0; q < 4; q++) acc1[i][j][q] = 0.f;

#pragma unroll
    for (int i = 0; i < 2; i++)
        ldsm4(aH[i], sb + C1_OFF + (wm + 16 * i + lrow) * 528 + lhalf);

    for (int ks = 0; ks < 16; ks++) {
        const int gks = GK_L1 + ks, slot = gks & 1, par = (gks >> 1) & 1;
        MBAR_WAIT(fullb + slot * 8, par);
        uint32_t stg = sb + WSTG + (uint32_t)slot * WSSZ;
        uint32_t bH[4][2];
#pragma unroll
        for (int nb = 0; nb < 2; nb++) {
            uint32_t rh[4];
            ldsm4(rh, stg + (wn * 32 + 16 * nb + lrow) * 48 + lhalf);
            bH[2 * nb][0] = rh[0]; bH[2 * nb][1] = rh[2];
            bH[2 * nb + 1][0] = rh[1]; bH[2 * nb + 1][1] = rh[3];
        }
        if (lane == 0) mbar_arrive(emptyb + slot * 8);
#pragma unroll
        for (int j = 0; j < 4; j++)
            mma_f16(acc1[0][j], aH[0], bH[j]);
        uint32_t aN[2][4];
        if (ks + 1 < 16) {
#pragma unroll
            for (int i = 0; i < 2; i++)
                ldsm4(aN[i], sb + C1_OFF + (wm + 16 * i + lrow) * 528 + (ks + 1) * 32 + lhalf);
        }
#pragma unroll
        for (int j = 0; j < 4; j++)
            mma_f16(acc1[1][j], aH[1], bH[j]);
        if (ks + 1 < 16) {
#pragma unroll
            for (int i = 0; i < 2; i++)
#pragma unroll
                for (int q = 0; q < 4; q++) aH[i][q] = aN[i][q];
        }
        produce(gks + 2);
    }
    __syncthreads();    // C1 reads done; region dead

    // epilogue 1 -> C2 (aliases C1)
    {
#pragma unroll
        for (int i = 0; i < 2; i++)
#pragma unroll
            for (int j = 0; j < 4; j++) {
                int col = wn * 32 + j * 8 + (lane & 3) * 2;
                int row = wm + 16 * i + (lane >> 2);
                float b0v = g_bf1[col], b1v = g_bf1[col + 1];
                *(uint32_t*)(smc + C2_OFF + row * 272 + col * 2) =
                    pack_h2(__float2half_rn(fmaxf(acc1[i][j][0] + b0v, 0.f)),
                            __float2half_rn(fmaxf(acc1[i][j][1] + b1v, 0.f)));
                *(uint32_t*)(smc + C2_OFF + (row + 8) * 272 + col * 2) =
                    pack_h2(__float2half_rn(fmaxf(acc1[i][j][2] + b0v, 0.f)),
                            __float2half_rn(fmaxf(acc1[i][j][3] + b1v, 0.f)));
            }
    }
    __syncthreads();    // C2 visible

    // ================= Layer 2: [128x128] -> 64 =================
    float acc2[2][2][4];
#pragma unroll
    for (int i = 0; i < 2; i++)
#pragma unroll
        for (int j = 0; j < 2; j++)
#pragma unroll
            for (int q = 0; q < 4; q++) acc2[i][j][q] = 0.f;

#pragma unroll
    for (int i = 0; i < 2; i++)
        ldsm4(aH[i], sb + C2_OFF + (wm + 16 * i + lrow) * 272 + lhalf);

    for (int ks = 0; ks < 8; ks++) {
        const int gks = GK_L2 + ks, slot = gks & 1, par = (gks >> 1) & 1;
        MBAR_WAIT(fullb + slot * 8, par);
        uint32_t stg = sb + WSTG + (uint32_t)slot * WSSZ;
        uint32_t bH[2][2];
        {
            uint32_t rh[4];
            ldsm4(rh, stg + (wn * 16 + lrow) * 48 + lhalf);
            bH[0][0] = rh[0]; bH[0][1] = rh[2]; bH[1][0] = rh[1]; bH[1][1] = rh[3];
        }
        if (lane == 0) mbar_arrive(emptyb + slot * 8);
#pragma unroll
        for (int j = 0; j < 2; j++)
            mma_f16(acc2[0][j], aH[0], bH[j]);
        uint32_t aN[2][4];
        if (ks + 1 < 8) {
#pragma unroll
            for (int i = 0; i < 2; i++)
                ldsm4(aN[i], sb + C2_OFF + (wm + 16 * i + lrow) * 272 + (ks + 1) * 32 + lhalf);
        }
#pragma unroll
        for (int j = 0; j < 2; j++)
            mma_f16(acc2[1][j], aH[1], bH[j]);
        if (ks + 1 < 8) {
#pragma unroll
            for (int i = 0; i < 2; i++)
#pragma unroll
                for (int q = 0; q < 4; q++) aH[i][q] = aN[i][q];
        }
        if (gks + 2 < GK_END) produce(gks + 2);
    }

    // epilogue 2 -> C3 (f32, above C2 region)
    {
#pragma unroll
        for (int i = 0; i < 2; i++)
#pragma unroll
            for (int j = 0; j < 2; j++) {
                int col = wn * 16 + j * 8 + (lane & 3) * 2;
                int row = wm + 16 * i + (lane >> 2);
                float b0v = g_bf2[col], b1v = g_bf2[col + 1];
                float2 v01 = make_float2(fmaxf(acc2[i][j][0] + b0v, 0.f),
                                         fmaxf(acc2[i][j][1] + b1v, 0.f));
                float2 v23 = make_float2(fmaxf(acc2[i][j][2] + b0v, 0.f),
                                         fmaxf(acc2[i][j][3] + b1v, 0.f));
                *(float2*)(smc + C3F + row * 272 + col * 4) = v01;
                *(float2*)(smc + C3F + (row + 8) * 272 + col * 4) = v23;
            }
    }
    __syncthreads();

    // ================= Output: dot Wo + fm + sigmoid =================
    if (t < MTILE) {
        const float* c3 = (const float*)(smc + C3F) + t * 68;
        float s = *(const float*)(smc + FMS + t * 4) + fmb[0] + bo[0];
#pragma unroll
        for (int k = 0; k < N2; k++)
            s = fmaf(c3[k], __ldg(&Wo[k]), s);
        out[m0g + t] = 1.f / (1.f + __expf(-s));
    }
}

// ================= Launch =================
extern "C" void kernel_launch(void* const* d_in, const int* in_sizes, int n_in,
                              void* d_out, int out_size)
{
    const int*   sp    = (const int*)  d_in[0];
    const float* dense = (const float*)d_in[1];
    const float* emb   = (const float*)d_in[2];
    const float* bias  = (const float*)d_in[3];
    const float* fmb   = (const float*)d_in[4];
    const float* Wo    = (const float*)d_in[5];
    const float* bo    = (const float*)d_in[6];
    const float* W0    = (const float*)d_in[7];
    const float* b0    = (const float*)d_in[8];
    const float* g0    = (const float*)d_in[9];
    const float* be0   = (const float*)d_in[10];
    const float* W1    = (const float*)d_in[11];
    const float* b1    = (const float*)d_in[12];
    const float* g1    = (const float*)d_in[13];
    const float* be1   = (const float*)d_in[14];
    const float* W2    = (const float*)d_in[15];
    const float* b2    = (const float*)d_in[16];
    const float* g2    = (const float*)d_in[17];
    const float* be2   = (const float*)d_in[18];
    float* out = (float*)d_out;

    prep_all<<<(PREP_TOT + 255) / 256, 256>>>(W0, b0, g0, be0, W1, b1, g1, be1, W2, b2, g2, be2);

    cudaFuncSetAttribute(mlp_kernel, cudaFuncAttributeMaxDynamicSharedMemorySize, SMEM_DYN);
    mlp_kernel<<<NCTA, NTHR, SMEM_DYN>>>(sp, dense, emb, bias, fmb, Wo, bo, out);
}